// round 7
// baseline (speedup 1.0000x reference)
#include <cuda_runtime.h>
#include <cuda_bf16.h>
#include <cuda_fp16.h>
#include <cstdint>

// Problem constants
#define BATCH 128
#define NN    128
#define D_IN  6
#define D_MP  64
#define TOTAL (BATCH*NN)    // 16384
#define U_STRIDE 512
#define U_PER_B  (512*512)

__device__ float g_A0[TOTAL*128];           // h @ We0[:64]
__device__ float g_B0[TOTAL*128];           // h @ We0[64:]
__device__ __half g_Bhi[128*136];           // We1^T hi (fp16), padded [n][136]
__device__ __half g_Blo[128*136];           // We1^T lo (fp16 residual)
__device__ __nv_bfloat16 g_W2hi[16*136];    // We2^T hi, padded [c][136]
__device__ __nv_bfloat16 g_W2lo[16*136];    // We2^T lo

__device__ __forceinline__ float lrelu(float v){ return v >= 0.f ? v : 0.1f*v; }

__device__ __forceinline__ uint32_t smem_u32(const void* p){
    uint32_t a;
    asm("{ .reg .u64 t; cvta.to.shared.u64 t, %1; cvt.u32.u64 %0, t; }"
        : "=r"(a) : "l"(p));
    return a;
}

#define LDM4(r, addr) \
    asm volatile("ldmatrix.sync.aligned.m8n8.x4.shared.b16 {%0,%1,%2,%3}, [%4];" \
        : "=r"((r)[0]), "=r"((r)[1]), "=r"((r)[2]), "=r"((r)[3]) : "r"(addr))

#define MMA16816(d, a, b0_, b1_) \
    asm volatile("mma.sync.aligned.m16n8k16.row.col.f32.bf16.bf16.f32 " \
        "{%0,%1,%2,%3}, {%4,%5,%6,%7}, {%8,%9}, {%0,%1,%2,%3};" \
        : "+f"((d)[0]), "+f"((d)[1]), "+f"((d)[2]), "+f"((d)[3]) \
        : "r"((a)[0]), "r"((a)[1]), "r"((a)[2]), "r"((a)[3]), "r"(b0_), "r"(b1_))

#define MMA16816H(d, a, b0_, b1_) \
    asm volatile("mma.sync.aligned.m16n8k16.row.col.f32.f16.f16.f32 " \
        "{%0,%1,%2,%3}, {%4,%5,%6,%7}, {%8,%9}, {%0,%1,%2,%3};" \
        : "+f"((d)[0]), "+f"((d)[1]), "+f"((d)[2]), "+f"((d)[3]) \
        : "r"((a)[0]), "r"((a)[1]), "r"((a)[2]), "r"((a)[3]), "r"(b0_), "r"(b1_))

__device__ __forceinline__ void split2(float s0, float s1, uint32_t& hi, uint32_t& lo){
    __nv_bfloat162 h2 = __floats2bfloat162_rn(s0, s1);
    __nv_bfloat162 l2 = __floats2bfloat162_rn(s0 - __low2float(h2), s1 - __high2float(h2));
    hi = *reinterpret_cast<uint32_t*>(&h2);
    lo = *reinterpret_cast<uint32_t*>(&l2);
}
__device__ __forceinline__ uint32_t packh2(float s0, float s1){
    __half2 h2 = __floats2half2_rn(s0, s1);
    return *reinterpret_cast<uint32_t*>(&h2);
}

// ---------------------------------------------------------------------------
// K1: 3-layer GCN on complete graph (unchanged, passing).
// ---------------------------------------------------------------------------
__global__ void k1_gcn(const float* __restrict__ x,
                       const float* __restrict__ Wg0, const float* __restrict__ bg0,
                       const float* __restrict__ Wg1, const float* __restrict__ bg1,
                       const float* __restrict__ Wg2, const float* __restrict__ bg2,
                       float* __restrict__ h_out)
{
    __shared__ float buf[128*65];
    __shared__ float S[64];
    const int n = threadIdx.x;
    const int base = blockIdx.x * NN;
    const float inv = 1.0f/127.0f;

    float xr[D_IN];
#pragma unroll
    for (int k=0;k<D_IN;k++) xr[k] = x[(base+n)*D_IN + k];

    float y[64];
#pragma unroll
    for (int c=0;c<32;c++){
        float a = 0.f;
#pragma unroll
        for (int k=0;k<D_IN;k++) a += xr[k]*__ldg(&Wg0[k*32+c]);
        y[c]=a; buf[n*65+c]=a;
    }
    __syncthreads();
    if (n<32){ float s=0.f; for(int m=0;m<128;m++) s += buf[m*65+n]; S[n]=s; }
    __syncthreads();
#pragma unroll
    for (int c=0;c<32;c++) buf[n*65+c] = lrelu((S[c]-y[c])*inv + __ldg(&bg0[c]));
    __syncthreads();

#pragma unroll
    for (int c=0;c<32;c++){
        float a = 0.f;
#pragma unroll
        for (int k=0;k<32;k++) a += buf[n*65+k]*__ldg(&Wg1[k*32+c]);
        y[c]=a;
    }
    __syncthreads();
#pragma unroll
    for (int c=0;c<32;c++) buf[n*65+c]=y[c];
    __syncthreads();
    if (n<32){ float s=0.f; for(int m=0;m<128;m++) s += buf[m*65+n]; S[n]=s; }
    __syncthreads();
#pragma unroll
    for (int c=0;c<32;c++) buf[n*65+c] = lrelu((S[c]-y[c])*inv + __ldg(&bg1[c]));
    __syncthreads();

#pragma unroll
    for (int c=0;c<64;c++){
        float a = 0.f;
#pragma unroll
        for (int k=0;k<32;k++) a += buf[n*65+k]*__ldg(&Wg2[k*64+c]);
        y[c]=a;
    }
    __syncthreads();
#pragma unroll
    for (int c=0;c<64;c++) buf[n*65+c]=y[c];
    __syncthreads();
    if (n<64){ float s=0.f; for(int m=0;m<128;m++) s += buf[m*65+n]; S[n]=s; }
    __syncthreads();
#pragma unroll
    for (int c=0;c<64;c++)
        h_out[(base+n)*64 + c] = (S[c]-y[c])*inv + __ldg(&bg2[c]);
}

// ---------------------------------------------------------------------------
// K2: A0 = h @ We0[:64,:], B0 = h @ We0[64:,:]  (unchanged, passing)
// ---------------------------------------------------------------------------
__global__ void k2_ab(const float* __restrict__ h, const float* __restrict__ We0)
{
    __shared__ float hs[32*64];
    const int tid = threadIdx.x;
    const int n0 = blockIdx.x * 32;

    for (int l = tid; l < 32*64; l += 256) hs[l] = h[n0*64 + l];
    __syncthreads();

    const int col = tid & 127;
    const int kb  = (tid >> 7) * 64;

    float acc[32];
#pragma unroll
    for (int i=0;i<32;i++) acc[i]=0.f;

    for (int k=0;k<64;k++){
        float w = __ldg(&We0[(kb+k)*128 + col]);
#pragma unroll
        for (int nn=0;nn<32;nn++) acc[nn] += hs[nn*64+k]*w;
    }

    float* dst = (tid < 128) ? g_A0 : g_B0;
#pragma unroll
    for (int nn=0;nn<32;nn++) dst[(size_t)(n0+nn)*128 + col] = acc[nn];
}

// ---------------------------------------------------------------------------
// K2b: node MLP + diagonal 4x4 blocks of U.
// 1024 blocks x 128 threads; 16 nodes/block, 8 threads/node (8 cols each).
// ---------------------------------------------------------------------------
#define K2B_W0   0
#define K2B_W1   4096
#define K2B_W2   8192
#define K2B_BA   8960
#define K2B_BB   10048
#define K2B_VB   11136
#define K2B_B0   11344
#define K2B_B1   11408
#define K2B_B2   11472
#define K2B_SMEM ((11472+16)*4)

__global__ void __launch_bounds__(128)
k2b_node(const float* __restrict__ h,
         const float* __restrict__ Wn0, const float* __restrict__ bn0,
         const float* __restrict__ Wn1, const float* __restrict__ bn1,
         const float* __restrict__ Wn2, const float* __restrict__ bn2,
         float* __restrict__ U)
{
    extern __shared__ float sm[];
    const int tid = threadIdx.x;
    const int ln  = tid >> 3;       // node 0..15
    const int q   = tid & 7;        // col group (8 cols)
    const int b   = blockIdx.x >> 3;
    const int n0  = (blockIdx.x & 7) * 16;

    float4* w0s = reinterpret_cast<float4*>(sm + K2B_W0);
    float4* w1s = reinterpret_cast<float4*>(sm + K2B_W1);

    for (int l = tid; l < 1024; l += 128){
        w0s[l] = reinterpret_cast<const float4*>(Wn0)[l];
        w1s[l] = reinterpret_cast<const float4*>(Wn1)[l];
    }
    for (int l = tid; l < 768; l += 128){
        int k = l / 12, c = l % 12;
        sm[K2B_W2 + l] = (c < 10) ? Wn2[k*10 + c] : 0.f;
    }
    if (tid < 64){ sm[K2B_B0 + tid] = bn0[tid]; sm[K2B_B1 + tid] = bn1[tid]; }
    else if (tid < 76) sm[K2B_B2 + tid - 64] = (tid - 64 < 10) ? bn2[tid-64] : 0.f;
    for (int l = tid; l < 1024; l += 128){
        int r_ = l >> 6, c = l & 63;
        sm[K2B_BA + r_*68 + c] = h[(size_t)(b*128 + n0 + r_)*64 + c];
    }
    __syncthreads();

    // layer 1: bufA -> bufB (cols q*8..q*8+7)
    {
        float acc[8];
#pragma unroll
        for (int m=0;m<8;m++) acc[m] = sm[K2B_B0 + q*8 + m];
        for (int k=0;k<64;k++){
            float hk = sm[K2B_BA + ln*68 + k];
            float4 wa = w0s[k*16 + q*2];
            float4 wb = w0s[k*16 + q*2 + 1];
            acc[0] += hk*wa.x; acc[1] += hk*wa.y; acc[2] += hk*wa.z; acc[3] += hk*wa.w;
            acc[4] += hk*wb.x; acc[5] += hk*wb.y; acc[6] += hk*wb.z; acc[7] += hk*wb.w;
        }
#pragma unroll
        for (int m=0;m<8;m++) sm[K2B_BB + ln*68 + q*8 + m] = lrelu(acc[m]);
    }
    __syncthreads();

    // layer 2: bufB -> bufA
    {
        float acc[8];
#pragma unroll
        for (int m=0;m<8;m++) acc[m] = sm[K2B_B1 + q*8 + m];
        for (int k=0;k<64;k++){
            float hk = sm[K2B_BB + ln*68 + k];
            float4 wa = w1s[k*16 + q*2];
            float4 wb = w1s[k*16 + q*2 + 1];
            acc[0] += hk*wa.x; acc[1] += hk*wa.y; acc[2] += hk*wa.z; acc[3] += hk*wa.w;
            acc[4] += hk*wb.x; acc[5] += hk*wb.y; acc[6] += hk*wb.z; acc[7] += hk*wb.w;
        }
        __syncthreads();
#pragma unroll
        for (int m=0;m<8;m++) sm[K2B_BA + ln*68 + q*8 + m] = lrelu(acc[m]);
    }
    __syncthreads();

    // layer 3: bufA -> vbuf (threads q<6 do 2 cols each)
    if (q < 6){
        const int c0 = 2*q, c1 = 2*q + 1;
        float a0 = sm[K2B_B2 + c0];
        float a1 = sm[K2B_B2 + c1];
        for (int k=0;k<64;k++){
            float hk = sm[K2B_BA + ln*68 + k];
            a0 += hk * sm[K2B_W2 + k*12 + c0];
            a1 += hk * sm[K2B_W2 + k*12 + c1];
        }
        sm[K2B_VB + ln*13 + c0] = a0;
        sm[K2B_VB + ln*13 + c1] = a1;
    }
    __syncthreads();

    // diagonal write: threads q<4, row q of the 4x4 block
    if (q < 4){
        const int SMAT[16] = {0,1,2,3, 1,4,5,6, 2,5,7,8, 3,6,8,9};
        const int node = n0 + ln;
        float4 rv;
        rv.x = sm[K2B_VB + ln*13 + SMAT[q*4+0]];
        rv.y = sm[K2B_VB + ln*13 + SMAT[q*4+1]];
        rv.z = sm[K2B_VB + ln*13 + SMAT[q*4+2]];
        rv.w = sm[K2B_VB + ln*13 + SMAT[q*4+3]];
        float* Ub = U + (size_t)b*U_PER_B;
        *reinterpret_cast<float4*>(Ub + (size_t)(4*node+q)*U_STRIDE + 4*node) = rv;
    }
}

// ---------------------------------------------------------------------------
// K_prep: We1^T -> fp16 hi/lo, We2^T -> bf16 hi/lo (once).
// ---------------------------------------------------------------------------
__global__ void k_prep(const float* __restrict__ We1, const float* __restrict__ We2)
{
    int idx = blockIdx.x*256 + threadIdx.x;
    if (idx < 128*128){
        int k = idx >> 7, n = idx & 127;
        float w = We1[k*128 + n];
        __half h = __float2half_rn(w);
        float lo = w - __half2float(h);
        g_Bhi[n*136 + k] = h;
        g_Blo[n*136 + k] = __float2half_rn(lo);
    } else if (idx < 128*128 + 128*16){
        int r = idx - 128*128;
        int k = r >> 4, c = r & 15;
        float w = We2[k*16 + c];
        __nv_bfloat16 h = __float2bfloat16_rn(w);
        float lo = w - __bfloat162float(h);
        g_W2hi[c*136 + k] = h;
        g_W2lo[c*136 + k] = __float2bfloat16_rn(lo);
    }
}

// ---------------------------------------------------------------------------
// K3: edge MLP. GEMM1: t0 fp16 in SMEM (ldmatrix A) x We1^T fp16 2-split.
// GEMM2: bf16 3-split chained from accumulators. Tile = 128 pairs (8i x 16j).
// ---------------------------------------------------------------------------
#define OFF_THI  0                    // t0 fp16 [128][136] = 34816
#define OFF_BHI  34816                // 34816
#define OFF_BLO  69632                // 34816
#define OFF_W2HI 104448               // 4352
#define OFF_W2LO 108800               // 4352
#define OFF_BE1  113152               // 512
#define OFF_BE2  113664               // 64
#define OFF_ES   OFF_THI              // alias: [128][20] f = 10240 (t0 dead)
#define K3_SMEM  113728               // -> 2 CTAs/SM

__global__ void __launch_bounds__(256, 2)
k3_edge_mma(const float* __restrict__ be0,
            const float* __restrict__ be1,
            const float* __restrict__ be2,
            float* __restrict__ U)
{
    extern __shared__ char smem[];
    float* smemf = reinterpret_cast<float*>(smem);
    const uint32_t sb = smem_u32(smem);
    const int tid = threadIdx.x;
    const int wid = tid >> 5;
    const int lane = tid & 31;
    const int g = lane >> 2;
    const int r = lane & 3;

    // triangular tile decode: jt s.t. jt(jt+1) <= t < (jt+1)(jt+2)
    const int t = blockIdx.x;
    int jt = 0;
#pragma unroll
    for (int q=1;q<8;q++) if (t >= q*(q+1)) jt = q;
    const int it = t - jt*(jt+1);
    const int b  = blockIdx.y;
    const int i0 = it*8, j0 = jt*16;

    // ---- stage weights ----
    {
        const uint4* sh  = reinterpret_cast<const uint4*>(g_Bhi);
        const uint4* sl  = reinterpret_cast<const uint4*>(g_Blo);
        uint4* dh = reinterpret_cast<uint4*>(smem + OFF_BHI);
        uint4* dl = reinterpret_cast<uint4*>(smem + OFF_BLO);
        for (int l = tid; l < 2176; l += 256){ dh[l] = sh[l]; dl[l] = sl[l]; }
        const uint4* s2h = reinterpret_cast<const uint4*>(g_W2hi);
        const uint4* s2l = reinterpret_cast<const uint4*>(g_W2lo);
        uint4* d2h = reinterpret_cast<uint4*>(smem + OFF_W2HI);
        uint4* d2l = reinterpret_cast<uint4*>(smem + OFF_W2LO);
        for (int l = tid; l < 272; l += 256){ d2h[l] = s2h[l]; d2l[l] = s2l[l]; }
        if (tid < 128) smemf[OFF_BE1/4 + tid] = be1[tid];
        else if (tid < 144) smemf[OFF_BE2/4 + tid - 128] = be2[tid - 128];
    }

    // ---- build t0 fp16 directly into SMEM: pair p = tid>>1, half h = tid&1 ----
    {
        const int p = tid >> 1, hh = tid & 1;
        const float* Ar = g_A0 + ((size_t)(b*NN + i0 + (p >> 4)))*128 + hh*64;
        const float* Br = g_B0 + ((size_t)(b*NN + j0 + (p & 15)))*128 + hh*64;
        uint32_t* trow = reinterpret_cast<uint32_t*>(smem + OFF_THI) + p*68 + hh*32;
#pragma unroll
        for (int k4 = 0; k4 < 16; k4++){
            float4 a  = *reinterpret_cast<const float4*>(Ar + k4*4);
            float4 bb = *reinterpret_cast<const float4*>(Br + k4*4);
            float4 e0 = *reinterpret_cast<const float4*>(be0 + hh*64 + k4*4);
            uint32_t u0 = packh2(lrelu(a.x+bb.x+e0.x), lrelu(a.y+bb.y+e0.y));
            uint32_t u1 = packh2(lrelu(a.z+bb.z+e0.z), lrelu(a.w+bb.w+e0.w));
            *reinterpret_cast<uint2*>(trow + k4*2) = make_uint2(u0, u1);
        }
    }
    __syncthreads();

    const int mg = wid >> 1;       // 0..3 -> rows mg*32..+31
    const int ng = wid & 1;        // 0..1 -> cols ng*64..+63
    float acc[2][8][4];
#pragma unroll
    for (int a1=0;a1<2;a1++)
#pragma unroll
        for (int a2=0;a2<8;a2++)
#pragma unroll
            for (int a3=0;a3<4;a3++) acc[a1][a2][a3] = 0.f;

    // ---- GEMM1: ldmatrix A (t0 fp16), ldmatrix B (We1^T fp16 hi/lo) ----
    {
        const uint32_t aOff = (uint32_t)((mg*32 + (lane & 15))*272 + (lane >> 4)*16);
        const uint32_t bOff = (uint32_t)((ng*64 + ((lane >> 4) << 3) + (lane & 7))*272
                                        + ((lane >> 3) & 1)*16);
        const uint32_t aHi = sb + OFF_THI + aOff;
        const uint32_t bHi = sb + OFF_BHI + bOff, bLo = sb + OFF_BLO + bOff;

#pragma unroll
        for (int ks = 0; ks < 8; ks++){
            uint32_t ah0[4], ah1[4];
            LDM4(ah0, aHi + ks*32);
            LDM4(ah1, aHi + 4352 + ks*32);
#pragma unroll
            for (int n2 = 0; n2 < 4; n2++){
                uint32_t bh[4], bl[4];
                LDM4(bh, bHi + n2*4352 + ks*32);
                LDM4(bl, bLo + n2*4352 + ks*32);
                MMA16816H(acc[0][2*n2],   ah0, bh[0], bh[1]);
                MMA16816H(acc[0][2*n2],   ah0, bl[0], bl[1]);
                MMA16816H(acc[0][2*n2+1], ah0, bh[2], bh[3]);
                MMA16816H(acc[0][2*n2+1], ah0, bl[2], bl[3]);
                MMA16816H(acc[1][2*n2],   ah1, bh[0], bh[1]);
                MMA16816H(acc[1][2*n2],   ah1, bl[0], bl[1]);
                MMA16816H(acc[1][2*n2+1], ah1, bh[2], bh[3]);
                MMA16816H(acc[1][2*n2+1], ah1, bl[2], bl[3]);
            }
        }
    }

    // ---- GEMM2: chain acc -> t1 A-fragments (bf16 3-split), partial e ----
    float e[2][2][4];
#pragma unroll
    for (int a1=0;a1<2;a1++)
#pragma unroll
        for (int a2=0;a2<2;a2++)
#pragma unroll
            for (int a3=0;a3<4;a3++) e[a1][a2][a3] = 0.f;

    {
        const uint32_t b2Off = (uint32_t)(((((lane >> 4) << 3) + (lane & 7))*272)
                                        + ((lane >> 3) & 1)*16);
        const uint32_t wHi = sb + OFF_W2HI + b2Off, wLo = sb + OFF_W2LO + b2Off;

#pragma unroll
        for (int qk = 0; qk < 4; qk++){
            uint32_t bh[4], bl[4];
            LDM4(bh, wHi + (ng*4+qk)*32);
            LDM4(bl, wLo + (ng*4+qk)*32);
#pragma unroll
            for (int mt = 0; mt < 2; mt++){
                const int ntA = 2*qk, ntB = 2*qk+1;
                const int cA = ng*64 + ntA*8 + 2*r;
                const int cB = ng*64 + ntB*8 + 2*r;
                float beA0 = smemf[OFF_BE1/4 + cA], beA1 = smemf[OFF_BE1/4 + cA + 1];
                float beB0 = smemf[OFF_BE1/4 + cB], beB1 = smemf[OFF_BE1/4 + cB + 1];
                uint32_t ah[4], al[4];
                split2(lrelu(acc[mt][ntA][0]+beA0), lrelu(acc[mt][ntA][1]+beA1), ah[0], al[0]);
                split2(lrelu(acc[mt][ntA][2]+beA0), lrelu(acc[mt][ntA][3]+beA1), ah[1], al[1]);
                split2(lrelu(acc[mt][ntB][0]+beB0), lrelu(acc[mt][ntB][1]+beB1), ah[2], al[2]);
                split2(lrelu(acc[mt][ntB][2]+beB0), lrelu(acc[mt][ntB][3]+beB1), ah[3], al[3]);
                MMA16816(e[mt][0], ah, bh[0], bh[1]);
                MMA16816(e[mt][0], al, bh[0], bh[1]);
                MMA16816(e[mt][0], ah, bl[0], bl[1]);
                MMA16816(e[mt][1], ah, bh[2], bh[3]);
                MMA16816(e[mt][1], al, bh[2], bh[3]);
                MMA16816(e[mt][1], ah, bl[2], bl[3]);
            }
        }
    }

    // ---- cross-warp (ng pair) reduction + scatter into U ----
    __syncthreads();   // t0 reads complete; safe to overwrite with ES
    float* es = smemf + OFF_ES/4;   // [128][20]

    if (ng == 1){
#pragma unroll
        for (int mt=0; mt<2; mt++)
#pragma unroll
        for (int t_=0; t_<2; t_++)
#pragma unroll
        for (int rh=0; rh<2; rh++){
            int row = mg*32 + mt*16 + g + rh*8;
            int c = t_*8 + 2*r;
            *reinterpret_cast<float2*>(&es[row*20 + c]) =
                make_float2(e[mt][t_][rh*2+0], e[mt][t_][rh*2+1]);
        }
    }
    __syncthreads();
    if (ng == 0){
        float* Ub = U + (size_t)b*U_PER_B;
#pragma unroll
        for (int mt=0; mt<2; mt++)
#pragma unroll
        for (int t_=0; t_<2; t_++)
#pragma unroll
        for (int rh=0; rh<2; rh++){
            int row = mg*32 + mt*16 + g + rh*8;
            int c = t_*8 + 2*r;
            float2 part = *reinterpret_cast<const float2*>(&es[row*20 + c]);
            float vx = e[mt][t_][rh*2+0] + part.x + smemf[OFF_BE2/4 + c];
            float vy = e[mt][t_][rh*2+1] + part.y + smemf[OFF_BE2/4 + c + 1];
            int i = i0 + (row >> 4);
            int j = j0 + (row & 15);
            if (i < j){
                int qq = c >> 2, m = c & 3;
                float2 v2 = make_float2(vx, vy);
                *reinterpret_cast<float2*>(Ub + (size_t)(4*i+qq)*U_STRIDE + 4*j + m) = v2;
                *reinterpret_cast<float2*>(Ub + (size_t)(4*j+qq)*U_STRIDE + 4*i + m) = v2;
            }
        }
    }
}

// ---------------------------------------------------------------------------
extern "C" void kernel_launch(void* const* d_in, const int* in_sizes, int n_in,
                              void* d_out, int out_size)
{
    const float* x   = (const float*)d_in[0];
    const float* Wg0 = (const float*)d_in[4];
    const float* bg0 = (const float*)d_in[5];
    const float* Wg1 = (const float*)d_in[6];
    const float* bg1 = (const float*)d_in[7];
    const float* Wg2 = (const float*)d_in[8];
    const float* bg2 = (const float*)d_in[9];
    const float* Wn0 = (const float*)d_in[10];
    const float* bn0 = (const float*)d_in[11];
    const float* Wn1 = (const float*)d_in[12];
    const float* bn1 = (const float*)d_in[13];
    const float* Wn2 = (const float*)d_in[14];
    const float* bn2 = (const float*)d_in[15];
    const float* We0 = (const float*)d_in[16];
    const float* be0 = (const float*)d_in[17];
    const float* We1 = (const float*)d_in[18];
    const float* be1 = (const float*)d_in[19];
    const float* We2 = (const float*)d_in[20];
    const float* be2 = (const float*)d_in[21];

    float* h_out = (float*)d_out;                 // (16384, 64)
    float* U     = h_out + (size_t)TOTAL*D_MP;    // (128, 512, 512)

    static bool attr_set = false;
    if (!attr_set){
        cudaFuncSetAttribute(k3_edge_mma, cudaFuncAttributeMaxDynamicSharedMemorySize, K3_SMEM);
        cudaFuncSetAttribute(k2b_node, cudaFuncAttributeMaxDynamicSharedMemorySize, K2B_SMEM);
        attr_set = true;
    }

    k_prep<<<72, 256>>>(We1, We2);
    k1_gcn<<<BATCH, 128>>>(x, Wg0,bg0, Wg1,bg1, Wg2,bg2, h_out);
    k2_ab<<<TOTAL/32, 256>>>(h_out, We0);
    k2b_node<<<1024, 128, K2B_SMEM>>>(h_out, Wn0,bn0, Wn1,bn1, Wn2,bn2, U);
    k3_edge_mma<<<dim3(72, BATCH), 256, K3_SMEM>>>(be0, be1, be2, U);
}

// round 8
// speedup vs baseline: 1.2545x; 1.2545x over previous
#include <cuda_runtime.h>
#include <cuda_bf16.h>
#include <cuda_fp16.h>
#include <cstdint>

// Problem constants
#define BATCH 128
#define NN    128
#define D_IN  6
#define D_MP  64
#define TOTAL (BATCH*NN)    // 16384
#define U_STRIDE 512
#define U_PER_B  (512*512)

__device__ float g_A0[TOTAL*128];           // h @ We0[:64]
__device__ float g_B0[TOTAL*128];           // h @ We0[64:]
__device__ __half g_Bhi[128*136];           // We1^T hi (fp16), padded [n][136]
__device__ __half g_Blo[128*136];           // We1^T lo (fp16 residual)
__device__ __nv_bfloat16 g_W2hi[16*136];    // We2^T hi, padded [c][136]
__device__ __nv_bfloat16 g_W2lo[16*136];    // We2^T lo

__device__ __forceinline__ float lrelu(float v){ return v >= 0.f ? v : 0.1f*v; }

__device__ __forceinline__ uint32_t smem_u32(const void* p){
    uint32_t a;
    asm("{ .reg .u64 t; cvta.to.shared.u64 t, %1; cvt.u32.u64 %0, t; }"
        : "=r"(a) : "l"(p));
    return a;
}

#define LDM4(r, addr) \
    asm volatile("ldmatrix.sync.aligned.m8n8.x4.shared.b16 {%0,%1,%2,%3}, [%4];" \
        : "=r"((r)[0]), "=r"((r)[1]), "=r"((r)[2]), "=r"((r)[3]) : "r"(addr))

#define MMA16816(d, a, b0_, b1_) \
    asm volatile("mma.sync.aligned.m16n8k16.row.col.f32.bf16.bf16.f32 " \
        "{%0,%1,%2,%3}, {%4,%5,%6,%7}, {%8,%9}, {%0,%1,%2,%3};" \
        : "+f"((d)[0]), "+f"((d)[1]), "+f"((d)[2]), "+f"((d)[3]) \
        : "r"((a)[0]), "r"((a)[1]), "r"((a)[2]), "r"((a)[3]), "r"(b0_), "r"(b1_))

#define MMA16816H(d, a, b0_, b1_) \
    asm volatile("mma.sync.aligned.m16n8k16.row.col.f32.f16.f16.f32 " \
        "{%0,%1,%2,%3}, {%4,%5,%6,%7}, {%8,%9}, {%0,%1,%2,%3};" \
        : "+f"((d)[0]), "+f"((d)[1]), "+f"((d)[2]), "+f"((d)[3]) \
        : "r"((a)[0]), "r"((a)[1]), "r"((a)[2]), "r"((a)[3]), "r"(b0_), "r"(b1_))

__device__ __forceinline__ void split2(float s0, float s1, uint32_t& hi, uint32_t& lo){
    __nv_bfloat162 h2 = __floats2bfloat162_rn(s0, s1);
    __nv_bfloat162 l2 = __floats2bfloat162_rn(s0 - __low2float(h2), s1 - __high2float(h2));
    hi = *reinterpret_cast<uint32_t*>(&h2);
    lo = *reinterpret_cast<uint32_t*>(&l2);
}
__device__ __forceinline__ uint32_t packh2(float s0, float s1){
    __half2 h2 = __floats2half2_rn(s0, s1);
    return *reinterpret_cast<uint32_t*>(&h2);
}

// ---------------------------------------------------------------------------
// K1: 3-layer GCN on complete graph (unchanged, passing).
// ---------------------------------------------------------------------------
__global__ void k1_gcn(const float* __restrict__ x,
                       const float* __restrict__ Wg0, const float* __restrict__ bg0,
                       const float* __restrict__ Wg1, const float* __restrict__ bg1,
                       const float* __restrict__ Wg2, const float* __restrict__ bg2,
                       float* __restrict__ h_out)
{
    __shared__ float buf[128*65];
    __shared__ float S[64];
    const int n = threadIdx.x;
    const int base = blockIdx.x * NN;
    const float inv = 1.0f/127.0f;

    float xr[D_IN];
#pragma unroll
    for (int k=0;k<D_IN;k++) xr[k] = x[(base+n)*D_IN + k];

    float y[64];
#pragma unroll
    for (int c=0;c<32;c++){
        float a = 0.f;
#pragma unroll
        for (int k=0;k<D_IN;k++) a += xr[k]*__ldg(&Wg0[k*32+c]);
        y[c]=a; buf[n*65+c]=a;
    }
    __syncthreads();
    if (n<32){ float s=0.f; for(int m=0;m<128;m++) s += buf[m*65+n]; S[n]=s; }
    __syncthreads();
#pragma unroll
    for (int c=0;c<32;c++) buf[n*65+c] = lrelu((S[c]-y[c])*inv + __ldg(&bg0[c]));
    __syncthreads();

#pragma unroll
    for (int c=0;c<32;c++){
        float a = 0.f;
#pragma unroll
        for (int k=0;k<32;k++) a += buf[n*65+k]*__ldg(&Wg1[k*32+c]);
        y[c]=a;
    }
    __syncthreads();
#pragma unroll
    for (int c=0;c<32;c++) buf[n*65+c]=y[c];
    __syncthreads();
    if (n<32){ float s=0.f; for(int m=0;m<128;m++) s += buf[m*65+n]; S[n]=s; }
    __syncthreads();
#pragma unroll
    for (int c=0;c<32;c++) buf[n*65+c] = lrelu((S[c]-y[c])*inv + __ldg(&bg1[c]));
    __syncthreads();

#pragma unroll
    for (int c=0;c<64;c++){
        float a = 0.f;
#pragma unroll
        for (int k=0;k<32;k++) a += buf[n*65+k]*__ldg(&Wg2[k*64+c]);
        y[c]=a;
    }
    __syncthreads();
#pragma unroll
    for (int c=0;c<64;c++) buf[n*65+c]=y[c];
    __syncthreads();
    if (n<64){ float s=0.f; for(int m=0;m<128;m++) s += buf[m*65+n]; S[n]=s; }
    __syncthreads();
#pragma unroll
    for (int c=0;c<64;c++)
        h_out[(base+n)*64 + c] = (S[c]-y[c])*inv + __ldg(&bg2[c]);
}

// ---------------------------------------------------------------------------
// K2: A0 = h @ We0[:64,:], B0 = h @ We0[64:,:]  (unchanged, passing)
// ---------------------------------------------------------------------------
__global__ void k2_ab(const float* __restrict__ h, const float* __restrict__ We0)
{
    __shared__ float hs[32*64];
    const int tid = threadIdx.x;
    const int n0 = blockIdx.x * 32;

    for (int l = tid; l < 32*64; l += 256) hs[l] = h[n0*64 + l];
    __syncthreads();

    const int col = tid & 127;
    const int kb  = (tid >> 7) * 64;

    float acc[32];
#pragma unroll
    for (int i=0;i<32;i++) acc[i]=0.f;

    for (int k=0;k<64;k++){
        float w = __ldg(&We0[(kb+k)*128 + col]);
#pragma unroll
        for (int nn=0;nn<32;nn++) acc[nn] += hs[nn*64+k]*w;
    }

    float* dst = (tid < 128) ? g_A0 : g_B0;
#pragma unroll
    for (int nn=0;nn<32;nn++) dst[(size_t)(n0+nn)*128 + col] = acc[nn];
}

// ---------------------------------------------------------------------------
// K2b: node MLP + diagonal 4x4 blocks of U.  (round-5 version: 512x256)
// ---------------------------------------------------------------------------
#define K2B_W0   0
#define K2B_W1   4096
#define K2B_W2   8192
#define K2B_BA   8960
#define K2B_BB   11136
#define K2B_VB   13312
#define K2B_B0   13728
#define K2B_B1   13792
#define K2B_B2   13856
#define K2B_SMEM ((13856+16)*4)

__global__ void __launch_bounds__(256)
k2b_node(const float* __restrict__ h,
         const float* __restrict__ Wn0, const float* __restrict__ bn0,
         const float* __restrict__ Wn1, const float* __restrict__ bn1,
         const float* __restrict__ Wn2, const float* __restrict__ bn2,
         float* __restrict__ U)
{
    extern __shared__ float sm[];
    const int tid = threadIdx.x;
    const int ln  = tid >> 3;       // node 0..31
    const int q   = tid & 7;        // col group (8 cols)
    const int b   = blockIdx.x >> 2;
    const int n0  = (blockIdx.x & 3) * 32;

    float4* w0s = reinterpret_cast<float4*>(sm + K2B_W0);
    float4* w1s = reinterpret_cast<float4*>(sm + K2B_W1);

    for (int l = tid; l < 1024; l += 256){
        w0s[l] = reinterpret_cast<const float4*>(Wn0)[l];
        w1s[l] = reinterpret_cast<const float4*>(Wn1)[l];
    }
    for (int l = tid; l < 768; l += 256){
        int k = l / 12, c = l % 12;
        sm[K2B_W2 + l] = (c < 10) ? Wn2[k*10 + c] : 0.f;
    }
    if (tid < 64){ sm[K2B_B0 + tid] = bn0[tid]; sm[K2B_B1 + tid] = bn1[tid]; }
    else if (tid < 76) sm[K2B_B2 + tid - 64] = (tid - 64 < 10) ? bn2[tid-64] : 0.f;
    for (int l = tid; l < 2048; l += 256){
        int r_ = l >> 6, c = l & 63;
        sm[K2B_BA + r_*68 + c] = h[(size_t)(b*128 + n0 + r_)*64 + c];
    }
    __syncthreads();

    // layer 1: bufA -> bufB (cols q*8..q*8+7)
    {
        float acc[8];
#pragma unroll
        for (int m=0;m<8;m++) acc[m] = sm[K2B_B0 + q*8 + m];
        for (int k=0;k<64;k++){
            float hk = sm[K2B_BA + ln*68 + k];
            float4 wa = w0s[k*16 + q*2];
            float4 wb = w0s[k*16 + q*2 + 1];
            acc[0] += hk*wa.x; acc[1] += hk*wa.y; acc[2] += hk*wa.z; acc[3] += hk*wa.w;
            acc[4] += hk*wb.x; acc[5] += hk*wb.y; acc[6] += hk*wb.z; acc[7] += hk*wb.w;
        }
#pragma unroll
        for (int m=0;m<8;m++) sm[K2B_BB + ln*68 + q*8 + m] = lrelu(acc[m]);
    }
    __syncthreads();

    // layer 2: bufB -> bufA
    {
        float acc[8];
#pragma unroll
        for (int m=0;m<8;m++) acc[m] = sm[K2B_B1 + q*8 + m];
        for (int k=0;k<64;k++){
            float hk = sm[K2B_BB + ln*68 + k];
            float4 wa = w1s[k*16 + q*2];
            float4 wb = w1s[k*16 + q*2 + 1];
            acc[0] += hk*wa.x; acc[1] += hk*wa.y; acc[2] += hk*wa.z; acc[3] += hk*wa.w;
            acc[4] += hk*wb.x; acc[5] += hk*wb.y; acc[6] += hk*wb.z; acc[7] += hk*wb.w;
        }
        __syncthreads();
#pragma unroll
        for (int m=0;m<8;m++) sm[K2B_BA + ln*68 + q*8 + m] = lrelu(acc[m]);
    }
    __syncthreads();

    // layer 3: bufA -> vbuf (threads q<6 do 2 cols each)
    if (q < 6){
        const int c0 = 2*q, c1 = 2*q + 1;
        float a0 = sm[K2B_B2 + c0];
        float a1 = sm[K2B_B2 + c1];
        for (int k=0;k<64;k++){
            float hk = sm[K2B_BA + ln*68 + k];
            a0 += hk * sm[K2B_W2 + k*12 + c0];
            a1 += hk * sm[K2B_W2 + k*12 + c1];
        }
        sm[K2B_VB + ln*13 + c0] = a0;
        sm[K2B_VB + ln*13 + c1] = a1;
    }
    __syncthreads();

    // diagonal write: threads q<4, row q of the 4x4 block
    if (q < 4){
        const int SMAT[16] = {0,1,2,3, 1,4,5,6, 2,5,7,8, 3,6,8,9};
        const int node = n0 + ln;
        float4 rv;
        rv.x = sm[K2B_VB + ln*13 + SMAT[q*4+0]];
        rv.y = sm[K2B_VB + ln*13 + SMAT[q*4+1]];
        rv.z = sm[K2B_VB + ln*13 + SMAT[q*4+2]];
        rv.w = sm[K2B_VB + ln*13 + SMAT[q*4+3]];
        float* Ub = U + (size_t)b*U_PER_B;
        *reinterpret_cast<float4*>(Ub + (size_t)(4*node+q)*U_STRIDE + 4*node) = rv;
    }
}

// ---------------------------------------------------------------------------
// K_prep: We1^T -> fp16 hi/lo, We2^T -> bf16 hi/lo (once).
// ---------------------------------------------------------------------------
__global__ void k_prep(const float* __restrict__ We1, const float* __restrict__ We2)
{
    int idx = blockIdx.x*256 + threadIdx.x;
    if (idx < 128*128){
        int k = idx >> 7, n = idx & 127;
        float w = We1[k*128 + n];
        __half h = __float2half_rn(w);
        float lo = w - __half2float(h);
        g_Bhi[n*136 + k] = h;
        g_Blo[n*136 + k] = __float2half_rn(lo);
    } else if (idx < 128*128 + 128*16){
        int r = idx - 128*128;
        int k = r >> 4, c = r & 15;
        float w = We2[k*16 + c];
        __nv_bfloat16 h = __float2bfloat16_rn(w);
        float lo = w - __bfloat162float(h);
        g_W2hi[c*136 + k] = h;
        g_W2lo[c*136 + k] = __float2bfloat16_rn(lo);
    }
}

// ---------------------------------------------------------------------------
// K3: edge MLP (round-6 core: register-built fp16 A, B 2-split fp16;
// GEMM2 bf16 3-split chained). NEW: coalesced float4 U epilogue via ES.
// ---------------------------------------------------------------------------
#define OFF_BHI  0                    // 34816
#define OFF_BLO  34816                // 34816
#define OFF_W2HI 69632                // 4352
#define OFF_W2LO 73984                // 4352
#define OFF_BE1  78336                // 512
#define OFF_BE2  78848                // 64
#define OFF_STG  78912                // A0s[8][132] + B0s[16][132] = 12672
#define OFF_A0S  OFF_STG
#define OFF_B0S  (OFF_STG + 8*132*4)
#define OFF_ES   OFF_STG              // alias: [128][20] f = 10240
#define K3_SMEM  (OFF_STG + 12672)    // 91584 B -> 2 CTAs/SM

__global__ void __launch_bounds__(256, 2)
k3_edge_mma(const float* __restrict__ be0,
            const float* __restrict__ be1,
            const float* __restrict__ be2,
            float* __restrict__ U)
{
    extern __shared__ char smem[];
    float* smemf = reinterpret_cast<float*>(smem);
    const uint32_t sb = smem_u32(smem);
    const int tid = threadIdx.x;
    const int wid = tid >> 5;
    const int lane = tid & 31;
    const int g = lane >> 2;
    const int r = lane & 3;

    // triangular tile decode: jt s.t. jt(jt+1) <= t < (jt+1)(jt+2)
    const int t = blockIdx.x;
    int jt = 0;
#pragma unroll
    for (int q=1;q<8;q++) if (t >= q*(q+1)) jt = q;
    const int it = t - jt*(jt+1);
    const int b  = blockIdx.y;
    const int i0 = it*8, j0 = jt*16;

    // ---- stage weights + A0/B0 rows ----
    {
        const uint4* sh  = reinterpret_cast<const uint4*>(g_Bhi);
        const uint4* sl  = reinterpret_cast<const uint4*>(g_Blo);
        uint4* dh = reinterpret_cast<uint4*>(smem + OFF_BHI);
        uint4* dl = reinterpret_cast<uint4*>(smem + OFF_BLO);
        for (int l = tid; l < 2176; l += 256){ dh[l] = sh[l]; dl[l] = sl[l]; }
        const uint4* s2h = reinterpret_cast<const uint4*>(g_W2hi);
        const uint4* s2l = reinterpret_cast<const uint4*>(g_W2lo);
        uint4* d2h = reinterpret_cast<uint4*>(smem + OFF_W2HI);
        uint4* d2l = reinterpret_cast<uint4*>(smem + OFF_W2LO);
        for (int l = tid; l < 272; l += 256){ d2h[l] = s2h[l]; d2l[l] = s2l[l]; }
        if (tid < 128) smemf[OFF_BE1/4 + tid] = be1[tid];
        else if (tid < 144) smemf[OFF_BE2/4 + tid - 128] = be2[tid - 128];
        // A0s: 8 rows x 128 f (no be0); B0s: 16 rows x 128 f (+be0)
        for (int l = tid; l < 256; l += 256){
            int rr = l >> 5, c4 = (l & 31)*4;
            float4 v = *reinterpret_cast<const float4*>(g_A0 + ((size_t)(b*NN + i0 + rr))*128 + c4);
            *reinterpret_cast<float4*>(smemf + OFF_A0S/4 + rr*132 + c4) = v;
        }
        for (int l = tid; l < 512; l += 256){
            int rr = l >> 5, c4 = (l & 31)*4;
            float4 v  = *reinterpret_cast<const float4*>(g_B0 + ((size_t)(b*NN + j0 + rr))*128 + c4);
            float4 e0 = *reinterpret_cast<const float4*>(be0 + c4);
            v.x += e0.x; v.y += e0.y; v.z += e0.z; v.w += e0.w;
            *reinterpret_cast<float4*>(smemf + OFF_B0S/4 + rr*132 + c4) = v;
        }
    }
    __syncthreads();

    const int mg = wid >> 1;       // 0..3 -> rows mg*32..+31
    const int ng = wid & 1;        // 0..1 -> cols ng*64..+63
    float acc[2][8][4];
#pragma unroll
    for (int a1=0;a1<2;a1++)
#pragma unroll
        for (int a2=0;a2<8;a2++)
#pragma unroll
            for (int a3=0;a3<4;a3++) acc[a1][a2][a3] = 0.f;

    // ---- GEMM1: register-built fp16 A (t0), ldmatrix fp16 B hi/lo ----
    {
        const uint32_t bOff = (uint32_t)((ng*64 + ((lane >> 4) << 3) + (lane & 7))*272
                                        + ((lane >> 3) & 1)*16);
        const uint32_t bHi = sb + OFF_BHI + bOff, bLo = sb + OFF_BLO + bOff;
        const float* A0p = smemf + OFF_A0S/4;
        const float* B0p = smemf + OFF_B0S/4;

#pragma unroll
        for (int ks = 0; ks < 8; ks++){
            // B0 rows j = g, g+8 (shared across mt)
            float2 b00 = *reinterpret_cast<const float2*>(B0p + g*132      + ks*16 + 2*r);
            float2 b01 = *reinterpret_cast<const float2*>(B0p + g*132      + ks*16 + 8 + 2*r);
            float2 b10 = *reinterpret_cast<const float2*>(B0p + (g+8)*132  + ks*16 + 2*r);
            float2 b11 = *reinterpret_cast<const float2*>(B0p + (g+8)*132  + ks*16 + 8 + 2*r);

            uint32_t ah[2][4];
#pragma unroll
            for (int mt=0; mt<2; mt++){
                const float* Ar = A0p + (mg*2+mt)*132 + ks*16;
                float2 ak0 = *reinterpret_cast<const float2*>(Ar + 2*r);
                float2 ak1 = *reinterpret_cast<const float2*>(Ar + 8 + 2*r);
                ah[mt][0] = packh2(lrelu(ak0.x+b00.x), lrelu(ak0.y+b00.y));
                ah[mt][1] = packh2(lrelu(ak0.x+b10.x), lrelu(ak0.y+b10.y));
                ah[mt][2] = packh2(lrelu(ak1.x+b01.x), lrelu(ak1.y+b01.y));
                ah[mt][3] = packh2(lrelu(ak1.x+b11.x), lrelu(ak1.y+b11.y));
            }
#pragma unroll
            for (int n2 = 0; n2 < 4; n2++){
                uint32_t bh[4], bl[4];
                LDM4(bh, bHi + n2*4352 + ks*32);
                LDM4(bl, bLo + n2*4352 + ks*32);
                MMA16816H(acc[0][2*n2],   ah[0], bh[0], bh[1]);
                MMA16816H(acc[0][2*n2],   ah[0], bl[0], bl[1]);
                MMA16816H(acc[0][2*n2+1], ah[0], bh[2], bh[3]);
                MMA16816H(acc[0][2*n2+1], ah[0], bl[2], bl[3]);
                MMA16816H(acc[1][2*n2],   ah[1], bh[0], bh[1]);
                MMA16816H(acc[1][2*n2],   ah[1], bl[0], bl[1]);
                MMA16816H(acc[1][2*n2+1], ah[1], bh[2], bh[3]);
                MMA16816H(acc[1][2*n2+1], ah[1], bl[2], bl[3]);
            }
        }
    }

    // ---- GEMM2: chain acc -> t1 A-fragments (bf16 3-split), partial e ----
    float e[2][2][4];
#pragma unroll
    for (int a1=0;a1<2;a1++)
#pragma unroll
        for (int a2=0;a2<2;a2++)
#pragma unroll
            for (int a3=0;a3<4;a3++) e[a1][a2][a3] = 0.f;

    {
        const uint32_t b2Off = (uint32_t)(((((lane >> 4) << 3) + (lane & 7))*272)
                                        + ((lane >> 3) & 1)*16);
        const uint32_t wHi = sb + OFF_W2HI + b2Off, wLo = sb + OFF_W2LO + b2Off;

#pragma unroll
        for (int qk = 0; qk < 4; qk++){
            uint32_t bh[4], bl[4];
            LDM4(bh, wHi + (ng*4+qk)*32);
            LDM4(bl, wLo + (ng*4+qk)*32);
#pragma unroll
            for (int mt = 0; mt < 2; mt++){
                const int ntA = 2*qk, ntB = 2*qk+1;
                const int cA = ng*64 + ntA*8 + 2*r;
                const int cB = ng*64 + ntB*8 + 2*r;
                float beA0 = smemf[OFF_BE1/4 + cA], beA1 = smemf[OFF_BE1/4 + cA + 1];
                float beB0 = smemf[OFF_BE1/4 + cB], beB1 = smemf[OFF_BE1/4 + cB + 1];
                uint32_t ah[4], al[4];
                split2(lrelu(acc[mt][ntA][0]+beA0), lrelu(acc[mt][ntA][1]+beA1), ah[0], al[0]);
                split2(lrelu(acc[mt][ntA][2]+beA0), lrelu(acc[mt][ntA][3]+beA1), ah[1], al[1]);
                split2(lrelu(acc[mt][ntB][0]+beB0), lrelu(acc[mt][ntB][1]+beB1), ah[2], al[2]);
                split2(lrelu(acc[mt][ntB][2]+beB0), lrelu(acc[mt][ntB][3]+beB1), ah[3], al[3]);
                MMA16816(e[mt][0], ah, bh[0], bh[1]);
                MMA16816(e[mt][0], al, bh[0], bh[1]);
                MMA16816(e[mt][0], ah, bl[0], bl[1]);
                MMA16816(e[mt][1], ah, bh[2], bh[3]);
                MMA16816(e[mt][1], al, bh[2], bh[3]);
                MMA16816(e[mt][1], ah, bl[2], bl[3]);
            }
        }
    }

    // ---- cross-warp (ng pair) reduction into ES, then coalesced U stores ----
    __syncthreads();   // A0s/B0s reads done; safe to overwrite with ES
    float* es = smemf + OFF_ES/4;   // [128][20]

    if (ng == 1){
#pragma unroll
        for (int mt=0; mt<2; mt++)
#pragma unroll
        for (int t_=0; t_<2; t_++)
#pragma unroll
        for (int rh=0; rh<2; rh++){
            int row = mg*32 + mt*16 + g + rh*8;
            int c = t_*8 + 2*r;
            *reinterpret_cast<float2*>(&es[row*20 + c]) =
                make_float2(e[mt][t_][rh*2+0], e[mt][t_][rh*2+1]);
        }
    }
    __syncthreads();
    if (ng == 0){
#pragma unroll
        for (int mt=0; mt<2; mt++)
#pragma unroll
        for (int t_=0; t_<2; t_++)
#pragma unroll
        for (int rh=0; rh<2; rh++){
            int row = mg*32 + mt*16 + g + rh*8;
            int c = t_*8 + 2*r;
            float2 part = *reinterpret_cast<const float2*>(&es[row*20 + c]);
            part.x += e[mt][t_][rh*2+0] + smemf[OFF_BE2/4 + c];
            part.y += e[mt][t_][rh*2+1] + smemf[OFF_BE2/4 + c + 1];
            *reinterpret_cast<float2*>(&es[row*20 + c]) = part;
        }
    }
    __syncthreads();

    // all 256 threads: one (pair, side) each, float4 stores
    {
        const int p = tid >> 1, side = tid & 1;
        const int i = i0 + (p >> 4);
        const int j = j0 + (p & 15);
        if (i < j){
            float* Ub = U + (size_t)b*U_PER_B;
            const float* ep = &es[p*20];
#pragma unroll
            for (int q = 0; q < 4; q++){
                float4 v4 = make_float4(ep[q*4], ep[q*4+1], ep[q*4+2], ep[q*4+3]);
                if (side == 0)
                    *reinterpret_cast<float4*>(Ub + (size_t)(4*i+q)*U_STRIDE + 4*j) = v4;
                else
                    *reinterpret_cast<float4*>(Ub + (size_t)(4*j+q)*U_STRIDE + 4*i) = v4;
            }
        }
    }
}

// ---------------------------------------------------------------------------
extern "C" void kernel_launch(void* const* d_in, const int* in_sizes, int n_in,
                              void* d_out, int out_size)
{
    const float* x   = (const float*)d_in[0];
    const float* Wg0 = (const float*)d_in[4];
    const float* bg0 = (const float*)d_in[5];
    const float* Wg1 = (const float*)d_in[6];
    const float* bg1 = (const float*)d_in[7];
    const float* Wg2 = (const float*)d_in[8];
    const float* bg2 = (const float*)d_in[9];
    const float* Wn0 = (const float*)d_in[10];
    const float* bn0 = (const float*)d_in[11];
    const float* Wn1 = (const float*)d_in[12];
    const float* bn1 = (const float*)d_in[13];
    const float* Wn2 = (const float*)d_in[14];
    const float* bn2 = (const float*)d_in[15];
    const float* We0 = (const float*)d_in[16];
    const float* be0 = (const float*)d_in[17];
    const float* We1 = (const float*)d_in[18];
    const float* be1 = (const float*)d_in[19];
    const float* We2 = (const float*)d_in[20];
    const float* be2 = (const float*)d_in[21];

    float* h_out = (float*)d_out;                 // (16384, 64)
    float* U     = h_out + (size_t)TOTAL*D_MP;    // (128, 512, 512)

    static bool attr_set = false;
    if (!attr_set){
        cudaFuncSetAttribute(k3_edge_mma, cudaFuncAttributeMaxDynamicSharedMemorySize, K3_SMEM);
        cudaFuncSetAttribute(k2b_node, cudaFuncAttributeMaxDynamicSharedMemorySize, K2B_SMEM);
        attr_set = true;
    }

    k_prep<<<72, 256>>>(We1, We2);
    k1_gcn<<<BATCH, 128>>>(x, Wg0,bg0, Wg1,bg1, Wg2,bg2, h_out);
    k2_ab<<<TOTAL/32, 256>>>(h_out, We0);
    k2b_node<<<512, 256, K2B_SMEM>>>(h_out, Wn0,bn0, Wn1,bn1, Wn2,bn2, U);
    k3_edge_mma<<<dim3(72, BATCH), 256, K3_SMEM>>>(be0, be1, be2, U);
}

// round 9
// speedup vs baseline: 1.5130x; 1.2060x over previous
#include <cuda_runtime.h>
#include <cuda_bf16.h>
#include <cuda_fp16.h>
#include <cstdint>

// Problem constants
#define BATCH 128
#define NN    128
#define D_IN  6
#define D_MP  64
#define TOTAL (BATCH*NN)    // 16384
#define U_STRIDE 512
#define U_PER_B  (512*512)

__device__ float g_A0[TOTAL*128];           // h @ We0[:64]
__device__ float g_B0[TOTAL*128];           // h @ We0[64:]
__device__ __half g_Bhi[128*136];           // We1^T fp16, padded [n][136]
__device__ __nv_bfloat16 g_W2hi[16*136];    // We2^T hi, padded [c][136]
__device__ __nv_bfloat16 g_W2lo[16*136];    // We2^T lo

__device__ __forceinline__ float lrelu(float v){ return v >= 0.f ? v : 0.1f*v; }

__device__ __forceinline__ uint32_t smem_u32(const void* p){
    uint32_t a;
    asm("{ .reg .u64 t; cvta.to.shared.u64 t, %1; cvt.u32.u64 %0, t; }"
        : "=r"(a) : "l"(p));
    return a;
}

#define LDM4(r, addr) \
    asm volatile("ldmatrix.sync.aligned.m8n8.x4.shared.b16 {%0,%1,%2,%3}, [%4];" \
        : "=r"((r)[0]), "=r"((r)[1]), "=r"((r)[2]), "=r"((r)[3]) : "r"(addr))

#define MMA16816(d, a, b0_, b1_) \
    asm volatile("mma.sync.aligned.m16n8k16.row.col.f32.bf16.bf16.f32 " \
        "{%0,%1,%2,%3}, {%4,%5,%6,%7}, {%8,%9}, {%0,%1,%2,%3};" \
        : "+f"((d)[0]), "+f"((d)[1]), "+f"((d)[2]), "+f"((d)[3]) \
        : "r"((a)[0]), "r"((a)[1]), "r"((a)[2]), "r"((a)[3]), "r"(b0_), "r"(b1_))

#define MMA16816H(d, a, b0_, b1_) \
    asm volatile("mma.sync.aligned.m16n8k16.row.col.f32.f16.f16.f32 " \
        "{%0,%1,%2,%3}, {%4,%5,%6,%7}, {%8,%9}, {%0,%1,%2,%3};" \
        : "+f"((d)[0]), "+f"((d)[1]), "+f"((d)[2]), "+f"((d)[3]) \
        : "r"((a)[0]), "r"((a)[1]), "r"((a)[2]), "r"((a)[3]), "r"(b0_), "r"(b1_))

__device__ __forceinline__ void split2(float s0, float s1, uint32_t& hi, uint32_t& lo){
    __nv_bfloat162 h2 = __floats2bfloat162_rn(s0, s1);
    __nv_bfloat162 l2 = __floats2bfloat162_rn(s0 - __low2float(h2), s1 - __high2float(h2));
    hi = *reinterpret_cast<uint32_t*>(&h2);
    lo = *reinterpret_cast<uint32_t*>(&l2);
}
__device__ __forceinline__ uint32_t packh2(float s0, float s1){
    __half2 h2 = __floats2half2_rn(s0, s1);
    return *reinterpret_cast<uint32_t*>(&h2);
}

// ---------------------------------------------------------------------------
// K1 fused: blocks [0,128) = GCN (1 block/batch); blocks [128,272) = weight prep.
// ---------------------------------------------------------------------------
__global__ void __launch_bounds__(128)
k1_fused(const float* __restrict__ x,
         const float* __restrict__ Wg0, const float* __restrict__ bg0,
         const float* __restrict__ Wg1, const float* __restrict__ bg1,
         const float* __restrict__ Wg2, const float* __restrict__ bg2,
         const float* __restrict__ We1, const float* __restrict__ We2,
         float* __restrict__ h_out)
{
    if (blockIdx.x >= 128){
        // ---- prep: We1^T -> fp16, We2^T -> bf16 hi/lo ----
        int idx = (blockIdx.x - 128)*128 + threadIdx.x;   // 0..18431
        if (idx < 128*128){
            int k = idx >> 7, n = idx & 127;
            g_Bhi[n*136 + k] = __float2half_rn(We1[k*128 + n]);
        } else {
            int r = idx - 128*128;                         // 0..2047
            int k = r >> 4, c = r & 15;
            float w = We2[k*16 + c];
            __nv_bfloat16 h = __float2bfloat16_rn(w);
            float lo = w - __bfloat162float(h);
            g_W2hi[c*136 + k] = h;
            g_W2lo[c*136 + k] = __float2bfloat16_rn(lo);
        }
        return;
    }

    __shared__ float buf[128*65];
    __shared__ float S[64];
    const int n = threadIdx.x;
    const int base = blockIdx.x * NN;
    const float inv = 1.0f/127.0f;

    float xr[D_IN];
#pragma unroll
    for (int k=0;k<D_IN;k++) xr[k] = x[(base+n)*D_IN + k];

    float y[64];
#pragma unroll
    for (int c=0;c<32;c++){
        float a = 0.f;
#pragma unroll
        for (int k=0;k<D_IN;k++) a += xr[k]*__ldg(&Wg0[k*32+c]);
        y[c]=a; buf[n*65+c]=a;
    }
    __syncthreads();
    if (n<32){ float s=0.f; for(int m=0;m<128;m++) s += buf[m*65+n]; S[n]=s; }
    __syncthreads();
#pragma unroll
    for (int c=0;c<32;c++) buf[n*65+c] = lrelu((S[c]-y[c])*inv + __ldg(&bg0[c]));
    __syncthreads();

#pragma unroll
    for (int c=0;c<32;c++){
        float a = 0.f;
#pragma unroll
        for (int k=0;k<32;k++) a += buf[n*65+k]*__ldg(&Wg1[k*32+c]);
        y[c]=a;
    }
    __syncthreads();
#pragma unroll
    for (int c=0;c<32;c++) buf[n*65+c]=y[c];
    __syncthreads();
    if (n<32){ float s=0.f; for(int m=0;m<128;m++) s += buf[m*65+n]; S[n]=s; }
    __syncthreads();
#pragma unroll
    for (int c=0;c<32;c++) buf[n*65+c] = lrelu((S[c]-y[c])*inv + __ldg(&bg1[c]));
    __syncthreads();

#pragma unroll
    for (int c=0;c<64;c++){
        float a = 0.f;
#pragma unroll
        for (int k=0;k<32;k++) a += buf[n*65+k]*__ldg(&Wg2[k*64+c]);
        y[c]=a;
    }
    __syncthreads();
#pragma unroll
    for (int c=0;c<64;c++) buf[n*65+c]=y[c];
    __syncthreads();
    if (n<64){ float s=0.f; for(int m=0;m<128;m++) s += buf[m*65+n]; S[n]=s; }
    __syncthreads();
#pragma unroll
    for (int c=0;c<64;c++)
        h_out[(base+n)*64 + c] = (S[c]-y[c])*inv + __ldg(&bg2[c]);
}

// ---------------------------------------------------------------------------
// K2 fused: blocks [0,512) = A0/B0 GEMM; blocks [512,1024) = node MLP + diag.
// Both depend only on h. Dynamic smem = K2B_SMEM.
// ---------------------------------------------------------------------------
#define K2B_W0   0
#define K2B_W1   4096
#define K2B_W2   8192
#define K2B_BA   8960
#define K2B_BB   11136
#define K2B_VB   13312
#define K2B_B0   13728
#define K2B_B1   13792
#define K2B_B2   13856
#define K2B_SMEM ((13856+16)*4)

__global__ void __launch_bounds__(256)
k2_fused(const float* __restrict__ h, const float* __restrict__ We0,
         const float* __restrict__ Wn0, const float* __restrict__ bn0,
         const float* __restrict__ Wn1, const float* __restrict__ bn1,
         const float* __restrict__ Wn2, const float* __restrict__ bn2,
         float* __restrict__ U)
{
    extern __shared__ float sm[];
    const int tid = threadIdx.x;

    if (blockIdx.x < 512){
        // ---- k2_ab ----
        float* hs = sm;                        // 32*64 floats
        const int n0 = blockIdx.x * 32;

        for (int l = tid; l < 32*64; l += 256) hs[l] = h[n0*64 + l];
        __syncthreads();

        const int col = tid & 127;
        const int kb  = (tid >> 7) * 64;

        float acc[32];
#pragma unroll
        for (int i=0;i<32;i++) acc[i]=0.f;

        for (int k=0;k<64;k++){
            float w = __ldg(&We0[(kb+k)*128 + col]);
#pragma unroll
            for (int nn=0;nn<32;nn++) acc[nn] += hs[nn*64+k]*w;
        }

        float* dst = (tid < 128) ? g_A0 : g_B0;
#pragma unroll
        for (int nn=0;nn<32;nn++) dst[(size_t)(n0+nn)*128 + col] = acc[nn];
        return;
    }

    // ---- k2b node MLP ----
    const int blk = blockIdx.x - 512;
    const int ln  = tid >> 3;       // node 0..31
    const int q   = tid & 7;        // col group (8 cols)
    const int b   = blk >> 2;
    const int n0  = (blk & 3) * 32;

    float4* w0s = reinterpret_cast<float4*>(sm + K2B_W0);
    float4* w1s = reinterpret_cast<float4*>(sm + K2B_W1);

    for (int l = tid; l < 1024; l += 256){
        w0s[l] = reinterpret_cast<const float4*>(Wn0)[l];
        w1s[l] = reinterpret_cast<const float4*>(Wn1)[l];
    }
    for (int l = tid; l < 768; l += 256){
        int k = l / 12, c = l % 12;
        sm[K2B_W2 + l] = (c < 10) ? Wn2[k*10 + c] : 0.f;
    }
    if (tid < 64){ sm[K2B_B0 + tid] = bn0[tid]; sm[K2B_B1 + tid] = bn1[tid]; }
    else if (tid < 76) sm[K2B_B2 + tid - 64] = (tid - 64 < 10) ? bn2[tid-64] : 0.f;
    for (int l = tid; l < 2048; l += 256){
        int r_ = l >> 6, c = l & 63;
        sm[K2B_BA + r_*68 + c] = h[(size_t)(b*128 + n0 + r_)*64 + c];
    }
    __syncthreads();

    {
        float acc[8];
#pragma unroll
        for (int m=0;m<8;m++) acc[m] = sm[K2B_B0 + q*8 + m];
        for (int k=0;k<64;k++){
            float hk = sm[K2B_BA + ln*68 + k];
            float4 wa = w0s[k*16 + q*2];
            float4 wb = w0s[k*16 + q*2 + 1];
            acc[0] += hk*wa.x; acc[1] += hk*wa.y; acc[2] += hk*wa.z; acc[3] += hk*wa.w;
            acc[4] += hk*wb.x; acc[5] += hk*wb.y; acc[6] += hk*wb.z; acc[7] += hk*wb.w;
        }
#pragma unroll
        for (int m=0;m<8;m++) sm[K2B_BB + ln*68 + q*8 + m] = lrelu(acc[m]);
    }
    __syncthreads();

    {
        float acc[8];
#pragma unroll
        for (int m=0;m<8;m++) acc[m] = sm[K2B_B1 + q*8 + m];
        for (int k=0;k<64;k++){
            float hk = sm[K2B_BB + ln*68 + k];
            float4 wa = w1s[k*16 + q*2];
            float4 wb = w1s[k*16 + q*2 + 1];
            acc[0] += hk*wa.x; acc[1] += hk*wa.y; acc[2] += hk*wa.z; acc[3] += hk*wa.w;
            acc[4] += hk*wb.x; acc[5] += hk*wb.y; acc[6] += hk*wb.z; acc[7] += hk*wb.w;
        }
        __syncthreads();
#pragma unroll
        for (int m=0;m<8;m++) sm[K2B_BA + ln*68 + q*8 + m] = lrelu(acc[m]);
    }
    __syncthreads();

    if (q < 6){
        const int c0 = 2*q, c1 = 2*q + 1;
        float a0 = sm[K2B_B2 + c0];
        float a1 = sm[K2B_B2 + c1];
        for (int k=0;k<64;k++){
            float hk = sm[K2B_BA + ln*68 + k];
            a0 += hk * sm[K2B_W2 + k*12 + c0];
            a1 += hk * sm[K2B_W2 + k*12 + c1];
        }
        sm[K2B_VB + ln*13 + c0] = a0;
        sm[K2B_VB + ln*13 + c1] = a1;
    }
    __syncthreads();

    if (q < 4){
        const int SMAT[16] = {0,1,2,3, 1,4,5,6, 2,5,7,8, 3,6,8,9};
        const int node = n0 + ln;
        float4 rv;
        rv.x = sm[K2B_VB + ln*13 + SMAT[q*4+0]];
        rv.y = sm[K2B_VB + ln*13 + SMAT[q*4+1]];
        rv.z = sm[K2B_VB + ln*13 + SMAT[q*4+2]];
        rv.w = sm[K2B_VB + ln*13 + SMAT[q*4+3]];
        float* Ub = U + (size_t)b*U_PER_B;
        *reinterpret_cast<float4*>(Ub + (size_t)(4*node+q)*U_STRIDE + 4*node) = rv;
    }
}

// ---------------------------------------------------------------------------
// K3: edge MLP. GEMM1: register-built fp16 A x single fp16 B (We1^T).
// GEMM2: bf16 3-split chained. Direct float2 scatter epilogue (round-6 best).
// ---------------------------------------------------------------------------
#define OFF_BHI  0                    // 34816
#define OFF_W2HI 34816                // 4352
#define OFF_W2LO 39168                // 4352
#define OFF_BE1  43520                // 512
#define OFF_BE2  44032                // 64
#define OFF_STG  44096                // A0s[8][132] + B0s[16][132] = 12672
#define OFF_A0S  OFF_STG
#define OFF_B0S  (OFF_STG + 8*132*4)
#define OFF_ES   OFF_STG              // alias: [128][20] f = 10240
#define K3_SMEM  (OFF_STG + 12672)    // 56768 B

__global__ void __launch_bounds__(256, 2)
k3_edge_mma(const float* __restrict__ be0,
            const float* __restrict__ be1,
            const float* __restrict__ be2,
            float* __restrict__ U)
{
    extern __shared__ char smem[];
    float* smemf = reinterpret_cast<float*>(smem);
    const uint32_t sb = smem_u32(smem);
    const int tid = threadIdx.x;
    const int wid = tid >> 5;
    const int lane = tid & 31;
    const int g = lane >> 2;
    const int r = lane & 3;

    // triangular tile decode: jt s.t. jt(jt+1) <= t < (jt+1)(jt+2)
    const int t = blockIdx.x;
    int jt = 0;
#pragma unroll
    for (int q=1;q<8;q++) if (t >= q*(q+1)) jt = q;
    const int it = t - jt*(jt+1);
    const int b  = blockIdx.y;
    const int i0 = it*8, j0 = jt*16;

    // ---- stage weights + A0/B0 rows ----
    {
        const uint4* sh  = reinterpret_cast<const uint4*>(g_Bhi);
        uint4* dh = reinterpret_cast<uint4*>(smem + OFF_BHI);
        for (int l = tid; l < 2176; l += 256) dh[l] = sh[l];
        const uint4* s2h = reinterpret_cast<const uint4*>(g_W2hi);
        const uint4* s2l = reinterpret_cast<const uint4*>(g_W2lo);
        uint4* d2h = reinterpret_cast<uint4*>(smem + OFF_W2HI);
        uint4* d2l = reinterpret_cast<uint4*>(smem + OFF_W2LO);
        for (int l = tid; l < 272; l += 256){ d2h[l] = s2h[l]; d2l[l] = s2l[l]; }
        if (tid < 128) smemf[OFF_BE1/4 + tid] = be1[tid];
        else if (tid < 144) smemf[OFF_BE2/4 + tid - 128] = be2[tid - 128];
        // A0s: 8 rows x 128 f (no be0); B0s: 16 rows x 128 f (+be0)
        for (int l = tid; l < 256; l += 256){
            int rr = l >> 5, c4 = (l & 31)*4;
            float4 v = *reinterpret_cast<const float4*>(g_A0 + ((size_t)(b*NN + i0 + rr))*128 + c4);
            *reinterpret_cast<float4*>(smemf + OFF_A0S/4 + rr*132 + c4) = v;
        }
        for (int l = tid; l < 512; l += 256){
            int rr = l >> 5, c4 = (l & 31)*4;
            float4 v  = *reinterpret_cast<const float4*>(g_B0 + ((size_t)(b*NN + j0 + rr))*128 + c4);
            float4 e0 = *reinterpret_cast<const float4*>(be0 + c4);
            v.x += e0.x; v.y += e0.y; v.z += e0.z; v.w += e0.w;
            *reinterpret_cast<float4*>(smemf + OFF_B0S/4 + rr*132 + c4) = v;
        }
    }
    __syncthreads();

    const int mg = wid >> 1;       // 0..3 -> rows mg*32..+31
    const int ng = wid & 1;        // 0..1 -> cols ng*64..+63
    float acc[2][8][4];
#pragma unroll
    for (int a1=0;a1<2;a1++)
#pragma unroll
        for (int a2=0;a2<8;a2++)
#pragma unroll
            for (int a3=0;a3<4;a3++) acc[a1][a2][a3] = 0.f;

    // ---- GEMM1: register-built fp16 A (t0) x single fp16 B (We1^T) ----
    {
        const uint32_t bOff = (uint32_t)((ng*64 + ((lane >> 4) << 3) + (lane & 7))*272
                                        + ((lane >> 3) & 1)*16);
        const uint32_t bHi = sb + OFF_BHI + bOff;
        const float* A0p = smemf + OFF_A0S/4;
        const float* B0p = smemf + OFF_B0S/4;

#pragma unroll
        for (int ks = 0; ks < 8; ks++){
            // B0 rows j = g, g+8 (shared across mt)
            float2 b00 = *reinterpret_cast<const float2*>(B0p + g*132      + ks*16 + 2*r);
            float2 b01 = *reinterpret_cast<const float2*>(B0p + g*132      + ks*16 + 8 + 2*r);
            float2 b10 = *reinterpret_cast<const float2*>(B0p + (g+8)*132  + ks*16 + 2*r);
            float2 b11 = *reinterpret_cast<const float2*>(B0p + (g+8)*132  + ks*16 + 8 + 2*r);

            uint32_t ah[2][4];
#pragma unroll
            for (int mt=0; mt<2; mt++){
                const float* Ar = A0p + (mg*2+mt)*132 + ks*16;
                float2 ak0 = *reinterpret_cast<const float2*>(Ar + 2*r);
                float2 ak1 = *reinterpret_cast<const float2*>(Ar + 8 + 2*r);
                ah[mt][0] = packh2(lrelu(ak0.x+b00.x), lrelu(ak0.y+b00.y));
                ah[mt][1] = packh2(lrelu(ak0.x+b10.x), lrelu(ak0.y+b10.y));
                ah[mt][2] = packh2(lrelu(ak1.x+b01.x), lrelu(ak1.y+b01.y));
                ah[mt][3] = packh2(lrelu(ak1.x+b11.x), lrelu(ak1.y+b11.y));
            }
#pragma unroll
            for (int n2 = 0; n2 < 4; n2++){
                uint32_t bh[4];
                LDM4(bh, bHi + n2*4352 + ks*32);
                MMA16816H(acc[0][2*n2],   ah[0], bh[0], bh[1]);
                MMA16816H(acc[0][2*n2+1], ah[0], bh[2], bh[3]);
                MMA16816H(acc[1][2*n2],   ah[1], bh[0], bh[1]);
                MMA16816H(acc[1][2*n2+1], ah[1], bh[2], bh[3]);
            }
        }
    }

    // ---- GEMM2: chain acc -> t1 A-fragments (bf16 3-split), partial e ----
    float e[2][2][4];
#pragma unroll
    for (int a1=0;a1<2;a1++)
#pragma unroll
        for (int a2=0;a2<2;a2++)
#pragma unroll
            for (int a3=0;a3<4;a3++) e[a1][a2][a3] = 0.f;

    {
        const uint32_t b2Off = (uint32_t)(((((lane >> 4) << 3) + (lane & 7))*272)
                                        + ((lane >> 3) & 1)*16);
        const uint32_t wHi = sb + OFF_W2HI + b2Off, wLo = sb + OFF_W2LO + b2Off;

#pragma unroll
        for (int qk = 0; qk < 4; qk++){
            uint32_t bh[4], bl[4];
            LDM4(bh, wHi + (ng*4+qk)*32);
            LDM4(bl, wLo + (ng*4+qk)*32);
#pragma unroll
            for (int mt = 0; mt < 2; mt++){
                const int ntA = 2*qk, ntB = 2*qk+1;
                const int cA = ng*64 + ntA*8 + 2*r;
                const int cB = ng*64 + ntB*8 + 2*r;
                float beA0 = smemf[OFF_BE1/4 + cA], beA1 = smemf[OFF_BE1/4 + cA + 1];
                float beB0 = smemf[OFF_BE1/4 + cB], beB1 = smemf[OFF_BE1/4 + cB + 1];
                uint32_t ah[4], al[4];
                split2(lrelu(acc[mt][ntA][0]+beA0), lrelu(acc[mt][ntA][1]+beA1), ah[0], al[0]);
                split2(lrelu(acc[mt][ntA][2]+beA0), lrelu(acc[mt][ntA][3]+beA1), ah[1], al[1]);
                split2(lrelu(acc[mt][ntB][0]+beB0), lrelu(acc[mt][ntB][1]+beB1), ah[2], al[2]);
                split2(lrelu(acc[mt][ntB][2]+beB0), lrelu(acc[mt][ntB][3]+beB1), ah[3], al[3]);
                MMA16816(e[mt][0], ah, bh[0], bh[1]);
                MMA16816(e[mt][0], al, bh[0], bh[1]);
                MMA16816(e[mt][0], ah, bl[0], bl[1]);
                MMA16816(e[mt][1], ah, bh[2], bh[3]);
                MMA16816(e[mt][1], al, bh[2], bh[3]);
                MMA16816(e[mt][1], ah, bl[2], bl[3]);
            }
        }
    }

    // ---- cross-warp (ng pair) reduction + direct scatter into U ----
    __syncthreads();   // A0s/B0s reads done; safe to overwrite with ES
    float* es = smemf + OFF_ES/4;   // [128][20]

    if (ng == 1){
#pragma unroll
        for (int mt=0; mt<2; mt++)
#pragma unroll
        for (int t_=0; t_<2; t_++)
#pragma unroll
        for (int rh=0; rh<2; rh++){
            int row = mg*32 + mt*16 + g + rh*8;
            int c = t_*8 + 2*r;
            *reinterpret_cast<float2*>(&es[row*20 + c]) =
                make_float2(e[mt][t_][rh*2+0], e[mt][t_][rh*2+1]);
        }
    }
    __syncthreads();
    if (ng == 0){
        float* Ub = U + (size_t)b*U_PER_B;
#pragma unroll
        for (int mt=0; mt<2; mt++)
#pragma unroll
        for (int t_=0; t_<2; t_++)
#pragma unroll
        for (int rh=0; rh<2; rh++){
            int row = mg*32 + mt*16 + g + rh*8;
            int c = t_*8 + 2*r;
            float2 part = *reinterpret_cast<const float2*>(&es[row*20 + c]);
            float vx = e[mt][t_][rh*2+0] + part.x + smemf[OFF_BE2/4 + c];
            float vy = e[mt][t_][rh*2+1] + part.y + smemf[OFF_BE2/4 + c + 1];
            int i = i0 + (row >> 4);
            int j = j0 + (row & 15);
            if (i < j){
                int qq = c >> 2, m = c & 3;
                float2 v2 = make_float2(vx, vy);
                *reinterpret_cast<float2*>(Ub + (size_t)(4*i+qq)*U_STRIDE + 4*j + m) = v2;
                *reinterpret_cast<float2*>(Ub + (size_t)(4*j+qq)*U_STRIDE + 4*i + m) = v2;
            }
        }
    }
}

// ---------------------------------------------------------------------------
extern "C" void kernel_launch(void* const* d_in, const int* in_sizes, int n_in,
                              void* d_out, int out_size)
{
    const float* x   = (const float*)d_in[0];
    const float* Wg0 = (const float*)d_in[4];
    const float* bg0 = (const float*)d_in[5];
    const float* Wg1 = (const float*)d_in[6];
    const float* bg1 = (const float*)d_in[7];
    const float* Wg2 = (const float*)d_in[8];
    const float* bg2 = (const float*)d_in[9];
    const float* Wn0 = (const float*)d_in[10];
    const float* bn0 = (const float*)d_in[11];
    const float* Wn1 = (const float*)d_in[12];
    const float* bn1 = (const float*)d_in[13];
    const float* Wn2 = (const float*)d_in[14];
    const float* bn2 = (const float*)d_in[15];
    const float* We0 = (const float*)d_in[16];
    const float* be0 = (const float*)d_in[17];
    const float* We1 = (const float*)d_in[18];
    const float* be1 = (const float*)d_in[19];
    const float* We2 = (const float*)d_in[20];
    const float* be2 = (const float*)d_in[21];

    float* h_out = (float*)d_out;                 // (16384, 64)
    float* U     = h_out + (size_t)TOTAL*D_MP;    // (128, 512, 512)

    static bool attr_set = false;
    if (!attr_set){
        cudaFuncSetAttribute(k3_edge_mma, cudaFuncAttributeMaxDynamicSharedMemorySize, K3_SMEM);
        cudaFuncSetAttribute(k2_fused, cudaFuncAttributeMaxDynamicSharedMemorySize, K2B_SMEM);
        attr_set = true;
    }

    k1_fused<<<272, 128>>>(x, Wg0,bg0, Wg1,bg1, Wg2,bg2, We1, We2, h_out);
    k2_fused<<<1024, 256, K2B_SMEM>>>(h_out, We0, Wn0,bn0, Wn1,bn1, Wn2,bn2, U);
    k3_edge_mma<<<dim3(72, BATCH), 256, K3_SMEM>>>(be0, be1, be2, U);
}

// round 10
// speedup vs baseline: 1.6208x; 1.0712x over previous
#include <cuda_runtime.h>
#include <cuda_bf16.h>
#include <cuda_fp16.h>
#include <cstdint>

// Problem constants
#define BATCH 128
#define NN    128
#define D_IN  6
#define D_MP  64
#define TOTAL (BATCH*NN)    // 16384
#define U_STRIDE 512
#define U_PER_B  (512*512)

__device__ float g_A0[TOTAL*128];           // h @ We0[:64]
__device__ float g_B0[TOTAL*128];           // h @ We0[64:]
__device__ __half g_Bhi[128*136];           // We1^T fp16, padded [n][136]
__device__ __half g_W2hi[16*136];           // We2^T fp16 hi, padded [c][136]
__device__ __half g_W2lo[16*136];           // We2^T fp16 lo residual

__device__ __forceinline__ float lrelu(float v){ return v >= 0.f ? v : 0.1f*v; }

__device__ __forceinline__ uint32_t smem_u32(const void* p){
    uint32_t a;
    asm("{ .reg .u64 t; cvta.to.shared.u64 t, %1; cvt.u32.u64 %0, t; }"
        : "=r"(a) : "l"(p));
    return a;
}

#define LDM4(r, addr) \
    asm volatile("ldmatrix.sync.aligned.m8n8.x4.shared.b16 {%0,%1,%2,%3}, [%4];" \
        : "=r"((r)[0]), "=r"((r)[1]), "=r"((r)[2]), "=r"((r)[3]) : "r"(addr))

#define MMA16816H(d, a, b0_, b1_) \
    asm volatile("mma.sync.aligned.m16n8k16.row.col.f32.f16.f16.f32 " \
        "{%0,%1,%2,%3}, {%4,%5,%6,%7}, {%8,%9}, {%0,%1,%2,%3};" \
        : "+f"((d)[0]), "+f"((d)[1]), "+f"((d)[2]), "+f"((d)[3]) \
        : "r"((a)[0]), "r"((a)[1]), "r"((a)[2]), "r"((a)[3]), "r"(b0_), "r"(b1_))

__device__ __forceinline__ uint32_t packh2(float s0, float s1){
    __half2 h2 = __floats2half2_rn(s0, s1);
    return *reinterpret_cast<uint32_t*>(&h2);
}

// ---------------------------------------------------------------------------
// K1 fused: blocks [0,128) = GCN (256 thr, 2/node); blocks [128,200) = prep.
// ---------------------------------------------------------------------------
__global__ void __launch_bounds__(256)
k1_fused(const float* __restrict__ x,
         const float* __restrict__ Wg0, const float* __restrict__ bg0,
         const float* __restrict__ Wg1, const float* __restrict__ bg1,
         const float* __restrict__ Wg2, const float* __restrict__ bg2,
         const float* __restrict__ We1, const float* __restrict__ We2,
         float* __restrict__ h_out)
{
    const int tid = threadIdx.x;

    if (blockIdx.x >= 128){
        // ---- prep: We1^T -> fp16, We2^T -> fp16 hi/lo ----
        int idx = (blockIdx.x - 128)*256 + tid;            // 0..18431
        if (idx < 128*128){
            int k = idx >> 7, n = idx & 127;
            g_Bhi[n*136 + k] = __float2half_rn(We1[k*128 + n]);
        } else {
            int r = idx - 128*128;                         // 0..2047
            int k = r >> 4, c = r & 15;
            float w = We2[k*16 + c];
            __half h = __float2half_rn(w);
            float lo = w - __half2float(h);
            g_W2hi[c*136 + k] = h;
            g_W2lo[c*136 + k] = __float2half_rn(lo);
        }
        return;
    }

    __shared__ float buf[128*65];
    __shared__ float Sp[8*33];      // layer0/1 partials (8 octs x 32 cols)
    __shared__ float Sp2[4*66];     // layer2 partials (4 quads x 64 cols)
    __shared__ float S[64];
    const int n  = tid >> 1;
    const int hf = tid & 1;
    const int base = blockIdx.x * NN;
    const float inv = 1.0f/127.0f;

    float xr[D_IN];
#pragma unroll
    for (int k=0;k<D_IN;k++) xr[k] = x[(base+n)*D_IN + k];

    float y[32];

    // ---- layer 0: D_IN -> 32, my cols [hf*16, hf*16+16) ----
#pragma unroll
    for (int cc=0;cc<16;cc++){
        int c = hf*16 + cc;
        float a = 0.f;
#pragma unroll
        for (int k=0;k<D_IN;k++) a += xr[k]*__ldg(&Wg0[k*32+c]);
        y[cc]=a; buf[n*65+c]=a;
    }
    __syncthreads();
    {
        int col = tid & 31, oct = tid >> 5;
        float s = 0.f;
#pragma unroll
        for (int m=0;m<16;m++) s += buf[(oct*16+m)*65 + col];
        Sp[oct*33 + col] = s;
    }
    __syncthreads();
    if (tid < 32){
        float s = 0.f;
#pragma unroll
        for (int o=0;o<8;o++) s += Sp[o*33 + tid];
        S[tid] = s;
    }
    __syncthreads();
#pragma unroll
    for (int cc=0;cc<16;cc++){
        int c = hf*16 + cc;
        buf[n*65+c] = lrelu((S[c]-y[cc])*inv + __ldg(&bg0[c]));
    }
    __syncthreads();

    // ---- layer 1: 32 -> 32 ----
#pragma unroll
    for (int cc=0;cc<16;cc++){
        int c = hf*16 + cc;
        float a = 0.f;
#pragma unroll
        for (int k=0;k<32;k++) a += buf[n*65+k]*__ldg(&Wg1[k*32+c]);
        y[cc]=a;
    }
    __syncthreads();
#pragma unroll
    for (int cc=0;cc<16;cc++) buf[n*65 + hf*16 + cc] = y[cc];
    __syncthreads();
    {
        int col = tid & 31, oct = tid >> 5;
        float s = 0.f;
#pragma unroll
        for (int m=0;m<16;m++) s += buf[(oct*16+m)*65 + col];
        Sp[oct*33 + col] = s;
    }
    __syncthreads();
    if (tid < 32){
        float s = 0.f;
#pragma unroll
        for (int o=0;o<8;o++) s += Sp[o*33 + tid];
        S[tid] = s;
    }
    __syncthreads();
#pragma unroll
    for (int cc=0;cc<16;cc++){
        int c = hf*16 + cc;
        buf[n*65+c] = lrelu((S[c]-y[cc])*inv + __ldg(&bg1[c]));
    }
    __syncthreads();

    // ---- layer 2: 32 -> 64, my cols [hf*32, hf*32+32) ----
#pragma unroll
    for (int cc=0;cc<32;cc++){
        int c = hf*32 + cc;
        float a = 0.f;
#pragma unroll
        for (int k=0;k<32;k++) a += buf[n*65+k]*__ldg(&Wg2[k*64+c]);
        y[cc]=a;
    }
    __syncthreads();
#pragma unroll
    for (int cc=0;cc<32;cc++) buf[n*65 + hf*32 + cc] = y[cc];
    __syncthreads();
    {
        int col = tid & 63, quad = tid >> 6;
        float s = 0.f;
#pragma unroll
        for (int m=0;m<32;m++) s += buf[(quad*32+m)*65 + col];
        Sp2[quad*66 + col] = s;
    }
    __syncthreads();
    if (tid < 64){
        float s = 0.f;
#pragma unroll
        for (int qd=0;qd<4;qd++) s += Sp2[qd*66 + tid];
        S[tid] = s;
    }
    __syncthreads();
#pragma unroll
    for (int cc=0;cc<32;cc++){
        int c = hf*32 + cc;
        h_out[(base+n)*64 + c] = (S[c]-y[cc])*inv + __ldg(&bg2[c]);
    }
}

// ---------------------------------------------------------------------------
// K2 fused: blocks [0,512) = A0/B0 GEMM; blocks [512,1024) = node MLP + diag.
// ---------------------------------------------------------------------------
#define K2B_W0   0
#define K2B_W1   4096
#define K2B_W2   8192
#define K2B_BA   8960
#define K2B_BB   11136
#define K2B_VB   13312
#define K2B_B0   13728
#define K2B_B1   13792
#define K2B_B2   13856
#define K2B_SMEM ((13856+16)*4)

__global__ void __launch_bounds__(256)
k2_fused(const float* __restrict__ h, const float* __restrict__ We0,
         const float* __restrict__ Wn0, const float* __restrict__ bn0,
         const float* __restrict__ Wn1, const float* __restrict__ bn1,
         const float* __restrict__ Wn2, const float* __restrict__ bn2,
         float* __restrict__ U)
{
    extern __shared__ float sm[];
    const int tid = threadIdx.x;

    if (blockIdx.x < 512){
        // ---- k2_ab ----
        float* hs = sm;
        const int n0 = blockIdx.x * 32;

        for (int l = tid; l < 32*64; l += 256) hs[l] = h[n0*64 + l];
        __syncthreads();

        const int col = tid & 127;
        const int kb  = (tid >> 7) * 64;

        float acc[32];
#pragma unroll
        for (int i=0;i<32;i++) acc[i]=0.f;

        for (int k=0;k<64;k++){
            float w = __ldg(&We0[(kb+k)*128 + col]);
#pragma unroll
            for (int nn=0;nn<32;nn++) acc[nn] += hs[nn*64+k]*w;
        }

        float* dst = (tid < 128) ? g_A0 : g_B0;
#pragma unroll
        for (int nn=0;nn<32;nn++) dst[(size_t)(n0+nn)*128 + col] = acc[nn];
        return;
    }

    // ---- k2b node MLP ----
    const int blk = blockIdx.x - 512;
    const int ln  = tid >> 3;
    const int q   = tid & 7;
    const int b   = blk >> 2;
    const int n0  = (blk & 3) * 32;

    float4* w0s = reinterpret_cast<float4*>(sm + K2B_W0);
    float4* w1s = reinterpret_cast<float4*>(sm + K2B_W1);

    for (int l = tid; l < 1024; l += 256){
        w0s[l] = reinterpret_cast<const float4*>(Wn0)[l];
        w1s[l] = reinterpret_cast<const float4*>(Wn1)[l];
    }
    for (int l = tid; l < 768; l += 256){
        int k = l / 12, c = l % 12;
        sm[K2B_W2 + l] = (c < 10) ? Wn2[k*10 + c] : 0.f;
    }
    if (tid < 64){ sm[K2B_B0 + tid] = bn0[tid]; sm[K2B_B1 + tid] = bn1[tid]; }
    else if (tid < 76) sm[K2B_B2 + tid - 64] = (tid - 64 < 10) ? bn2[tid-64] : 0.f;
    for (int l = tid; l < 2048; l += 256){
        int r_ = l >> 6, c = l & 63;
        sm[K2B_BA + r_*68 + c] = h[(size_t)(b*128 + n0 + r_)*64 + c];
    }
    __syncthreads();

    {
        float acc[8];
#pragma unroll
        for (int m=0;m<8;m++) acc[m] = sm[K2B_B0 + q*8 + m];
        for (int k=0;k<64;k++){
            float hk = sm[K2B_BA + ln*68 + k];
            float4 wa = w0s[k*16 + q*2];
            float4 wb = w0s[k*16 + q*2 + 1];
            acc[0] += hk*wa.x; acc[1] += hk*wa.y; acc[2] += hk*wa.z; acc[3] += hk*wa.w;
            acc[4] += hk*wb.x; acc[5] += hk*wb.y; acc[6] += hk*wb.z; acc[7] += hk*wb.w;
        }
#pragma unroll
        for (int m=0;m<8;m++) sm[K2B_BB + ln*68 + q*8 + m] = lrelu(acc[m]);
    }
    __syncthreads();

    {
        float acc[8];
#pragma unroll
        for (int m=0;m<8;m++) acc[m] = sm[K2B_B1 + q*8 + m];
        for (int k=0;k<64;k++){
            float hk = sm[K2B_BB + ln*68 + k];
            float4 wa = w1s[k*16 + q*2];
            float4 wb = w1s[k*16 + q*2 + 1];
            acc[0] += hk*wa.x; acc[1] += hk*wa.y; acc[2] += hk*wa.z; acc[3] += hk*wa.w;
            acc[4] += hk*wb.x; acc[5] += hk*wb.y; acc[6] += hk*wb.z; acc[7] += hk*wb.w;
        }
        __syncthreads();
#pragma unroll
        for (int m=0;m<8;m++) sm[K2B_BA + ln*68 + q*8 + m] = lrelu(acc[m]);
    }
    __syncthreads();

    if (q < 6){
        const int c0 = 2*q, c1 = 2*q + 1;
        float a0 = sm[K2B_B2 + c0];
        float a1 = sm[K2B_B2 + c1];
        for (int k=0;k<64;k++){
            float hk = sm[K2B_BA + ln*68 + k];
            a0 += hk * sm[K2B_W2 + k*12 + c0];
            a1 += hk * sm[K2B_W2 + k*12 + c1];
        }
        sm[K2B_VB + ln*13 + c0] = a0;
        sm[K2B_VB + ln*13 + c1] = a1;
    }
    __syncthreads();

    if (q < 4){
        const int SMAT[16] = {0,1,2,3, 1,4,5,6, 2,5,7,8, 3,6,8,9};
        const int node = n0 + ln;
        float4 rv;
        rv.x = sm[K2B_VB + ln*13 + SMAT[q*4+0]];
        rv.y = sm[K2B_VB + ln*13 + SMAT[q*4+1]];
        rv.z = sm[K2B_VB + ln*13 + SMAT[q*4+2]];
        rv.w = sm[K2B_VB + ln*13 + SMAT[q*4+3]];
        float* Ub = U + (size_t)b*U_PER_B;
        *reinterpret_cast<float4*>(Ub + (size_t)(4*node+q)*U_STRIDE + 4*node) = rv;
    }
}

// ---------------------------------------------------------------------------
// K3: edge MLP. GEMM1: register-built fp16 A x single fp16 B (We1^T).
// GEMM2: fp16 A single x fp16 B 2-split (We2^T hi/lo). Direct scatter.
// ---------------------------------------------------------------------------
#define OFF_BHI  0                    // 34816
#define OFF_W2HI 34816                // 4352
#define OFF_W2LO 39168                // 4352
#define OFF_BE1  43520                // 512
#define OFF_BE2  44032                // 64
#define OFF_STG  44096                // A0s[8][132] + B0s[16][132] = 12672
#define OFF_A0S  OFF_STG
#define OFF_B0S  (OFF_STG + 8*132*4)
#define OFF_ES   OFF_STG              // alias: [128][20] f = 10240
#define K3_SMEM  (OFF_STG + 12672)    // 56768 B

__global__ void __launch_bounds__(256, 2)
k3_edge_mma(const float* __restrict__ be0,
            const float* __restrict__ be1,
            const float* __restrict__ be2,
            float* __restrict__ U)
{
    extern __shared__ char smem[];
    float* smemf = reinterpret_cast<float*>(smem);
    const uint32_t sb = smem_u32(smem);
    const int tid = threadIdx.x;
    const int wid = tid >> 5;
    const int lane = tid & 31;
    const int g = lane >> 2;
    const int r = lane & 3;

    // triangular tile decode: jt s.t. jt(jt+1) <= t < (jt+1)(jt+2)
    const int t = blockIdx.x;
    int jt = 0;
#pragma unroll
    for (int q=1;q<8;q++) if (t >= q*(q+1)) jt = q;
    const int it = t - jt*(jt+1);
    const int b  = blockIdx.y;
    const int i0 = it*8, j0 = jt*16;

    // ---- stage weights + A0/B0 rows ----
    {
        const uint4* sh  = reinterpret_cast<const uint4*>(g_Bhi);
        uint4* dh = reinterpret_cast<uint4*>(smem + OFF_BHI);
        for (int l = tid; l < 2176; l += 256) dh[l] = sh[l];
        const uint4* s2h = reinterpret_cast<const uint4*>(g_W2hi);
        const uint4* s2l = reinterpret_cast<const uint4*>(g_W2lo);
        uint4* d2h = reinterpret_cast<uint4*>(smem + OFF_W2HI);
        uint4* d2l = reinterpret_cast<uint4*>(smem + OFF_W2LO);
        for (int l = tid; l < 272; l += 256){ d2h[l] = s2h[l]; d2l[l] = s2l[l]; }
        if (tid < 128) smemf[OFF_BE1/4 + tid] = be1[tid];
        else if (tid < 144) smemf[OFF_BE2/4 + tid - 128] = be2[tid - 128];
        // A0s: 8 rows x 128 f (no be0); B0s: 16 rows x 128 f (+be0)
        for (int l = tid; l < 256; l += 256){
            int rr = l >> 5, c4 = (l & 31)*4;
            float4 v = *reinterpret_cast<const float4*>(g_A0 + ((size_t)(b*NN + i0 + rr))*128 + c4);
            *reinterpret_cast<float4*>(smemf + OFF_A0S/4 + rr*132 + c4) = v;
        }
        for (int l = tid; l < 512; l += 256){
            int rr = l >> 5, c4 = (l & 31)*4;
            float4 v  = *reinterpret_cast<const float4*>(g_B0 + ((size_t)(b*NN + j0 + rr))*128 + c4);
            float4 e0 = *reinterpret_cast<const float4*>(be0 + c4);
            v.x += e0.x; v.y += e0.y; v.z += e0.z; v.w += e0.w;
            *reinterpret_cast<float4*>(smemf + OFF_B0S/4 + rr*132 + c4) = v;
        }
    }
    __syncthreads();

    const int mg = wid >> 1;       // 0..3 -> rows mg*32..+31
    const int ng = wid & 1;        // 0..1 -> cols ng*64..+63
    float acc[2][8][4];
#pragma unroll
    for (int a1=0;a1<2;a1++)
#pragma unroll
        for (int a2=0;a2<8;a2++)
#pragma unroll
            for (int a3=0;a3<4;a3++) acc[a1][a2][a3] = 0.f;

    // ---- GEMM1: register-built fp16 A (t0) x single fp16 B (We1^T) ----
    {
        const uint32_t bOff = (uint32_t)((ng*64 + ((lane >> 4) << 3) + (lane & 7))*272
                                        + ((lane >> 3) & 1)*16);
        const uint32_t bHi = sb + OFF_BHI + bOff;
        const float* A0p = smemf + OFF_A0S/4;
        const float* B0p = smemf + OFF_B0S/4;

#pragma unroll
        for (int ks = 0; ks < 8; ks++){
            float2 b00 = *reinterpret_cast<const float2*>(B0p + g*132      + ks*16 + 2*r);
            float2 b01 = *reinterpret_cast<const float2*>(B0p + g*132      + ks*16 + 8 + 2*r);
            float2 b10 = *reinterpret_cast<const float2*>(B0p + (g+8)*132  + ks*16 + 2*r);
            float2 b11 = *reinterpret_cast<const float2*>(B0p + (g+8)*132  + ks*16 + 8 + 2*r);

            uint32_t ah[2][4];
#pragma unroll
            for (int mt=0; mt<2; mt++){
                const float* Ar = A0p + (mg*2+mt)*132 + ks*16;
                float2 ak0 = *reinterpret_cast<const float2*>(Ar + 2*r);
                float2 ak1 = *reinterpret_cast<const float2*>(Ar + 8 + 2*r);
                ah[mt][0] = packh2(lrelu(ak0.x+b00.x), lrelu(ak0.y+b00.y));
                ah[mt][1] = packh2(lrelu(ak0.x+b10.x), lrelu(ak0.y+b10.y));
                ah[mt][2] = packh2(lrelu(ak1.x+b01.x), lrelu(ak1.y+b01.y));
                ah[mt][3] = packh2(lrelu(ak1.x+b11.x), lrelu(ak1.y+b11.y));
            }
#pragma unroll
            for (int n2 = 0; n2 < 4; n2++){
                uint32_t bh[4];
                LDM4(bh, bHi + n2*4352 + ks*32);
                MMA16816H(acc[0][2*n2],   ah[0], bh[0], bh[1]);
                MMA16816H(acc[0][2*n2+1], ah[0], bh[2], bh[3]);
                MMA16816H(acc[1][2*n2],   ah[1], bh[0], bh[1]);
                MMA16816H(acc[1][2*n2+1], ah[1], bh[2], bh[3]);
            }
        }
    }

    // ---- GEMM2: chain acc -> t1 fp16 A-fragments x We2^T fp16 hi/lo ----
    float e[2][2][4];
#pragma unroll
    for (int a1=0;a1<2;a1++)
#pragma unroll
        for (int a2=0;a2<2;a2++)
#pragma unroll
            for (int a3=0;a3<4;a3++) e[a1][a2][a3] = 0.f;

    {
        const uint32_t b2Off = (uint32_t)(((((lane >> 4) << 3) + (lane & 7))*272)
                                        + ((lane >> 3) & 1)*16);
        const uint32_t wHi = sb + OFF_W2HI + b2Off, wLo = sb + OFF_W2LO + b2Off;

#pragma unroll
        for (int qk = 0; qk < 4; qk++){
            uint32_t bh[4], bl[4];
            LDM4(bh, wHi + (ng*4+qk)*32);
            LDM4(bl, wLo + (ng*4+qk)*32);
#pragma unroll
            for (int mt = 0; mt < 2; mt++){
                const int ntA = 2*qk, ntB = 2*qk+1;
                const int cA = ng*64 + ntA*8 + 2*r;
                const int cB = ng*64 + ntB*8 + 2*r;
                float beA0 = smemf[OFF_BE1/4 + cA], beA1 = smemf[OFF_BE1/4 + cA + 1];
                float beB0 = smemf[OFF_BE1/4 + cB], beB1 = smemf[OFF_BE1/4 + cB + 1];
                uint32_t ah[4];
                ah[0] = packh2(lrelu(acc[mt][ntA][0]+beA0), lrelu(acc[mt][ntA][1]+beA1));
                ah[1] = packh2(lrelu(acc[mt][ntA][2]+beA0), lrelu(acc[mt][ntA][3]+beA1));
                ah[2] = packh2(lrelu(acc[mt][ntB][0]+beB0), lrelu(acc[mt][ntB][1]+beB1));
                ah[3] = packh2(lrelu(acc[mt][ntB][2]+beB0), lrelu(acc[mt][ntB][3]+beB1));
                MMA16816H(e[mt][0], ah, bh[0], bh[1]);
                MMA16816H(e[mt][0], ah, bl[0], bl[1]);
                MMA16816H(e[mt][1], ah, bh[2], bh[3]);
                MMA16816H(e[mt][1], ah, bl[2], bl[3]);
            }
        }
    }

    // ---- cross-warp (ng pair) reduction + direct scatter into U ----
    __syncthreads();   // A0s/B0s reads done; safe to overwrite with ES
    float* es = smemf + OFF_ES/4;   // [128][20]

    if (ng == 1){
#pragma unroll
        for (int mt=0; mt<2; mt++)
#pragma unroll
        for (int t_=0; t_<2; t_++)
#pragma unroll
        for (int rh=0; rh<2; rh++){
            int row = mg*32 + mt*16 + g + rh*8;
            int c = t_*8 + 2*r;
            *reinterpret_cast<float2*>(&es[row*20 + c]) =
                make_float2(e[mt][t_][rh*2+0], e[mt][t_][rh*2+1]);
        }
    }
    __syncthreads();
    if (ng == 0){
        float* Ub = U + (size_t)b*U_PER_B;
#pragma unroll
        for (int mt=0; mt<2; mt++)
#pragma unroll
        for (int t_=0; t_<2; t_++)
#pragma unroll
        for (int rh=0; rh<2; rh++){
            int row = mg*32 + mt*16 + g + rh*8;
            int c = t_*8 + 2*r;
            float2 part = *reinterpret_cast<const float2*>(&es[row*20 + c]);
            float vx = e[mt][t_][rh*2+0] + part.x + smemf[OFF_BE2/4 + c];
            float vy = e[mt][t_][rh*2+1] + part.y + smemf[OFF_BE2/4 + c + 1];
            int i = i0 + (row >> 4);
            int j = j0 + (row & 15);
            if (i < j){
                int qq = c >> 2, m = c & 3;
                float2 v2 = make_float2(vx, vy);
                *reinterpret_cast<float2*>(Ub + (size_t)(4*i+qq)*U_STRIDE + 4*j + m) = v2;
                *reinterpret_cast<float2*>(Ub + (size_t)(4*j+qq)*U_STRIDE + 4*i + m) = v2;
            }
        }
    }
}

// ---------------------------------------------------------------------------
extern "C" void kernel_launch(void* const* d_in, const int* in_sizes, int n_in,
                              void* d_out, int out_size)
{
    const float* x   = (const float*)d_in[0];
    const float* Wg0 = (const float*)d_in[4];
    const float* bg0 = (const float*)d_in[5];
    const float* Wg1 = (const float*)d_in[6];
    const float* bg1 = (const float*)d_in[7];
    const float* Wg2 = (const float*)d_in[8];
    const float* bg2 = (const float*)d_in[9];
    const float* Wn0 = (const float*)d_in[10];
    const float* bn0 = (const float*)d_in[11];
    const float* Wn1 = (const float*)d_in[12];
    const float* bn1 = (const float*)d_in[13];
    const float* Wn2 = (const float*)d_in[14];
    const float* bn2 = (const float*)d_in[15];
    const float* We0 = (const float*)d_in[16];
    const float* be0 = (const float*)d_in[17];
    const float* We1 = (const float*)d_in[18];
    const float* be1 = (const float*)d_in[19];
    const float* We2 = (const float*)d_in[20];
    const float* be2 = (const float*)d_in[21];

    float* h_out = (float*)d_out;                 // (16384, 64)
    float* U     = h_out + (size_t)TOTAL*D_MP;    // (128, 512, 512)

    static bool attr_set = false;
    if (!attr_set){
        cudaFuncSetAttribute(k3_edge_mma, cudaFuncAttributeMaxDynamicSharedMemorySize, K3_SMEM);
        cudaFuncSetAttribute(k2_fused, cudaFuncAttributeMaxDynamicSharedMemorySize, K2B_SMEM);
        attr_set = true;
    }

    k1_fused<<<200, 256>>>(x, Wg0,bg0, Wg1,bg1, Wg2,bg2, We1, We2, h_out);
    k2_fused<<<1024, 256, K2B_SMEM>>>(h_out, We0, Wn0,bn0, Wn1,bn1, Wn2,bn2, U);
    k3_edge_mma<<<dim3(72, BATCH), 256, K3_SMEM>>>(be0, be1, be2, U);
}

// round 11
// speedup vs baseline: 1.7710x; 1.0927x over previous
#include <cuda_runtime.h>
#include <cuda_bf16.h>
#include <cuda_fp16.h>
#include <cstdint>

// Problem constants
#define BATCH 128
#define NN    128
#define D_IN  6
#define D_MP  64
#define TOTAL (BATCH*NN)    // 16384
#define U_STRIDE 512
#define U_PER_B  (512*512)

__device__ float g_A0[TOTAL*128];           // h @ We0[:64]
__device__ float g_B0[TOTAL*128];           // h @ We0[64:]
__device__ __half g_Bhi[128*136];           // We1^T fp16, padded [n][136]
__device__ __half g_W2hi[16*136];           // We2^T fp16, padded [c][136]

__device__ __forceinline__ float lrelu(float v){ return v >= 0.f ? v : 0.1f*v; }

__device__ __forceinline__ uint32_t smem_u32(const void* p){
    uint32_t a;
    asm("{ .reg .u64 t; cvta.to.shared.u64 t, %1; cvt.u32.u64 %0, t; }"
        : "=r"(a) : "l"(p));
    return a;
}

#define LDM4(r, addr) \
    asm volatile("ldmatrix.sync.aligned.m8n8.x4.shared.b16 {%0,%1,%2,%3}, [%4];" \
        : "=r"((r)[0]), "=r"((r)[1]), "=r"((r)[2]), "=r"((r)[3]) : "r"(addr))

#define MMA16816H(d, a, b0_, b1_) \
    asm volatile("mma.sync.aligned.m16n8k16.row.col.f32.f16.f16.f32 " \
        "{%0,%1,%2,%3}, {%4,%5,%6,%7}, {%8,%9}, {%0,%1,%2,%3};" \
        : "+f"((d)[0]), "+f"((d)[1]), "+f"((d)[2]), "+f"((d)[3]) \
        : "r"((a)[0]), "r"((a)[1]), "r"((a)[2]), "r"((a)[3]), "r"(b0_), "r"(b1_))

__device__ __forceinline__ uint32_t packh2(float s0, float s1){
    __half2 h2 = __floats2half2_rn(s0, s1);
    return *reinterpret_cast<uint32_t*>(&h2);
}

// ---------------------------------------------------------------------------
// K1 fused: blocks [0,128) = GCN (512 thr, 4/node); blocks [128,164) = prep.
// GCN uses S = (colsum a) @ W  (linearity) so only input activations are
// reduced; each thread computes its own S_c locally.
// ---------------------------------------------------------------------------
__global__ void __launch_bounds__(512)
k1_fused(const float* __restrict__ x,
         const float* __restrict__ Wg0, const float* __restrict__ bg0,
         const float* __restrict__ Wg1, const float* __restrict__ bg1,
         const float* __restrict__ Wg2, const float* __restrict__ bg2,
         const float* __restrict__ We1, const float* __restrict__ We2,
         float* __restrict__ h_out)
{
    const int tid = threadIdx.x;

    if (blockIdx.x >= 128){
        // ---- prep: We1^T -> fp16, We2^T -> fp16 ----
        int idx = (blockIdx.x - 128)*512 + tid;            // 0..18431
        if (idx < 128*128){
            int k = idx >> 7, n = idx & 127;
            g_Bhi[n*136 + k] = __float2half_rn(We1[k*128 + n]);
        } else if (idx < 128*128 + 128*16){
            int r = idx - 128*128;                         // 0..2047
            int k = r >> 4, c = r & 15;
            g_W2hi[c*136 + k] = __float2half_rn(We2[k*16 + c]);
        }
        return;
    }

    __shared__ float buf[128*33];   // activations, padded stride 33
    __shared__ float Sp[16*33];     // reduction partials
    __shared__ float SV[32];        // column sums of input activations
    const int n  = tid >> 2;
    const int qf = tid & 3;
    const int base = blockIdx.x * NN;
    const float inv = 1.0f/127.0f;

    // ---- load x; stage into buf for reduction ----
    float xr[D_IN];
#pragma unroll
    for (int k=0;k<D_IN;k++) xr[k] = x[(base+n)*D_IN + k];
    if (qf == 0){
#pragma unroll
        for (int k=0;k<D_IN;k++) buf[n*33 + k] = xr[k];
    }
    __syncthreads();

    // reduce x (6 cols)
    if (tid < 96){
        int col = tid % 6, grp = tid / 6;     // 16 grps x 8 rows
        float s = 0.f;
#pragma unroll
        for (int m=0;m<8;m++) s += buf[(grp*8+m)*33 + col];
        Sp[grp*7 + col] = s;
    }
    __syncthreads();
    if (tid < 6){
        float s = 0.f;
#pragma unroll
        for (int g2=0;g2<16;g2++) s += Sp[g2*7 + tid];
        SV[tid] = s;
    }
    __syncthreads();

    // ---- layer 0: D_IN -> 32, my cols qf*8..+8 ----
    float a0[8];
#pragma unroll
    for (int cc=0;cc<8;cc++){
        int c = qf*8 + cc;
        float y = 0.f, S = 0.f;
#pragma unroll
        for (int k=0;k<D_IN;k++){
            float w = __ldg(&Wg0[k*32+c]);
            y += xr[k]*w;  S += SV[k]*w;
        }
        a0[cc] = lrelu((S - y)*inv + __ldg(&bg0[c]));
    }
    __syncthreads();      // x reads in reduction done (already), buf reuse safe
#pragma unroll
    for (int cc=0;cc<8;cc++) buf[n*33 + qf*8 + cc] = a0[cc];
    __syncthreads();

    // ---- layer 1: 32 -> 32 ----
    {
        int col = tid & 31, grp = tid >> 5;   // 16 grps x 8 rows
        float s = 0.f;
#pragma unroll
        for (int m=0;m<8;m++) s += buf[(grp*8+m)*33 + col];
        Sp[grp*33 + col] = s;
    }
    __syncthreads();
    if (tid < 32){
        float s = 0.f;
#pragma unroll
        for (int g2=0;g2<16;g2++) s += Sp[g2*33 + tid];
        SV[tid] = s;
    }
    __syncthreads();

    float a1[8];
#pragma unroll
    for (int cc=0;cc<8;cc++){
        int c = qf*8 + cc;
        float y = 0.f, S = 0.f;
#pragma unroll
        for (int k=0;k<32;k++){
            float w = __ldg(&Wg1[k*32+c]);
            y += buf[n*33+k]*w;  S += SV[k]*w;
        }
        a1[cc] = lrelu((S - y)*inv + __ldg(&bg1[c]));
    }
    __syncthreads();      // all buf reads complete before overwrite
#pragma unroll
    for (int cc=0;cc<8;cc++) buf[n*33 + qf*8 + cc] = a1[cc];
    __syncthreads();

    // ---- layer 2: 32 -> 64, my cols qf*16..+16 ----
    {
        int col = tid & 31, grp = tid >> 5;
        float s = 0.f;
#pragma unroll
        for (int m=0;m<8;m++) s += buf[(grp*8+m)*33 + col];
        Sp[grp*33 + col] = s;
    }
    __syncthreads();
    if (tid < 32){
        float s = 0.f;
#pragma unroll
        for (int g2=0;g2<16;g2++) s += Sp[g2*33 + tid];
        SV[tid] = s;
    }
    __syncthreads();

#pragma unroll
    for (int cc=0;cc<16;cc++){
        int c = qf*16 + cc;
        float y = 0.f, S = 0.f;
#pragma unroll
        for (int k=0;k<32;k++){
            float w = __ldg(&Wg2[k*64+c]);
            y += buf[n*33+k]*w;  S += SV[k]*w;
        }
        h_out[(base+n)*64 + c] = (S - y)*inv + __ldg(&bg2[c]);
    }
}

// ---------------------------------------------------------------------------
// K2 fused: blocks [0,512) = A0/B0 GEMM; blocks [512,1024) = node MLP + diag.
// ---------------------------------------------------------------------------
#define K2B_W0   0
#define K2B_W1   4096
#define K2B_W2   8192
#define K2B_BA   8960
#define K2B_BB   11136
#define K2B_VB   13312
#define K2B_B0   13728
#define K2B_B1   13792
#define K2B_B2   13856
#define K2B_SMEM ((13856+16)*4)

__global__ void __launch_bounds__(256)
k2_fused(const float* __restrict__ h, const float* __restrict__ We0,
         const float* __restrict__ Wn0, const float* __restrict__ bn0,
         const float* __restrict__ Wn1, const float* __restrict__ bn1,
         const float* __restrict__ Wn2, const float* __restrict__ bn2,
         float* __restrict__ U)
{
    extern __shared__ float sm[];
    const int tid = threadIdx.x;

    if (blockIdx.x < 512){
        // ---- k2_ab ----
        float* hs = sm;
        const int n0 = blockIdx.x * 32;

        for (int l = tid; l < 32*64; l += 256) hs[l] = h[n0*64 + l];
        __syncthreads();

        const int col = tid & 127;
        const int kb  = (tid >> 7) * 64;

        float acc[32];
#pragma unroll
        for (int i=0;i<32;i++) acc[i]=0.f;

        for (int k=0;k<64;k++){
            float w = __ldg(&We0[(kb+k)*128 + col]);
#pragma unroll
            for (int nn=0;nn<32;nn++) acc[nn] += hs[nn*64+k]*w;
        }

        float* dst = (tid < 128) ? g_A0 : g_B0;
#pragma unroll
        for (int nn=0;nn<32;nn++) dst[(size_t)(n0+nn)*128 + col] = acc[nn];
        return;
    }

    // ---- k2b node MLP ----
    const int blk = blockIdx.x - 512;
    const int ln  = tid >> 3;
    const int q   = tid & 7;
    const int b   = blk >> 2;
    const int n0  = (blk & 3) * 32;

    float4* w0s = reinterpret_cast<float4*>(sm + K2B_W0);
    float4* w1s = reinterpret_cast<float4*>(sm + K2B_W1);

    for (int l = tid; l < 1024; l += 256){
        w0s[l] = reinterpret_cast<const float4*>(Wn0)[l];
        w1s[l] = reinterpret_cast<const float4*>(Wn1)[l];
    }
    for (int l = tid; l < 768; l += 256){
        int k = l / 12, c = l % 12;
        sm[K2B_W2 + l] = (c < 10) ? Wn2[k*10 + c] : 0.f;
    }
    if (tid < 64){ sm[K2B_B0 + tid] = bn0[tid]; sm[K2B_B1 + tid] = bn1[tid]; }
    else if (tid < 76) sm[K2B_B2 + tid - 64] = (tid - 64 < 10) ? bn2[tid-64] : 0.f;
    for (int l = tid; l < 2048; l += 256){
        int r_ = l >> 6, c = l & 63;
        sm[K2B_BA + r_*68 + c] = h[(size_t)(b*128 + n0 + r_)*64 + c];
    }
    __syncthreads();

    {
        float acc[8];
#pragma unroll
        for (int m=0;m<8;m++) acc[m] = sm[K2B_B0 + q*8 + m];
        for (int k=0;k<64;k++){
            float hk = sm[K2B_BA + ln*68 + k];
            float4 wa = w0s[k*16 + q*2];
            float4 wb = w0s[k*16 + q*2 + 1];
            acc[0] += hk*wa.x; acc[1] += hk*wa.y; acc[2] += hk*wa.z; acc[3] += hk*wa.w;
            acc[4] += hk*wb.x; acc[5] += hk*wb.y; acc[6] += hk*wb.z; acc[7] += hk*wb.w;
        }
#pragma unroll
        for (int m=0;m<8;m++) sm[K2B_BB + ln*68 + q*8 + m] = lrelu(acc[m]);
    }
    __syncthreads();

    {
        float acc[8];
#pragma unroll
        for (int m=0;m<8;m++) acc[m] = sm[K2B_B1 + q*8 + m];
        for (int k=0;k<64;k++){
            float hk = sm[K2B_BB + ln*68 + k];
            float4 wa = w1s[k*16 + q*2];
            float4 wb = w1s[k*16 + q*2 + 1];
            acc[0] += hk*wa.x; acc[1] += hk*wa.y; acc[2] += hk*wa.z; acc[3] += hk*wa.w;
            acc[4] += hk*wb.x; acc[5] += hk*wb.y; acc[6] += hk*wb.z; acc[7] += hk*wb.w;
        }
        __syncthreads();
#pragma unroll
        for (int m=0;m<8;m++) sm[K2B_BA + ln*68 + q*8 + m] = lrelu(acc[m]);
    }
    __syncthreads();

    if (q < 6){
        const int c0 = 2*q, c1 = 2*q + 1;
        float a0 = sm[K2B_B2 + c0];
        float a1 = sm[K2B_B2 + c1];
        for (int k=0;k<64;k++){
            float hk = sm[K2B_BA + ln*68 + k];
            a0 += hk * sm[K2B_W2 + k*12 + c0];
            a1 += hk * sm[K2B_W2 + k*12 + c1];
        }
        sm[K2B_VB + ln*13 + c0] = a0;
        sm[K2B_VB + ln*13 + c1] = a1;
    }
    __syncthreads();

    if (q < 4){
        const int SMAT[16] = {0,1,2,3, 1,4,5,6, 2,5,7,8, 3,6,8,9};
        const int node = n0 + ln;
        float4 rv;
        rv.x = sm[K2B_VB + ln*13 + SMAT[q*4+0]];
        rv.y = sm[K2B_VB + ln*13 + SMAT[q*4+1]];
        rv.z = sm[K2B_VB + ln*13 + SMAT[q*4+2]];
        rv.w = sm[K2B_VB + ln*13 + SMAT[q*4+3]];
        float* Ub = U + (size_t)b*U_PER_B;
        *reinterpret_cast<float4*>(Ub + (size_t)(4*node+q)*U_STRIDE + 4*node) = rv;
    }
}

// ---------------------------------------------------------------------------
// K3: edge MLP. GEMM1: register-built fp16 A x single fp16 B (We1^T).
// GEMM2: single fp16 x single fp16 (We2^T). Direct scatter.
// ---------------------------------------------------------------------------
#define OFF_BHI  0                    // 34816
#define OFF_W2HI 34816                // 4352
#define OFF_BE1  39168                // 512
#define OFF_BE2  39680                // 64
#define OFF_STG  39744                // A0s[8][132] + B0s[16][132] = 12672
#define OFF_A0S  OFF_STG
#define OFF_B0S  (OFF_STG + 8*132*4)
#define OFF_ES   OFF_STG              // alias: [128][20] f = 10240
#define K3_SMEM  (OFF_STG + 12672)    // 52416 B

__global__ void __launch_bounds__(256, 2)
k3_edge_mma(const float* __restrict__ be0,
            const float* __restrict__ be1,
            const float* __restrict__ be2,
            float* __restrict__ U)
{
    extern __shared__ char smem[];
    float* smemf = reinterpret_cast<float*>(smem);
    const uint32_t sb = smem_u32(smem);
    const int tid = threadIdx.x;
    const int wid = tid >> 5;
    const int lane = tid & 31;
    const int g = lane >> 2;
    const int r = lane & 3;

    // triangular tile decode: jt s.t. jt(jt+1) <= t < (jt+1)(jt+2)
    const int t = blockIdx.x;
    int jt = 0;
#pragma unroll
    for (int q=1;q<8;q++) if (t >= q*(q+1)) jt = q;
    const int it = t - jt*(jt+1);
    const int b  = blockIdx.y;
    const int i0 = it*8, j0 = jt*16;

    // ---- stage weights + A0/B0 rows ----
    {
        const uint4* sh  = reinterpret_cast<const uint4*>(g_Bhi);
        uint4* dh = reinterpret_cast<uint4*>(smem + OFF_BHI);
        for (int l = tid; l < 2176; l += 256) dh[l] = sh[l];
        const uint4* s2h = reinterpret_cast<const uint4*>(g_W2hi);
        uint4* d2h = reinterpret_cast<uint4*>(smem + OFF_W2HI);
        for (int l = tid; l < 272; l += 256) d2h[l] = s2h[l];
        if (tid < 128) smemf[OFF_BE1/4 + tid] = be1[tid];
        else if (tid < 144) smemf[OFF_BE2/4 + tid - 128] = be2[tid - 128];
        // A0s: 8 rows x 128 f (no be0); B0s: 16 rows x 128 f (+be0)
        for (int l = tid; l < 256; l += 256){
            int rr = l >> 5, c4 = (l & 31)*4;
            float4 v = *reinterpret_cast<const float4*>(g_A0 + ((size_t)(b*NN + i0 + rr))*128 + c4);
            *reinterpret_cast<float4*>(smemf + OFF_A0S/4 + rr*132 + c4) = v;
        }
        for (int l = tid; l < 512; l += 256){
            int rr = l >> 5, c4 = (l & 31)*4;
            float4 v  = *reinterpret_cast<const float4*>(g_B0 + ((size_t)(b*NN + j0 + rr))*128 + c4);
            float4 e0 = *reinterpret_cast<const float4*>(be0 + c4);
            v.x += e0.x; v.y += e0.y; v.z += e0.z; v.w += e0.w;
            *reinterpret_cast<float4*>(smemf + OFF_B0S/4 + rr*132 + c4) = v;
        }
    }
    __syncthreads();

    const int mg = wid >> 1;       // 0..3 -> rows mg*32..+31
    const int ng = wid & 1;        // 0..1 -> cols ng*64..+63
    float acc[2][8][4];
#pragma unroll
    for (int a1=0;a1<2;a1++)
#pragma unroll
        for (int a2=0;a2<8;a2++)
#pragma unroll
            for (int a3=0;a3<4;a3++) acc[a1][a2][a3] = 0.f;

    // ---- GEMM1: register-built fp16 A (t0) x single fp16 B (We1^T) ----
    {
        const uint32_t bOff = (uint32_t)((ng*64 + ((lane >> 4) << 3) + (lane & 7))*272
                                        + ((lane >> 3) & 1)*16);
        const uint32_t bHi = sb + OFF_BHI + bOff;
        const float* A0p = smemf + OFF_A0S/4;
        const float* B0p = smemf + OFF_B0S/4;

#pragma unroll
        for (int ks = 0; ks < 8; ks++){
            float2 b00 = *reinterpret_cast<const float2*>(B0p + g*132      + ks*16 + 2*r);
            float2 b01 = *reinterpret_cast<const float2*>(B0p + g*132      + ks*16 + 8 + 2*r);
            float2 b10 = *reinterpret_cast<const float2*>(B0p + (g+8)*132  + ks*16 + 2*r);
            float2 b11 = *reinterpret_cast<const float2*>(B0p + (g+8)*132  + ks*16 + 8 + 2*r);

            uint32_t ah[2][4];
#pragma unroll
            for (int mt=0; mt<2; mt++){
                const float* Ar = A0p + (mg*2+mt)*132 + ks*16;
                float2 ak0 = *reinterpret_cast<const float2*>(Ar + 2*r);
                float2 ak1 = *reinterpret_cast<const float2*>(Ar + 8 + 2*r);
                ah[mt][0] = packh2(lrelu(ak0.x+b00.x), lrelu(ak0.y+b00.y));
                ah[mt][1] = packh2(lrelu(ak0.x+b10.x), lrelu(ak0.y+b10.y));
                ah[mt][2] = packh2(lrelu(ak1.x+b01.x), lrelu(ak1.y+b01.y));
                ah[mt][3] = packh2(lrelu(ak1.x+b11.x), lrelu(ak1.y+b11.y));
            }
#pragma unroll
            for (int n2 = 0; n2 < 4; n2++){
                uint32_t bh[4];
                LDM4(bh, bHi + n2*4352 + ks*32);
                MMA16816H(acc[0][2*n2],   ah[0], bh[0], bh[1]);
                MMA16816H(acc[0][2*n2+1], ah[0], bh[2], bh[3]);
                MMA16816H(acc[1][2*n2],   ah[1], bh[0], bh[1]);
                MMA16816H(acc[1][2*n2+1], ah[1], bh[2], bh[3]);
            }
        }
    }

    // ---- GEMM2: chain acc -> t1 fp16 A-fragments x We2^T fp16 ----
    float e[2][2][4];
#pragma unroll
    for (int a1=0;a1<2;a1++)
#pragma unroll
        for (int a2=0;a2<2;a2++)
#pragma unroll
            for (int a3=0;a3<4;a3++) e[a1][a2][a3] = 0.f;

    {
        const uint32_t b2Off = (uint32_t)(((((lane >> 4) << 3) + (lane & 7))*272)
                                        + ((lane >> 3) & 1)*16);
        const uint32_t wHi = sb + OFF_W2HI + b2Off;

#pragma unroll
        for (int qk = 0; qk < 4; qk++){
            uint32_t bh[4];
            LDM4(bh, wHi + (ng*4+qk)*32);
#pragma unroll
            for (int mt = 0; mt < 2; mt++){
                const int ntA = 2*qk, ntB = 2*qk+1;
                const int cA = ng*64 + ntA*8 + 2*r;
                const int cB = ng*64 + ntB*8 + 2*r;
                float beA0 = smemf[OFF_BE1/4 + cA], beA1 = smemf[OFF_BE1/4 + cA + 1];
                float beB0 = smemf[OFF_BE1/4 + cB], beB1 = smemf[OFF_BE1/4 + cB + 1];
                uint32_t ah[4];
                ah[0] = packh2(lrelu(acc[mt][ntA][0]+beA0), lrelu(acc[mt][ntA][1]+beA1));
                ah[1] = packh2(lrelu(acc[mt][ntA][2]+beA0), lrelu(acc[mt][ntA][3]+beA1));
                ah[2] = packh2(lrelu(acc[mt][ntB][0]+beB0), lrelu(acc[mt][ntB][1]+beB1));
                ah[3] = packh2(lrelu(acc[mt][ntB][2]+beB0), lrelu(acc[mt][ntB][3]+beB1));
                MMA16816H(e[mt][0], ah, bh[0], bh[1]);
                MMA16816H(e[mt][1], ah, bh[2], bh[3]);
            }
        }
    }

    // ---- cross-warp (ng pair) reduction + direct scatter into U ----
    __syncthreads();   // A0s/B0s reads done; safe to overwrite with ES
    float* es = smemf + OFF_ES/4;   // [128][20]

    if (ng == 1){
#pragma unroll
        for (int mt=0; mt<2; mt++)
#pragma unroll
        for (int t_=0; t_<2; t_++)
#pragma unroll
        for (int rh=0; rh<2; rh++){
            int row = mg*32 + mt*16 + g + rh*8;
            int c = t_*8 + 2*r;
            *reinterpret_cast<float2*>(&es[row*20 + c]) =
                make_float2(e[mt][t_][rh*2+0], e[mt][t_][rh*2+1]);
        }
    }
    __syncthreads();
    if (ng == 0){
        float* Ub = U + (size_t)b*U_PER_B;
#pragma unroll
        for (int mt=0; mt<2; mt++)
#pragma unroll
        for (int t_=0; t_<2; t_++)
#pragma unroll
        for (int rh=0; rh<2; rh++){
            int row = mg*32 + mt*16 + g + rh*8;
            int c = t_*8 + 2*r;
            float2 part = *reinterpret_cast<const float2*>(&es[row*20 + c]);
            float vx = e[mt][t_][rh*2+0] + part.x + smemf[OFF_BE2/4 + c];
            float vy = e[mt][t_][rh*2+1] + part.y + smemf[OFF_BE2/4 + c + 1];
            int i = i0 + (row >> 4);
            int j = j0 + (row & 15);
            if (i < j){
                int qq = c >> 2, m = c & 3;
                float2 v2 = make_float2(vx, vy);
                *reinterpret_cast<float2*>(Ub + (size_t)(4*i+qq)*U_STRIDE + 4*j + m) = v2;
                *reinterpret_cast<float2*>(Ub + (size_t)(4*j+qq)*U_STRIDE + 4*i + m) = v2;
            }
        }
    }
}

// ---------------------------------------------------------------------------
extern "C" void kernel_launch(void* const* d_in, const int* in_sizes, int n_in,
                              void* d_out, int out_size)
{
    const float* x   = (const float*)d_in[0];
    const float* Wg0 = (const float*)d_in[4];
    const float* bg0 = (const float*)d_in[5];
    const float* Wg1 = (const float*)d_in[6];
    const float* bg1 = (const float*)d_in[7];
    const float* Wg2 = (const float*)d_in[8];
    const float* bg2 = (const float*)d_in[9];
    const float* Wn0 = (const float*)d_in[10];
    const float* bn0 = (const float*)d_in[11];
    const float* Wn1 = (const float*)d_in[12];
    const float* bn1 = (const float*)d_in[13];
    const float* Wn2 = (const float*)d_in[14];
    const float* bn2 = (const float*)d_in[15];
    const float* We0 = (const float*)d_in[16];
    const float* be0 = (const float*)d_in[17];
    const float* We1 = (const float*)d_in[18];
    const float* be1 = (const float*)d_in[19];
    const float* We2 = (const float*)d_in[20];
    const float* be2 = (const float*)d_in[21];

    float* h_out = (float*)d_out;                 // (16384, 64)
    float* U     = h_out + (size_t)TOTAL*D_MP;    // (128, 512, 512)

    static bool attr_set = false;
    if (!attr_set){
        cudaFuncSetAttribute(k3_edge_mma, cudaFuncAttributeMaxDynamicSharedMemorySize, K3_SMEM);
        cudaFuncSetAttribute(k2_fused, cudaFuncAttributeMaxDynamicSharedMemorySize, K2B_SMEM);
        attr_set = true;
    }

    k1_fused<<<164, 512>>>(x, Wg0,bg0, Wg1,bg1, Wg2,bg2, We1, We2, h_out);
    k2_fused<<<1024, 256, K2B_SMEM>>>(h_out, We0, Wn0,bn0, Wn1,bn1, Wn2,bn2, U);
    k3_edge_mma<<<dim3(72, BATCH), 256, K3_SMEM>>>(be0, be1, be2, U);
}

// round 12
// speedup vs baseline: 2.2388x; 1.2642x over previous
#include <cuda_runtime.h>
#include <cuda_bf16.h>
#include <cuda_fp16.h>
#include <cstdint>

// Problem constants
#define BATCH 128
#define NN    128
#define D_IN  6
#define D_MP  64
#define TOTAL (BATCH*NN)    // 16384
#define U_STRIDE 512
#define U_PER_B  (512*512)

__device__ __half g_A0h[TOTAL*128];         // fp16(h @ We0[:64])
__device__ __half g_B0h[TOTAL*128];         // fp16(h @ We0[64:] + be0)
__device__ __half g_Bhi[128*136];           // We1^T fp16, padded [n][136]
__device__ __half g_W2hi[16*136];           // We2^T fp16, padded [c][136]

__device__ __forceinline__ float lrelu(float v){ return v >= 0.f ? v : 0.1f*v; }

__device__ __forceinline__ uint32_t smem_u32(const void* p){
    uint32_t a;
    asm("{ .reg .u64 t; cvta.to.shared.u64 t, %1; cvt.u32.u64 %0, t; }"
        : "=r"(a) : "l"(p));
    return a;
}

#define LDM4(r, addr) \
    asm volatile("ldmatrix.sync.aligned.m8n8.x4.shared.b16 {%0,%1,%2,%3}, [%4];" \
        : "=r"((r)[0]), "=r"((r)[1]), "=r"((r)[2]), "=r"((r)[3]) : "r"(addr))

#define MMA16816H(d, a, b0_, b1_) \
    asm volatile("mma.sync.aligned.m16n8k16.row.col.f32.f16.f16.f32 " \
        "{%0,%1,%2,%3}, {%4,%5,%6,%7}, {%8,%9}, {%0,%1,%2,%3};" \
        : "+f"((d)[0]), "+f"((d)[1]), "+f"((d)[2]), "+f"((d)[3]) \
        : "r"((a)[0]), "r"((a)[1]), "r"((a)[2]), "r"((a)[3]), "r"(b0_), "r"(b1_))

__device__ __forceinline__ uint32_t packh2(float s0, float s1){
    __half2 h2 = __floats2half2_rn(s0, s1);
    return *reinterpret_cast<uint32_t*>(&h2);
}
// lrelu on packed half2: max(v, 0.1*v) — exact for both signs
__device__ __forceinline__ uint32_t lrelu2(__half2 v, __half2 slope){
    __half2 o = __hmax2(v, __hmul2(v, slope));
    return *reinterpret_cast<uint32_t*>(&o);
}

// ---------------------------------------------------------------------------
// K1 fused: blocks [0,128) = GCN (512 thr, 4/node); blocks [128,164) = prep.
// ---------------------------------------------------------------------------
__global__ void __launch_bounds__(512)
k1_fused(const float* __restrict__ x,
         const float* __restrict__ Wg0, const float* __restrict__ bg0,
         const float* __restrict__ Wg1, const float* __restrict__ bg1,
         const float* __restrict__ Wg2, const float* __restrict__ bg2,
         const float* __restrict__ We1, const float* __restrict__ We2,
         float* __restrict__ h_out)
{
    const int tid = threadIdx.x;

    if (blockIdx.x >= 128){
        // ---- prep: We1^T -> fp16, We2^T -> fp16 ----
        int idx = (blockIdx.x - 128)*512 + tid;            // 0..18431
        if (idx < 128*128){
            int k = idx >> 7, n = idx & 127;
            g_Bhi[n*136 + k] = __float2half_rn(We1[k*128 + n]);
        } else if (idx < 128*128 + 128*16){
            int r = idx - 128*128;                         // 0..2047
            int k = r >> 4, c = r & 15;
            g_W2hi[c*136 + k] = __float2half_rn(We2[k*16 + c]);
        }
        return;
    }

    __shared__ float buf[128*33];   // activations, padded stride 33
    __shared__ float Sp[16*33];     // reduction partials
    __shared__ float SV[32];        // column sums of input activations
    const int n  = tid >> 2;
    const int qf = tid & 3;
    const int base = blockIdx.x * NN;
    const float inv = 1.0f/127.0f;

    float xr[D_IN];
#pragma unroll
    for (int k=0;k<D_IN;k++) xr[k] = x[(base+n)*D_IN + k];
    if (qf == 0){
#pragma unroll
        for (int k=0;k<D_IN;k++) buf[n*33 + k] = xr[k];
    }
    __syncthreads();

    if (tid < 96){
        int col = tid % 6, grp = tid / 6;
        float s = 0.f;
#pragma unroll
        for (int m=0;m<8;m++) s += buf[(grp*8+m)*33 + col];
        Sp[grp*7 + col] = s;
    }
    __syncthreads();
    if (tid < 6){
        float s = 0.f;
#pragma unroll
        for (int g2=0;g2<16;g2++) s += Sp[g2*7 + tid];
        SV[tid] = s;
    }
    __syncthreads();

    float a0[8];
#pragma unroll
    for (int cc=0;cc<8;cc++){
        int c = qf*8 + cc;
        float y = 0.f, S = 0.f;
#pragma unroll
        for (int k=0;k<D_IN;k++){
            float w = __ldg(&Wg0[k*32+c]);
            y += xr[k]*w;  S += SV[k]*w;
        }
        a0[cc] = lrelu((S - y)*inv + __ldg(&bg0[c]));
    }
    __syncthreads();
#pragma unroll
    for (int cc=0;cc<8;cc++) buf[n*33 + qf*8 + cc] = a0[cc];
    __syncthreads();

    {
        int col = tid & 31, grp = tid >> 5;
        float s = 0.f;
#pragma unroll
        for (int m=0;m<8;m++) s += buf[(grp*8+m)*33 + col];
        Sp[grp*33 + col] = s;
    }
    __syncthreads();
    if (tid < 32){
        float s = 0.f;
#pragma unroll
        for (int g2=0;g2<16;g2++) s += Sp[g2*33 + tid];
        SV[tid] = s;
    }
    __syncthreads();

    float a1[8];
#pragma unroll
    for (int cc=0;cc<8;cc++){
        int c = qf*8 + cc;
        float y = 0.f, S = 0.f;
#pragma unroll
        for (int k=0;k<32;k++){
            float w = __ldg(&Wg1[k*32+c]);
            y += buf[n*33+k]*w;  S += SV[k]*w;
        }
        a1[cc] = lrelu((S - y)*inv + __ldg(&bg1[c]));
    }
    __syncthreads();
#pragma unroll
    for (int cc=0;cc<8;cc++) buf[n*33 + qf*8 + cc] = a1[cc];
    __syncthreads();

    {
        int col = tid & 31, grp = tid >> 5;
        float s = 0.f;
#pragma unroll
        for (int m=0;m<8;m++) s += buf[(grp*8+m)*33 + col];
        Sp[grp*33 + col] = s;
    }
    __syncthreads();
    if (tid < 32){
        float s = 0.f;
#pragma unroll
        for (int g2=0;g2<16;g2++) s += Sp[g2*33 + tid];
        SV[tid] = s;
    }
    __syncthreads();

#pragma unroll
    for (int cc=0;cc<16;cc++){
        int c = qf*16 + cc;
        float y = 0.f, S = 0.f;
#pragma unroll
        for (int k=0;k<32;k++){
            float w = __ldg(&Wg2[k*64+c]);
            y += buf[n*33+k]*w;  S += SV[k]*w;
        }
        h_out[(base+n)*64 + c] = (S - y)*inv + __ldg(&bg2[c]);
    }
}

// ---------------------------------------------------------------------------
// K2 fused: blocks [0,512) = A0/B0 GEMM (fp16 out, be0 folded into B0);
// blocks [512,1024) = node MLP + diag.
// ---------------------------------------------------------------------------
#define K2B_W0   0
#define K2B_W1   4096
#define K2B_W2   8192
#define K2B_BA   8960
#define K2B_BB   11136
#define K2B_VB   13312
#define K2B_B0   13728
#define K2B_B1   13792
#define K2B_B2   13856
#define K2B_SMEM ((13856+16)*4)

__global__ void __launch_bounds__(256)
k2_fused(const float* __restrict__ h, const float* __restrict__ We0,
         const float* __restrict__ be0,
         const float* __restrict__ Wn0, const float* __restrict__ bn0,
         const float* __restrict__ Wn1, const float* __restrict__ bn1,
         const float* __restrict__ Wn2, const float* __restrict__ bn2,
         float* __restrict__ U)
{
    extern __shared__ float sm[];
    const int tid = threadIdx.x;

    if (blockIdx.x < 512){
        // ---- k2_ab ----
        float* hs = sm;
        const int n0 = blockIdx.x * 32;

        for (int l = tid; l < 32*64; l += 256) hs[l] = h[n0*64 + l];
        __syncthreads();

        const int col = tid & 127;
        const int kb  = (tid >> 7) * 64;
        const float bias = (tid >= 128) ? __ldg(&be0[col]) : 0.f;

        float acc[32];
#pragma unroll
        for (int i=0;i<32;i++) acc[i]=0.f;

        for (int k=0;k<64;k++){
            float w = __ldg(&We0[(kb+k)*128 + col]);
#pragma unroll
            for (int nn=0;nn<32;nn++) acc[nn] += hs[nn*64+k]*w;
        }

        __half* dst = (tid < 128) ? g_A0h : g_B0h;
#pragma unroll
        for (int nn=0;nn<32;nn++)
            dst[(size_t)(n0+nn)*128 + col] = __float2half_rn(acc[nn] + bias);
        return;
    }

    // ---- k2b node MLP ----
    const int blk = blockIdx.x - 512;
    const int ln  = tid >> 3;
    const int q   = tid & 7;
    const int b   = blk >> 2;
    const int n0  = (blk & 3) * 32;

    float4* w0s = reinterpret_cast<float4*>(sm + K2B_W0);
    float4* w1s = reinterpret_cast<float4*>(sm + K2B_W1);

    for (int l = tid; l < 1024; l += 256){
        w0s[l] = reinterpret_cast<const float4*>(Wn0)[l];
        w1s[l] = reinterpret_cast<const float4*>(Wn1)[l];
    }
    for (int l = tid; l < 768; l += 256){
        int k = l / 12, c = l % 12;
        sm[K2B_W2 + l] = (c < 10) ? Wn2[k*10 + c] : 0.f;
    }
    if (tid < 64){ sm[K2B_B0 + tid] = bn0[tid]; sm[K2B_B1 + tid] = bn1[tid]; }
    else if (tid < 76) sm[K2B_B2 + tid - 64] = (tid - 64 < 10) ? bn2[tid-64] : 0.f;
    for (int l = tid; l < 2048; l += 256){
        int r_ = l >> 6, c = l & 63;
        sm[K2B_BA + r_*68 + c] = h[(size_t)(b*128 + n0 + r_)*64 + c];
    }
    __syncthreads();

    {
        float acc[8];
#pragma unroll
        for (int m=0;m<8;m++) acc[m] = sm[K2B_B0 + q*8 + m];
        for (int k=0;k<64;k++){
            float hk = sm[K2B_BA + ln*68 + k];
            float4 wa = w0s[k*16 + q*2];
            float4 wb = w0s[k*16 + q*2 + 1];
            acc[0] += hk*wa.x; acc[1] += hk*wa.y; acc[2] += hk*wa.z; acc[3] += hk*wa.w;
            acc[4] += hk*wb.x; acc[5] += hk*wb.y; acc[6] += hk*wb.z; acc[7] += hk*wb.w;
        }
#pragma unroll
        for (int m=0;m<8;m++) sm[K2B_BB + ln*68 + q*8 + m] = lrelu(acc[m]);
    }
    __syncthreads();

    {
        float acc[8];
#pragma unroll
        for (int m=0;m<8;m++) acc[m] = sm[K2B_B1 + q*8 + m];
        for (int k=0;k<64;k++){
            float hk = sm[K2B_BB + ln*68 + k];
            float4 wa = w1s[k*16 + q*2];
            float4 wb = w1s[k*16 + q*2 + 1];
            acc[0] += hk*wa.x; acc[1] += hk*wa.y; acc[2] += hk*wa.z; acc[3] += hk*wa.w;
            acc[4] += hk*wb.x; acc[5] += hk*wb.y; acc[6] += hk*wb.z; acc[7] += hk*wb.w;
        }
        __syncthreads();
#pragma unroll
        for (int m=0;m<8;m++) sm[K2B_BA + ln*68 + q*8 + m] = lrelu(acc[m]);
    }
    __syncthreads();

    if (q < 6){
        const int c0 = 2*q, c1 = 2*q + 1;
        float a0 = sm[K2B_B2 + c0];
        float a1 = sm[K2B_B2 + c1];
        for (int k=0;k<64;k++){
            float hk = sm[K2B_BA + ln*68 + k];
            a0 += hk * sm[K2B_W2 + k*12 + c0];
            a1 += hk * sm[K2B_W2 + k*12 + c1];
        }
        sm[K2B_VB + ln*13 + c0] = a0;
        sm[K2B_VB + ln*13 + c1] = a1;
    }
    __syncthreads();

    if (q < 4){
        const int SMAT[16] = {0,1,2,3, 1,4,5,6, 2,5,7,8, 3,6,8,9};
        const int node = n0 + ln;
        float4 rv;
        rv.x = sm[K2B_VB + ln*13 + SMAT[q*4+0]];
        rv.y = sm[K2B_VB + ln*13 + SMAT[q*4+1]];
        rv.z = sm[K2B_VB + ln*13 + SMAT[q*4+2]];
        rv.w = sm[K2B_VB + ln*13 + SMAT[q*4+3]];
        float* Ub = U + (size_t)b*U_PER_B;
        *reinterpret_cast<float4*>(Ub + (size_t)(4*node+q)*U_STRIDE + 4*node) = rv;
    }
}

// ---------------------------------------------------------------------------
// K3: edge MLP. GEMM1: half2-built fp16 A x single fp16 B (We1^T).
// GEMM2: single fp16 x single fp16 (We2^T). Direct scatter.
// ---------------------------------------------------------------------------
#define OFF_BHI  0                    // 34816 (aliased by ES after GEMMs)
#define OFF_W2HI 34816                // 4352
#define OFF_BE1  39168                // 512
#define OFF_BE2  39680                // 64
#define OFF_A0S  39744                // 8 x 272 B = 2176 (fp16, stride 136 h)
#define OFF_B0S  41920                // 16 x 272 B = 4352
#define OFF_ES   0                    // alias over BHI (dead after GEMMs)
#define K3_SMEM  46272

__global__ void __launch_bounds__(256, 2)
k3_edge_mma(const float* __restrict__ be1,
            const float* __restrict__ be2,
            float* __restrict__ U)
{
    extern __shared__ char smem[];
    float* smemf = reinterpret_cast<float*>(smem);
    const uint32_t sb = smem_u32(smem);
    const int tid = threadIdx.x;
    const int wid = tid >> 5;
    const int lane = tid & 31;
    const int g = lane >> 2;
    const int r = lane & 3;

    // triangular tile decode: jt s.t. jt(jt+1) <= t < (jt+1)(jt+2)
    const int t = blockIdx.x;
    int jt = 0;
#pragma unroll
    for (int q=1;q<8;q++) if (t >= q*(q+1)) jt = q;
    const int it = t - jt*(jt+1);
    const int b  = blockIdx.y;
    const int i0 = it*8, j0 = jt*16;

    // ---- stage weights + A0/B0 rows (fp16) ----
    {
        const uint4* sh  = reinterpret_cast<const uint4*>(g_Bhi);
        uint4* dh = reinterpret_cast<uint4*>(smem + OFF_BHI);
        for (int l = tid; l < 2176; l += 256) dh[l] = sh[l];
        const uint4* s2h = reinterpret_cast<const uint4*>(g_W2hi);
        uint4* d2h = reinterpret_cast<uint4*>(smem + OFF_W2HI);
        for (int l = tid; l < 272; l += 256) d2h[l] = s2h[l];
        if (tid < 128) smemf[OFF_BE1/4 + tid] = be1[tid];
        else if (tid < 144) smemf[OFF_BE2/4 + tid - 128] = be2[tid - 128];
        // A0s: 8 rows x 128 h = 128 uint4; B0s: 16 rows = 256 uint4
        if (tid < 128){
            int rr = tid >> 4, c16 = tid & 15;
            uint4 v = reinterpret_cast<const uint4*>(g_A0h + ((size_t)(b*NN + i0 + rr))*128)[c16];
            *reinterpret_cast<uint4*>(smem + OFF_A0S + rr*272 + c16*16) = v;
        }
        for (int l = tid; l < 256; l += 256){
            int rr = l >> 4, c16 = l & 15;
            uint4 v = reinterpret_cast<const uint4*>(g_B0h + ((size_t)(b*NN + j0 + rr))*128)[c16];
            *reinterpret_cast<uint4*>(smem + OFF_B0S + rr*272 + c16*16) = v;
        }
    }
    __syncthreads();

    const int mg = wid >> 1;       // 0..3 -> rows mg*32..+31
    const int ng = wid & 1;        // 0..1 -> cols ng*64..+63
    float acc[2][8][4];
#pragma unroll
    for (int a1=0;a1<2;a1++)
#pragma unroll
        for (int a2=0;a2<8;a2++)
#pragma unroll
            for (int a3=0;a3<4;a3++) acc[a1][a2][a3] = 0.f;

    // ---- GEMM1: half2-built fp16 A (t0) x single fp16 B (We1^T) ----
    {
        const uint32_t bOff = (uint32_t)((ng*64 + ((lane >> 4) << 3) + (lane & 7))*272
                                        + ((lane >> 3) & 1)*16);
        const uint32_t bHi = sb + OFF_BHI + bOff;
        const __half2* A0p = reinterpret_cast<const __half2*>(smem + OFF_A0S);  // stride 68 h2
        const __half2* B0p = reinterpret_cast<const __half2*>(smem + OFF_B0S);
        const __half2 slope = __floats2half2_rn(0.1f, 0.1f);

#pragma unroll
        for (int ks = 0; ks < 8; ks++){
            __half2 b0a = B0p[g*68      + ks*8 + r];
            __half2 b0b = B0p[g*68      + ks*8 + 4 + r];
            __half2 b1a = B0p[(g+8)*68  + ks*8 + r];
            __half2 b1b = B0p[(g+8)*68  + ks*8 + 4 + r];

            uint32_t ah[2][4];
#pragma unroll
            for (int mt=0; mt<2; mt++){
                __half2 aa = A0p[(mg*2+mt)*68 + ks*8 + r];
                __half2 ab = A0p[(mg*2+mt)*68 + ks*8 + 4 + r];
                ah[mt][0] = lrelu2(__hadd2(aa, b0a), slope);
                ah[mt][1] = lrelu2(__hadd2(aa, b1a), slope);
                ah[mt][2] = lrelu2(__hadd2(ab, b0b), slope);
                ah[mt][3] = lrelu2(__hadd2(ab, b1b), slope);
            }
#pragma unroll
            for (int n2 = 0; n2 < 4; n2++){
                uint32_t bh[4];
                LDM4(bh, bHi + n2*4352 + ks*32);
                MMA16816H(acc[0][2*n2],   ah[0], bh[0], bh[1]);
                MMA16816H(acc[0][2*n2+1], ah[0], bh[2], bh[3]);
                MMA16816H(acc[1][2*n2],   ah[1], bh[0], bh[1]);
                MMA16816H(acc[1][2*n2+1], ah[1], bh[2], bh[3]);
            }
        }
    }

    // ---- GEMM2: chain acc -> t1 fp16 A-fragments x We2^T fp16 ----
    float e[2][2][4];
#pragma unroll
    for (int a1=0;a1<2;a1++)
#pragma unroll
        for (int a2=0;a2<2;a2++)
#pragma unroll
            for (int a3=0;a3<4;a3++) e[a1][a2][a3] = 0.f;

    {
        const uint32_t b2Off = (uint32_t)(((((lane >> 4) << 3) + (lane & 7))*272)
                                        + ((lane >> 3) & 1)*16);
        const uint32_t wHi = sb + OFF_W2HI + b2Off;

#pragma unroll
        for (int qk = 0; qk < 4; qk++){
            uint32_t bh[4];
            LDM4(bh, wHi + (ng*4+qk)*32);
#pragma unroll
            for (int mt = 0; mt < 2; mt++){
                const int ntA = 2*qk, ntB = 2*qk+1;
                const int cA = ng*64 + ntA*8 + 2*r;
                const int cB = ng*64 + ntB*8 + 2*r;
                float beA0 = smemf[OFF_BE1/4 + cA], beA1 = smemf[OFF_BE1/4 + cA + 1];
                float beB0 = smemf[OFF_BE1/4 + cB], beB1 = smemf[OFF_BE1/4 + cB + 1];
                uint32_t ah[4];
                ah[0] = packh2(lrelu(acc[mt][ntA][0]+beA0), lrelu(acc[mt][ntA][1]+beA1));
                ah[1] = packh2(lrelu(acc[mt][ntA][2]+beA0), lrelu(acc[mt][ntA][3]+beA1));
                ah[2] = packh2(lrelu(acc[mt][ntB][0]+beB0), lrelu(acc[mt][ntB][1]+beB1));
                ah[3] = packh2(lrelu(acc[mt][ntB][2]+beB0), lrelu(acc[mt][ntB][3]+beB1));
                MMA16816H(e[mt][0], ah, bh[0], bh[1]);
                MMA16816H(e[mt][1], ah, bh[2], bh[3]);
            }
        }
    }

    // ---- cross-warp (ng pair) reduction + direct scatter into U ----
    __syncthreads();   // all GEMM SMEM reads done; ES aliases BHI region
    float* es = smemf + OFF_ES/4;   // [128][20]

    if (ng == 1){
#pragma unroll
        for (int mt=0; mt<2; mt++)
#pragma unroll
        for (int t_=0; t_<2; t_++)
#pragma unroll
        for (int rh=0; rh<2; rh++){
            int row = mg*32 + mt*16 + g + rh*8;
            int c = t_*8 + 2*r;
            *reinterpret_cast<float2*>(&es[row*20 + c]) =
                make_float2(e[mt][t_][rh*2+0], e[mt][t_][rh*2+1]);
        }
    }
    __syncthreads();
    if (ng == 0){
        float* Ub = U + (size_t)b*U_PER_B;
#pragma unroll
        for (int mt=0; mt<2; mt++)
#pragma unroll
        for (int t_=0; t_<2; t_++)
#pragma unroll
        for (int rh=0; rh<2; rh++){
            int row = mg*32 + mt*16 + g + rh*8;
            int c = t_*8 + 2*r;
            float2 part = *reinterpret_cast<const float2*>(&es[row*20 + c]);
            float vx = e[mt][t_][rh*2+0] + part.x + smemf[OFF_BE2/4 + c];
            float vy = e[mt][t_][rh*2+1] + part.y + smemf[OFF_BE2/4 + c + 1];
            int i = i0 + (row >> 4);
            int j = j0 + (row & 15);
            if (i < j){
                int qq = c >> 2, m = c & 3;
                float2 v2 = make_float2(vx, vy);
                *reinterpret_cast<float2*>(Ub + (size_t)(4*i+qq)*U_STRIDE + 4*j + m) = v2;
                *reinterpret_cast<float2*>(Ub + (size_t)(4*j+qq)*U_STRIDE + 4*i + m) = v2;
            }
        }
    }
}

// ---------------------------------------------------------------------------
extern "C" void kernel_launch(void* const* d_in, const int* in_sizes, int n_in,
                              void* d_out, int out_size)
{
    const float* x   = (const float*)d_in[0];
    const float* Wg0 = (const float*)d_in[4];
    const float* bg0 = (const float*)d_in[5];
    const float* Wg1 = (const float*)d_in[6];
    const float* bg1 = (const float*)d_in[7];
    const float* Wg2 = (const float*)d_in[8];
    const float* bg2 = (const float*)d_in[9];
    const float* Wn0 = (const float*)d_in[10];
    const float* bn0 = (const float*)d_in[11];
    const float* Wn1 = (const float*)d_in[12];
    const float* bn1 = (const float*)d_in[13];
    const float* Wn2 = (const float*)d_in[14];
    const float* bn2 = (const float*)d_in[15];
    const float* We0 = (const float*)d_in[16];
    const float* be0 = (const float*)d_in[17];
    const float* We1 = (const float*)d_in[18];
    const float* be1 = (const float*)d_in[19];
    const float* We2 = (const float*)d_in[20];
    const float* be2 = (const float*)d_in[21];

    float* h_out = (float*)d_out;                 // (16384, 64)
    float* U     = h_out + (size_t)TOTAL*D_MP;    // (128, 512, 512)

    static bool attr_set = false;
    if (!attr_set){
        cudaFuncSetAttribute(k3_edge_mma, cudaFuncAttributeMaxDynamicSharedMemorySize, K3_SMEM);
        cudaFuncSetAttribute(k2_fused, cudaFuncAttributeMaxDynamicSharedMemorySize, K2B_SMEM);
        attr_set = true;
    }

    k1_fused<<<164, 512>>>(x, Wg0,bg0, Wg1,bg1, Wg2,bg2, We1, We2, h_out);
    k2_fused<<<1024, 256, K2B_SMEM>>>(h_out, We0, be0, Wn0,bn0, Wn1,bn1, Wn2,bn2, U);
    k3_edge_mma<<<dim3(72, BATCH), 256, K3_SMEM>>>(be1, be2, U);
}

// round 13
// speedup vs baseline: 2.2986x; 1.0267x over previous
#include <cuda_runtime.h>
#include <cuda_bf16.h>
#include <cuda_fp16.h>
#include <cstdint>

// Problem constants
#define BATCH 128
#define NN    128
#define D_IN  6
#define D_MP  64
#define TOTAL (BATCH*NN)    // 16384
#define U_STRIDE 512
#define U_PER_B  (512*512)

__device__ __half g_A0h[TOTAL*128];         // fp16(h @ We0[:64])
__device__ __half g_B0h[TOTAL*128];         // fp16(h @ We0[64:] + be0)
__device__ __half g_Bhi[128*136];           // We1^T fp16, padded [n][136]
__device__ __half g_W2hi[16*136];           // We2^T fp16, padded [c][136]

__device__ __forceinline__ float lrelu(float v){ return v >= 0.f ? v : 0.1f*v; }

__device__ __forceinline__ uint32_t smem_u32(const void* p){
    uint32_t a;
    asm("{ .reg .u64 t; cvta.to.shared.u64 t, %1; cvt.u32.u64 %0, t; }"
        : "=r"(a) : "l"(p));
    return a;
}

#define LDM4(r, addr) \
    asm volatile("ldmatrix.sync.aligned.m8n8.x4.shared.b16 {%0,%1,%2,%3}, [%4];" \
        : "=r"((r)[0]), "=r"((r)[1]), "=r"((r)[2]), "=r"((r)[3]) : "r"(addr))

#define MMA16816H(d, a, b0_, b1_) \
    asm volatile("mma.sync.aligned.m16n8k16.row.col.f32.f16.f16.f32 " \
        "{%0,%1,%2,%3}, {%4,%5,%6,%7}, {%8,%9}, {%0,%1,%2,%3};" \
        : "+f"((d)[0]), "+f"((d)[1]), "+f"((d)[2]), "+f"((d)[3]) \
        : "r"((a)[0]), "r"((a)[1]), "r"((a)[2]), "r"((a)[3]), "r"(b0_), "r"(b1_))

__device__ __forceinline__ uint32_t packh2(float s0, float s1){
    __half2 h2 = __floats2half2_rn(s0, s1);
    return *reinterpret_cast<uint32_t*>(&h2);
}
// lrelu on packed half2: max(v, 0.1*v) — exact for both signs
__device__ __forceinline__ uint32_t lrelu2(__half2 v, __half2 slope){
    __half2 o = __hmax2(v, __hmul2(v, slope));
    return *reinterpret_cast<uint32_t*>(&o);
}

// ---------------------------------------------------------------------------
// K1 fused: blocks [0,128) = GCN (512 thr, 4/node); blocks [128,164) = prep.
// ---------------------------------------------------------------------------
__global__ void __launch_bounds__(512)
k1_fused(const float* __restrict__ x,
         const float* __restrict__ Wg0, const float* __restrict__ bg0,
         const float* __restrict__ Wg1, const float* __restrict__ bg1,
         const float* __restrict__ Wg2, const float* __restrict__ bg2,
         const float* __restrict__ We1, const float* __restrict__ We2,
         float* __restrict__ h_out)
{
    const int tid = threadIdx.x;

    if (blockIdx.x >= 128){
        // ---- prep: We1^T -> fp16, We2^T -> fp16 ----
        int idx = (blockIdx.x - 128)*512 + tid;            // 0..18431
        if (idx < 128*128){
            int k = idx >> 7, n = idx & 127;
            g_Bhi[n*136 + k] = __float2half_rn(We1[k*128 + n]);
        } else if (idx < 128*128 + 128*16){
            int r = idx - 128*128;                         // 0..2047
            int k = r >> 4, c = r & 15;
            g_W2hi[c*136 + k] = __float2half_rn(We2[k*16 + c]);
        }
        return;
    }

    __shared__ float buf[128*33];
    __shared__ float Sp[16*33];
    __shared__ float SV[32];
    const int n  = tid >> 2;
    const int qf = tid & 3;
    const int base = blockIdx.x * NN;
    const float inv = 1.0f/127.0f;

    float xr[D_IN];
#pragma unroll
    for (int k=0;k<D_IN;k++) xr[k] = x[(base+n)*D_IN + k];
    if (qf == 0){
#pragma unroll
        for (int k=0;k<D_IN;k++) buf[n*33 + k] = xr[k];
    }
    __syncthreads();

    if (tid < 96){
        int col = tid % 6, grp = tid / 6;
        float s = 0.f;
#pragma unroll
        for (int m=0;m<8;m++) s += buf[(grp*8+m)*33 + col];
        Sp[grp*7 + col] = s;
    }
    __syncthreads();
    if (tid < 6){
        float s = 0.f;
#pragma unroll
        for (int g2=0;g2<16;g2++) s += Sp[g2*7 + tid];
        SV[tid] = s;
    }
    __syncthreads();

    float a0[8];
#pragma unroll
    for (int cc=0;cc<8;cc++){
        int c = qf*8 + cc;
        float y = 0.f, S = 0.f;
#pragma unroll
        for (int k=0;k<D_IN;k++){
            float w = __ldg(&Wg0[k*32+c]);
            y += xr[k]*w;  S += SV[k]*w;
        }
        a0[cc] = lrelu((S - y)*inv + __ldg(&bg0[c]));
    }
    __syncthreads();
#pragma unroll
    for (int cc=0;cc<8;cc++) buf[n*33 + qf*8 + cc] = a0[cc];
    __syncthreads();

    {
        int col = tid & 31, grp = tid >> 5;
        float s = 0.f;
#pragma unroll
        for (int m=0;m<8;m++) s += buf[(grp*8+m)*33 + col];
        Sp[grp*33 + col] = s;
    }
    __syncthreads();
    if (tid < 32){
        float s = 0.f;
#pragma unroll
        for (int g2=0;g2<16;g2++) s += Sp[g2*33 + tid];
        SV[tid] = s;
    }
    __syncthreads();

    float a1[8];
#pragma unroll
    for (int cc=0;cc<8;cc++){
        int c = qf*8 + cc;
        float y = 0.f, S = 0.f;
#pragma unroll
        for (int k=0;k<32;k++){
            float w = __ldg(&Wg1[k*32+c]);
            y += buf[n*33+k]*w;  S += SV[k]*w;
        }
        a1[cc] = lrelu((S - y)*inv + __ldg(&bg1[c]));
    }
    __syncthreads();
#pragma unroll
    for (int cc=0;cc<8;cc++) buf[n*33 + qf*8 + cc] = a1[cc];
    __syncthreads();

    {
        int col = tid & 31, grp = tid >> 5;
        float s = 0.f;
#pragma unroll
        for (int m=0;m<8;m++) s += buf[(grp*8+m)*33 + col];
        Sp[grp*33 + col] = s;
    }
    __syncthreads();
    if (tid < 32){
        float s = 0.f;
#pragma unroll
        for (int g2=0;g2<16;g2++) s += Sp[g2*33 + tid];
        SV[tid] = s;
    }
    __syncthreads();

#pragma unroll
    for (int cc=0;cc<16;cc++){
        int c = qf*16 + cc;
        float y = 0.f, S = 0.f;
#pragma unroll
        for (int k=0;k<32;k++){
            float w = __ldg(&Wg2[k*64+c]);
            y += buf[n*33+k]*w;  S += SV[k]*w;
        }
        h_out[(base+n)*64 + c] = (S - y)*inv + __ldg(&bg2[c]);
    }
}

// ---------------------------------------------------------------------------
// K2 fused: blocks [0,512) = A0/B0 GEMM (fp16 out, be0 folded into B0);
// blocks [512,1024) = node MLP + diag.
// ---------------------------------------------------------------------------
#define K2B_W0   0
#define K2B_W1   4096
#define K2B_W2   8192
#define K2B_BA   8960
#define K2B_BB   11136
#define K2B_VB   13312
#define K2B_B0   13728
#define K2B_B1   13792
#define K2B_B2   13856
#define K2B_SMEM ((13856+16)*4)

__global__ void __launch_bounds__(256)
k2_fused(const float* __restrict__ h, const float* __restrict__ We0,
         const float* __restrict__ be0,
         const float* __restrict__ Wn0, const float* __restrict__ bn0,
         const float* __restrict__ Wn1, const float* __restrict__ bn1,
         const float* __restrict__ Wn2, const float* __restrict__ bn2,
         float* __restrict__ U)
{
    extern __shared__ float sm[];
    const int tid = threadIdx.x;

    if (blockIdx.x < 512){
        // ---- k2_ab ----
        float* hs = sm;
        const int n0 = blockIdx.x * 32;

        for (int l = tid; l < 32*64; l += 256) hs[l] = h[n0*64 + l];
        __syncthreads();

        const int col = tid & 127;
        const int kb  = (tid >> 7) * 64;
        const float bias = (tid >= 128) ? __ldg(&be0[col]) : 0.f;

        float acc[32];
#pragma unroll
        for (int i=0;i<32;i++) acc[i]=0.f;

        for (int k=0;k<64;k++){
            float w = __ldg(&We0[(kb+k)*128 + col]);
#pragma unroll
            for (int nn=0;nn<32;nn++) acc[nn] += hs[nn*64+k]*w;
        }

        __half* dst = (tid < 128) ? g_A0h : g_B0h;
#pragma unroll
        for (int nn=0;nn<32;nn++)
            dst[(size_t)(n0+nn)*128 + col] = __float2half_rn(acc[nn] + bias);
        return;
    }

    // ---- k2b node MLP ----
    const int blk = blockIdx.x - 512;
    const int ln  = tid >> 3;
    const int q   = tid & 7;
    const int b   = blk >> 2;
    const int n0  = (blk & 3) * 32;

    float4* w0s = reinterpret_cast<float4*>(sm + K2B_W0);
    float4* w1s = reinterpret_cast<float4*>(sm + K2B_W1);

    for (int l = tid; l < 1024; l += 256){
        w0s[l] = reinterpret_cast<const float4*>(Wn0)[l];
        w1s[l] = reinterpret_cast<const float4*>(Wn1)[l];
    }
    for (int l = tid; l < 768; l += 256){
        int k = l / 12, c = l % 12;
        sm[K2B_W2 + l] = (c < 10) ? Wn2[k*10 + c] : 0.f;
    }
    if (tid < 64){ sm[K2B_B0 + tid] = bn0[tid]; sm[K2B_B1 + tid] = bn1[tid]; }
    else if (tid < 76) sm[K2B_B2 + tid - 64] = (tid - 64 < 10) ? bn2[tid-64] : 0.f;
    for (int l = tid; l < 2048; l += 256){
        int r_ = l >> 6, c = l & 63;
        sm[K2B_BA + r_*68 + c] = h[(size_t)(b*128 + n0 + r_)*64 + c];
    }
    __syncthreads();

    {
        float acc[8];
#pragma unroll
        for (int m=0;m<8;m++) acc[m] = sm[K2B_B0 + q*8 + m];
        for (int k=0;k<64;k++){
            float hk = sm[K2B_BA + ln*68 + k];
            float4 wa = w0s[k*16 + q*2];
            float4 wb = w0s[k*16 + q*2 + 1];
            acc[0] += hk*wa.x; acc[1] += hk*wa.y; acc[2] += hk*wa.z; acc[3] += hk*wa.w;
            acc[4] += hk*wb.x; acc[5] += hk*wb.y; acc[6] += hk*wb.z; acc[7] += hk*wb.w;
        }
#pragma unroll
        for (int m=0;m<8;m++) sm[K2B_BB + ln*68 + q*8 + m] = lrelu(acc[m]);
    }
    __syncthreads();

    {
        float acc[8];
#pragma unroll
        for (int m=0;m<8;m++) acc[m] = sm[K2B_B1 + q*8 + m];
        for (int k=0;k<64;k++){
            float hk = sm[K2B_BB + ln*68 + k];
            float4 wa = w1s[k*16 + q*2];
            float4 wb = w1s[k*16 + q*2 + 1];
            acc[0] += hk*wa.x; acc[1] += hk*wa.y; acc[2] += hk*wa.z; acc[3] += hk*wa.w;
            acc[4] += hk*wb.x; acc[5] += hk*wb.y; acc[6] += hk*wb.z; acc[7] += hk*wb.w;
        }
        __syncthreads();
#pragma unroll
        for (int m=0;m<8;m++) sm[K2B_BA + ln*68 + q*8 + m] = lrelu(acc[m]);
    }
    __syncthreads();

    if (q < 6){
        const int c0 = 2*q, c1 = 2*q + 1;
        float a0 = sm[K2B_B2 + c0];
        float a1 = sm[K2B_B2 + c1];
        for (int k=0;k<64;k++){
            float hk = sm[K2B_BA + ln*68 + k];
            a0 += hk * sm[K2B_W2 + k*12 + c0];
            a1 += hk * sm[K2B_W2 + k*12 + c1];
        }
        sm[K2B_VB + ln*13 + c0] = a0;
        sm[K2B_VB + ln*13 + c1] = a1;
    }
    __syncthreads();

    if (q < 4){
        const int SMAT[16] = {0,1,2,3, 1,4,5,6, 2,5,7,8, 3,6,8,9};
        const int node = n0 + ln;
        float4 rv;
        rv.x = sm[K2B_VB + ln*13 + SMAT[q*4+0]];
        rv.y = sm[K2B_VB + ln*13 + SMAT[q*4+1]];
        rv.z = sm[K2B_VB + ln*13 + SMAT[q*4+2]];
        rv.w = sm[K2B_VB + ln*13 + SMAT[q*4+3]];
        float* Ub = U + (size_t)b*U_PER_B;
        *reinterpret_cast<float4*>(Ub + (size_t)(4*node+q)*U_STRIDE + 4*node) = rv;
    }
}

// ---------------------------------------------------------------------------
// K3: PERSISTENT edge MLP. 296 CTAs (1 wave, 2/SM); weights staged once per
// CTA; loop over ~31 tiles each. GEMM1: half2-built fp16 A x fp16 We1^T;
// GEMM2: fp16 x fp16 We2^T. Dedicated ES region (no aliasing).
// ---------------------------------------------------------------------------
#define OFF_BHI  0                    // 34816 (persistent)
#define OFF_W2HI 34816                // 4352  (persistent)
#define OFF_BE1  39168                // 512
#define OFF_BE2  39680                // 64
#define OFF_A0S  39744                // 8 x 272 B = 2176 (fp16, stride 136 h)
#define OFF_B0S  41920                // 16 x 272 B = 4352
#define OFF_ES   46272                // [128][20] f = 10240 (dedicated)
#define K3_SMEM  56512

#define K3_GRID  296
#define N_TILES  (72*BATCH)

__global__ void __launch_bounds__(256, 2)
k3_edge_mma(const float* __restrict__ be1,
            const float* __restrict__ be2,
            float* __restrict__ U)
{
    extern __shared__ char smem[];
    float* smemf = reinterpret_cast<float*>(smem);
    const uint32_t sb = smem_u32(smem);
    const int tid = threadIdx.x;
    const int wid = tid >> 5;
    const int lane = tid & 31;
    const int g = lane >> 2;
    const int r = lane & 3;
    const int mg = wid >> 1;
    const int ng = wid & 1;

    // ---- stage persistent weights once ----
    {
        const uint4* sh  = reinterpret_cast<const uint4*>(g_Bhi);
        uint4* dh = reinterpret_cast<uint4*>(smem + OFF_BHI);
        for (int l = tid; l < 2176; l += 256) dh[l] = sh[l];
        const uint4* s2h = reinterpret_cast<const uint4*>(g_W2hi);
        uint4* d2h = reinterpret_cast<uint4*>(smem + OFF_W2HI);
        for (int l = tid; l < 272; l += 256) d2h[l] = s2h[l];
        if (tid < 128) smemf[OFF_BE1/4 + tid] = be1[tid];
        else if (tid < 144) smemf[OFF_BE2/4 + tid - 128] = be2[tid - 128];
    }

    const uint32_t bOff = (uint32_t)((ng*64 + ((lane >> 4) << 3) + (lane & 7))*272
                                    + ((lane >> 3) & 1)*16);
    const uint32_t bHi = sb + OFF_BHI + bOff;
    const uint32_t b2Off = (uint32_t)(((((lane >> 4) << 3) + (lane & 7))*272)
                                    + ((lane >> 3) & 1)*16);
    const uint32_t wHi = sb + OFF_W2HI + b2Off;
    const __half2 slope = __floats2half2_rn(0.1f, 0.1f);
    float* es = smemf + OFF_ES/4;   // [128][20]

    for (int tt = blockIdx.x; tt < N_TILES; tt += K3_GRID){
        const int tri = tt % 72;
        const int b   = tt / 72;
        int jt = 0;
#pragma unroll
        for (int q=1;q<8;q++) if (tri >= q*(q+1)) jt = q;
        const int it = tri - jt*(jt+1);
        const int i0 = it*8, j0 = jt*16;

        // ---- stage A0/B0 rows (fp16) ----
        if (tid < 128){
            int rr = tid >> 4, c16 = tid & 15;
            uint4 v = reinterpret_cast<const uint4*>(g_A0h + ((size_t)(b*NN + i0 + rr))*128)[c16];
            *reinterpret_cast<uint4*>(smem + OFF_A0S + rr*272 + c16*16) = v;
        } else {
            int l = tid - 128;
#pragma unroll
            for (int h2_ = 0; h2_ < 2; h2_++){
                int rr = (l + h2_*128) >> 4, c16 = (l + h2_*128) & 15;
                uint4 v = reinterpret_cast<const uint4*>(g_B0h + ((size_t)(b*NN + j0 + rr))*128)[c16];
                *reinterpret_cast<uint4*>(smem + OFF_B0S + rr*272 + c16*16) = v;
            }
        }
        __syncthreads();

        float acc[2][8][4];
#pragma unroll
        for (int a1=0;a1<2;a1++)
#pragma unroll
            for (int a2=0;a2<8;a2++)
#pragma unroll
                for (int a3=0;a3<4;a3++) acc[a1][a2][a3] = 0.f;

        // ---- GEMM1 ----
        {
            const __half2* A0p = reinterpret_cast<const __half2*>(smem + OFF_A0S);
            const __half2* B0p = reinterpret_cast<const __half2*>(smem + OFF_B0S);

#pragma unroll
            for (int ks = 0; ks < 8; ks++){
                __half2 b0a = B0p[g*68      + ks*8 + r];
                __half2 b0b = B0p[g*68      + ks*8 + 4 + r];
                __half2 b1a = B0p[(g+8)*68  + ks*8 + r];
                __half2 b1b = B0p[(g+8)*68  + ks*8 + 4 + r];

                uint32_t ah[2][4];
#pragma unroll
                for (int mt=0; mt<2; mt++){
                    __half2 aa = A0p[(mg*2+mt)*68 + ks*8 + r];
                    __half2 ab = A0p[(mg*2+mt)*68 + ks*8 + 4 + r];
                    ah[mt][0] = lrelu2(__hadd2(aa, b0a), slope);
                    ah[mt][1] = lrelu2(__hadd2(aa, b1a), slope);
                    ah[mt][2] = lrelu2(__hadd2(ab, b0b), slope);
                    ah[mt][3] = lrelu2(__hadd2(ab, b1b), slope);
                }
#pragma unroll
                for (int n2 = 0; n2 < 4; n2++){
                    uint32_t bh[4];
                    LDM4(bh, bHi + n2*4352 + ks*32);
                    MMA16816H(acc[0][2*n2],   ah[0], bh[0], bh[1]);
                    MMA16816H(acc[0][2*n2+1], ah[0], bh[2], bh[3]);
                    MMA16816H(acc[1][2*n2],   ah[1], bh[0], bh[1]);
                    MMA16816H(acc[1][2*n2+1], ah[1], bh[2], bh[3]);
                }
            }
        }

        // ---- GEMM2 ----
        float e[2][2][4];
#pragma unroll
        for (int a1=0;a1<2;a1++)
#pragma unroll
            for (int a2=0;a2<2;a2++)
#pragma unroll
                for (int a3=0;a3<4;a3++) e[a1][a2][a3] = 0.f;

        {
#pragma unroll
            for (int qk = 0; qk < 4; qk++){
                uint32_t bh[4];
                LDM4(bh, wHi + (ng*4+qk)*32);
#pragma unroll
                for (int mt = 0; mt < 2; mt++){
                    const int ntA = 2*qk, ntB = 2*qk+1;
                    const int cA = ng*64 + ntA*8 + 2*r;
                    const int cB = ng*64 + ntB*8 + 2*r;
                    float beA0 = smemf[OFF_BE1/4 + cA], beA1 = smemf[OFF_BE1/4 + cA + 1];
                    float beB0 = smemf[OFF_BE1/4 + cB], beB1 = smemf[OFF_BE1/4 + cB + 1];
                    uint32_t ah[4];
                    ah[0] = packh2(lrelu(acc[mt][ntA][0]+beA0), lrelu(acc[mt][ntA][1]+beA1));
                    ah[1] = packh2(lrelu(acc[mt][ntA][2]+beA0), lrelu(acc[mt][ntA][3]+beA1));
                    ah[2] = packh2(lrelu(acc[mt][ntB][0]+beB0), lrelu(acc[mt][ntB][1]+beB1));
                    ah[3] = packh2(lrelu(acc[mt][ntB][2]+beB0), lrelu(acc[mt][ntB][3]+beB1));
                    MMA16816H(e[mt][0], ah, bh[0], bh[1]);
                    MMA16816H(e[mt][1], ah, bh[2], bh[3]);
                }
            }
        }

        // ---- cross-warp (ng pair) reduction + direct scatter into U ----
        if (ng == 1){
#pragma unroll
            for (int mt=0; mt<2; mt++)
#pragma unroll
            for (int t_=0; t_<2; t_++)
#pragma unroll
            for (int rh=0; rh<2; rh++){
                int row = mg*32 + mt*16 + g + rh*8;
                int c = t_*8 + 2*r;
                *reinterpret_cast<float2*>(&es[row*20 + c]) =
                    make_float2(e[mt][t_][rh*2+0], e[mt][t_][rh*2+1]);
            }
        }
        __syncthreads();
        if (ng == 0){
            float* Ub = U + (size_t)b*U_PER_B;
#pragma unroll
            for (int mt=0; mt<2; mt++)
#pragma unroll
            for (int t_=0; t_<2; t_++)
#pragma unroll
            for (int rh=0; rh<2; rh++){
                int row = mg*32 + mt*16 + g + rh*8;
                int c = t_*8 + 2*r;
                float2 part = *reinterpret_cast<const float2*>(&es[row*20 + c]);
                float vx = e[mt][t_][rh*2+0] + part.x + smemf[OFF_BE2/4 + c];
                float vy = e[mt][t_][rh*2+1] + part.y + smemf[OFF_BE2/4 + c + 1];
                int i = i0 + (row >> 4);
                int j = j0 + (row & 15);
                if (i < j){
                    int qq = c >> 2, m = c & 3;
                    float2 v2 = make_float2(vx, vy);
                    *reinterpret_cast<float2*>(Ub + (size_t)(4*i+qq)*U_STRIDE + 4*j + m) = v2;
                    *reinterpret_cast<float2*>(Ub + (size_t)(4*j+qq)*U_STRIDE + 4*i + m) = v2;
                }
            }
        }
        __syncthreads();   // protect A0S/B0S and ES for next tile
    }
}

// ---------------------------------------------------------------------------
extern "C" void kernel_launch(void* const* d_in, const int* in_sizes, int n_in,
                              void* d_out, int out_size)
{
    const float* x   = (const float*)d_in[0];
    const float* Wg0 = (const float*)d_in[4];
    const float* bg0 = (const float*)d_in[5];
    const float* Wg1 = (const float*)d_in[6];
    const float* bg1 = (const float*)d_in[7];
    const float* Wg2 = (const float*)d_in[8];
    const float* bg2 = (const float*)d_in[9];
    const float* Wn0 = (const float*)d_in[10];
    const float* bn0 = (const float*)d_in[11];
    const float* Wn1 = (const float*)d_in[12];
    const float* bn1 = (const float*)d_in[13];
    const float* Wn2 = (const float*)d_in[14];
    const float* bn2 = (const float*)d_in[15];
    const float* We0 = (const float*)d_in[16];
    const float* be0 = (const float*)d_in[17];
    const float* We1 = (const float*)d_in[18];
    const float* be1 = (const float*)d_in[19];
    const float* We2 = (const float*)d_in[20];
    const float* be2 = (const float*)d_in[21];

    float* h_out = (float*)d_out;                 // (16384, 64)
    float* U     = h_out + (size_t)TOTAL*D_MP;    // (128, 512, 512)

    static bool attr_set = false;
    if (!attr_set){
        cudaFuncSetAttribute(k3_edge_mma, cudaFuncAttributeMaxDynamicSharedMemorySize, K3_SMEM);
        cudaFuncSetAttribute(k2_fused, cudaFuncAttributeMaxDynamicSharedMemorySize, K2B_SMEM);
        attr_set = true;
    }

    k1_fused<<<164, 512>>>(x, Wg0,bg0, Wg1,bg1, Wg2,bg2, We1, We2, h_out);
    k2_fused<<<1024, 256, K2B_SMEM>>>(h_out, We0, be0, Wn0,bn0, Wn1,bn1, Wn2,bn2, U);
    k3_edge_mma<<<K3_GRID, 256, K3_SMEM>>>(be1, be2, U);
}

// round 14
// speedup vs baseline: 2.5494x; 1.1091x over previous
#include <cuda_runtime.h>
#include <cuda_bf16.h>
#include <cuda_fp16.h>
#include <cstdint>

// Problem constants
#define BATCH 128
#define NN    128
#define D_IN  6
#define D_MP  64
#define TOTAL (BATCH*NN)    // 16384
#define U_STRIDE 512
#define U_PER_B  (512*512)

__device__ __half g_A0h[TOTAL*128];         // fp16(h @ We0[:64])
__device__ __half g_B0h[TOTAL*128];         // fp16(h @ We0[64:] + be0)
__device__ __half g_Bhi[128*136];           // We1^T fp16, padded [n][136]
__device__ __half g_W2hi[16*136];           // We2^T fp16, padded [c][136]

__device__ __forceinline__ float lrelu(float v){ return v >= 0.f ? v : 0.1f*v; }

__device__ __forceinline__ uint32_t smem_u32(const void* p){
    uint32_t a;
    asm("{ .reg .u64 t; cvta.to.shared.u64 t, %1; cvt.u32.u64 %0, t; }"
        : "=r"(a) : "l"(p));
    return a;
}

#define LDM4(r, addr) \
    asm volatile("ldmatrix.sync.aligned.m8n8.x4.shared.b16 {%0,%1,%2,%3}, [%4];" \
        : "=r"((r)[0]), "=r"((r)[1]), "=r"((r)[2]), "=r"((r)[3]) : "r"(addr))

#define MMA16816H(d, a, b0_, b1_) \
    asm volatile("mma.sync.aligned.m16n8k16.row.col.f32.f16.f16.f32 " \
        "{%0,%1,%2,%3}, {%4,%5,%6,%7}, {%8,%9}, {%0,%1,%2,%3};" \
        : "+f"((d)[0]), "+f"((d)[1]), "+f"((d)[2]), "+f"((d)[3]) \
        : "r"((a)[0]), "r"((a)[1]), "r"((a)[2]), "r"((a)[3]), "r"(b0_), "r"(b1_))

__device__ __forceinline__ uint32_t packh2(float s0, float s1){
    __half2 h2 = __floats2half2_rn(s0, s1);
    return *reinterpret_cast<uint32_t*>(&h2);
}
__device__ __forceinline__ uint32_t lrelu2(__half2 v, __half2 slope){
    __half2 o = __hmax2(v, __hmul2(v, slope));
    return *reinterpret_cast<uint32_t*>(&o);
}

// ---------------------------------------------------------------------------
// K1 fused: blocks [0,128) = GCN (512 thr, 4/node); blocks [128,164) = prep.
// (unchanged from round-13 best)
// ---------------------------------------------------------------------------
__global__ void __launch_bounds__(512)
k1_fused(const float* __restrict__ x,
         const float* __restrict__ Wg0, const float* __restrict__ bg0,
         const float* __restrict__ Wg1, const float* __restrict__ bg1,
         const float* __restrict__ Wg2, const float* __restrict__ bg2,
         const float* __restrict__ We1, const float* __restrict__ We2,
         float* __restrict__ h_out)
{
    const int tid = threadIdx.x;

    if (blockIdx.x >= 128){
        int idx = (blockIdx.x - 128)*512 + tid;
        if (idx < 128*128){
            int k = idx >> 7, n = idx & 127;
            g_Bhi[n*136 + k] = __float2half_rn(We1[k*128 + n]);
        } else if (idx < 128*128 + 128*16){
            int r = idx - 128*128;
            int k = r >> 4, c = r & 15;
            g_W2hi[c*136 + k] = __float2half_rn(We2[k*16 + c]);
        }
        return;
    }

    __shared__ float buf[128*33];
    __shared__ float Sp[16*33];
    __shared__ float SV[32];
    const int n  = tid >> 2;
    const int qf = tid & 3;
    const int base = blockIdx.x * NN;
    const float inv = 1.0f/127.0f;

    float xr[D_IN];
#pragma unroll
    for (int k=0;k<D_IN;k++) xr[k] = x[(base+n)*D_IN + k];
    if (qf == 0){
#pragma unroll
        for (int k=0;k<D_IN;k++) buf[n*33 + k] = xr[k];
    }
    __syncthreads();

    if (tid < 96){
        int col = tid % 6, grp = tid / 6;
        float s = 0.f;
#pragma unroll
        for (int m=0;m<8;m++) s += buf[(grp*8+m)*33 + col];
        Sp[grp*7 + col] = s;
    }
    __syncthreads();
    if (tid < 6){
        float s = 0.f;
#pragma unroll
        for (int g2=0;g2<16;g2++) s += Sp[g2*7 + tid];
        SV[tid] = s;
    }
    __syncthreads();

    float a0[8];
#pragma unroll
    for (int cc=0;cc<8;cc++){
        int c = qf*8 + cc;
        float y = 0.f, S = 0.f;
#pragma unroll
        for (int k=0;k<D_IN;k++){
            float w = __ldg(&Wg0[k*32+c]);
            y += xr[k]*w;  S += SV[k]*w;
        }
        a0[cc] = lrelu((S - y)*inv + __ldg(&bg0[c]));
    }
    __syncthreads();
#pragma unroll
    for (int cc=0;cc<8;cc++) buf[n*33 + qf*8 + cc] = a0[cc];
    __syncthreads();

    {
        int col = tid & 31, grp = tid >> 5;
        float s = 0.f;
#pragma unroll
        for (int m=0;m<8;m++) s += buf[(grp*8+m)*33 + col];
        Sp[grp*33 + col] = s;
    }
    __syncthreads();
    if (tid < 32){
        float s = 0.f;
#pragma unroll
        for (int g2=0;g2<16;g2++) s += Sp[g2*33 + tid];
        SV[tid] = s;
    }
    __syncthreads();

    float a1[8];
#pragma unroll
    for (int cc=0;cc<8;cc++){
        int c = qf*8 + cc;
        float y = 0.f, S = 0.f;
#pragma unroll
        for (int k=0;k<32;k++){
            float w = __ldg(&Wg1[k*32+c]);
            y += buf[n*33+k]*w;  S += SV[k]*w;
        }
        a1[cc] = lrelu((S - y)*inv + __ldg(&bg1[c]));
    }
    __syncthreads();
#pragma unroll
    for (int cc=0;cc<8;cc++) buf[n*33 + qf*8 + cc] = a1[cc];
    __syncthreads();

    {
        int col = tid & 31, grp = tid >> 5;
        float s = 0.f;
#pragma unroll
        for (int m=0;m<8;m++) s += buf[(grp*8+m)*33 + col];
        Sp[grp*33 + col] = s;
    }
    __syncthreads();
    if (tid < 32){
        float s = 0.f;
#pragma unroll
        for (int g2=0;g2<16;g2++) s += Sp[g2*33 + tid];
        SV[tid] = s;
    }
    __syncthreads();

#pragma unroll
    for (int cc=0;cc<16;cc++){
        int c = qf*16 + cc;
        float y = 0.f, S = 0.f;
#pragma unroll
        for (int k=0;k<32;k++){
            float w = __ldg(&Wg2[k*64+c]);
            y += buf[n*33+k]*w;  S += SV[k]*w;
        }
        h_out[(base+n)*64 + c] = (S - y)*inv + __ldg(&bg2[c]);
    }
}

// ---------------------------------------------------------------------------
// K2a: A0/B0 GEMM (fp16 out, be0 folded into B0). float4 hs loads.
// ---------------------------------------------------------------------------
__global__ void __launch_bounds__(256)
k2_ab(const float* __restrict__ h, const float* __restrict__ We0,
      const float* __restrict__ be0)
{
    __shared__ float hs[32*64];
    const int tid = threadIdx.x;
    const int n0 = blockIdx.x * 32;

    for (int l = tid; l < 32*64; l += 256) hs[l] = h[n0*64 + l];
    __syncthreads();

    const int col = tid & 127;
    const int kb  = (tid >> 7) * 64;
    const float bias = (tid >= 128) ? __ldg(&be0[col]) : 0.f;

    float acc[32];
#pragma unroll
    for (int i=0;i<32;i++) acc[i]=0.f;

    for (int k=0;k<64;k+=4){
        float w0 = __ldg(&We0[(kb+k+0)*128 + col]);
        float w1 = __ldg(&We0[(kb+k+1)*128 + col]);
        float w2 = __ldg(&We0[(kb+k+2)*128 + col]);
        float w3 = __ldg(&We0[(kb+k+3)*128 + col]);
#pragma unroll
        for (int nn=0;nn<32;nn++){
            float4 hv = *reinterpret_cast<const float4*>(&hs[nn*64 + k]);
            acc[nn] += hv.x*w0 + hv.y*w1 + hv.z*w2 + hv.w*w3;
        }
    }

    __half* dst = (tid < 128) ? g_A0h : g_B0h;
#pragma unroll
    for (int nn=0;nn<32;nn++)
        dst[(size_t)(n0+nn)*128 + col] = __float2half_rn(acc[nn] + bias);
}

// ---------------------------------------------------------------------------
// K2b: node MLP + diagonal 4x4 blocks of U (round-13 code, standalone).
// Runs on a side stream, concurrent with k2_ab / k3 ramp.
// ---------------------------------------------------------------------------
#define K2B_W0   0
#define K2B_W1   4096
#define K2B_W2   8192
#define K2B_BA   8960
#define K2B_BB   11136
#define K2B_VB   13312
#define K2B_B0   13728
#define K2B_B1   13792
#define K2B_B2   13856
#define K2B_SMEM ((13856+16)*4)

__global__ void __launch_bounds__(256)
k2b_node(const float* __restrict__ h,
         const float* __restrict__ Wn0, const float* __restrict__ bn0,
         const float* __restrict__ Wn1, const float* __restrict__ bn1,
         const float* __restrict__ Wn2, const float* __restrict__ bn2,
         float* __restrict__ U)
{
    extern __shared__ float sm[];
    const int tid = threadIdx.x;
    const int blk = blockIdx.x;
    const int ln  = tid >> 3;
    const int q   = tid & 7;
    const int b   = blk >> 2;
    const int n0  = (blk & 3) * 32;

    float4* w0s = reinterpret_cast<float4*>(sm + K2B_W0);
    float4* w1s = reinterpret_cast<float4*>(sm + K2B_W1);

    for (int l = tid; l < 1024; l += 256){
        w0s[l] = reinterpret_cast<const float4*>(Wn0)[l];
        w1s[l] = reinterpret_cast<const float4*>(Wn1)[l];
    }
    for (int l = tid; l < 768; l += 256){
        int k = l / 12, c = l % 12;
        sm[K2B_W2 + l] = (c < 10) ? Wn2[k*10 + c] : 0.f;
    }
    if (tid < 64){ sm[K2B_B0 + tid] = bn0[tid]; sm[K2B_B1 + tid] = bn1[tid]; }
    else if (tid < 76) sm[K2B_B2 + tid - 64] = (tid - 64 < 10) ? bn2[tid-64] : 0.f;
    for (int l = tid; l < 2048; l += 256){
        int r_ = l >> 6, c = l & 63;
        sm[K2B_BA + r_*68 + c] = h[(size_t)(b*128 + n0 + r_)*64 + c];
    }
    __syncthreads();

    {
        float acc[8];
#pragma unroll
        for (int m=0;m<8;m++) acc[m] = sm[K2B_B0 + q*8 + m];
        for (int k=0;k<64;k++){
            float hk = sm[K2B_BA + ln*68 + k];
            float4 wa = w0s[k*16 + q*2];
            float4 wb = w0s[k*16 + q*2 + 1];
            acc[0] += hk*wa.x; acc[1] += hk*wa.y; acc[2] += hk*wa.z; acc[3] += hk*wa.w;
            acc[4] += hk*wb.x; acc[5] += hk*wb.y; acc[6] += hk*wb.z; acc[7] += hk*wb.w;
        }
#pragma unroll
        for (int m=0;m<8;m++) sm[K2B_BB + ln*68 + q*8 + m] = lrelu(acc[m]);
    }
    __syncthreads();

    {
        float acc[8];
#pragma unroll
        for (int m=0;m<8;m++) acc[m] = sm[K2B_B1 + q*8 + m];
        for (int k=0;k<64;k++){
            float hk = sm[K2B_BB + ln*68 + k];
            float4 wa = w1s[k*16 + q*2];
            float4 wb = w1s[k*16 + q*2 + 1];
            acc[0] += hk*wa.x; acc[1] += hk*wa.y; acc[2] += hk*wa.z; acc[3] += hk*wa.w;
            acc[4] += hk*wb.x; acc[5] += hk*wb.y; acc[6] += hk*wb.z; acc[7] += hk*wb.w;
        }
        __syncthreads();
#pragma unroll
        for (int m=0;m<8;m++) sm[K2B_BA + ln*68 + q*8 + m] = lrelu(acc[m]);
    }
    __syncthreads();

    if (q < 6){
        const int c0 = 2*q, c1 = 2*q + 1;
        float a0 = sm[K2B_B2 + c0];
        float a1 = sm[K2B_B2 + c1];
        for (int k=0;k<64;k++){
            float hk = sm[K2B_BA + ln*68 + k];
            a0 += hk * sm[K2B_W2 + k*12 + c0];
            a1 += hk * sm[K2B_W2 + k*12 + c1];
        }
        sm[K2B_VB + ln*13 + c0] = a0;
        sm[K2B_VB + ln*13 + c1] = a1;
    }
    __syncthreads();

    if (q < 4){
        const int SMAT[16] = {0,1,2,3, 1,4,5,6, 2,5,7,8, 3,6,8,9};
        const int node = n0 + ln;
        float4 rv;
        rv.x = sm[K2B_VB + ln*13 + SMAT[q*4+0]];
        rv.y = sm[K2B_VB + ln*13 + SMAT[q*4+1]];
        rv.z = sm[K2B_VB + ln*13 + SMAT[q*4+2]];
        rv.w = sm[K2B_VB + ln*13 + SMAT[q*4+3]];
        float* Ub = U + (size_t)b*U_PER_B;
        *reinterpret_cast<float4*>(Ub + (size_t)(4*node+q)*U_STRIDE + 4*node) = rv;
    }
}

// ---------------------------------------------------------------------------
// K3: PERSISTENT edge MLP (unchanged from round-13 best).
// ---------------------------------------------------------------------------
#define OFF_BHI  0
#define OFF_W2HI 34816
#define OFF_BE1  39168
#define OFF_BE2  39680
#define OFF_A0S  39744
#define OFF_B0S  41920
#define OFF_ES   46272
#define K3_SMEM  56512

#define K3_GRID  296
#define N_TILES  (72*BATCH)

__global__ void __launch_bounds__(256, 2)
k3_edge_mma(const float* __restrict__ be1,
            const float* __restrict__ be2,
            float* __restrict__ U)
{
    extern __shared__ char smem[];
    float* smemf = reinterpret_cast<float*>(smem);
    const uint32_t sb = smem_u32(smem);
    const int tid = threadIdx.x;
    const int wid = tid >> 5;
    const int lane = tid & 31;
    const int g = lane >> 2;
    const int r = lane & 3;
    const int mg = wid >> 1;
    const int ng = wid & 1;

    {
        const uint4* sh  = reinterpret_cast<const uint4*>(g_Bhi);
        uint4* dh = reinterpret_cast<uint4*>(smem + OFF_BHI);
        for (int l = tid; l < 2176; l += 256) dh[l] = sh[l];
        const uint4* s2h = reinterpret_cast<const uint4*>(g_W2hi);
        uint4* d2h = reinterpret_cast<uint4*>(smem + OFF_W2HI);
        for (int l = tid; l < 272; l += 256) d2h[l] = s2h[l];
        if (tid < 128) smemf[OFF_BE1/4 + tid] = be1[tid];
        else if (tid < 144) smemf[OFF_BE2/4 + tid - 128] = be2[tid - 128];
    }

    const uint32_t bOff = (uint32_t)((ng*64 + ((lane >> 4) << 3) + (lane & 7))*272
                                    + ((lane >> 3) & 1)*16);
    const uint32_t bHi = sb + OFF_BHI + bOff;
    const uint32_t b2Off = (uint32_t)(((((lane >> 4) << 3) + (lane & 7))*272)
                                    + ((lane >> 3) & 1)*16);
    const uint32_t wHi = sb + OFF_W2HI + b2Off;
    const __half2 slope = __floats2half2_rn(0.1f, 0.1f);
    float* es = smemf + OFF_ES/4;

    for (int tt = blockIdx.x; tt < N_TILES; tt += K3_GRID){
        const int tri = tt % 72;
        const int b   = tt / 72;
        int jt = 0;
#pragma unroll
        for (int q=1;q<8;q++) if (tri >= q*(q+1)) jt = q;
        const int it = tri - jt*(jt+1);
        const int i0 = it*8, j0 = jt*16;

        if (tid < 128){
            int rr = tid >> 4, c16 = tid & 15;
            uint4 v = reinterpret_cast<const uint4*>(g_A0h + ((size_t)(b*NN + i0 + rr))*128)[c16];
            *reinterpret_cast<uint4*>(smem + OFF_A0S + rr*272 + c16*16) = v;
        } else {
            int l = tid - 128;
#pragma unroll
            for (int h2_ = 0; h2_ < 2; h2_++){
                int rr = (l + h2_*128) >> 4, c16 = (l + h2_*128) & 15;
                uint4 v = reinterpret_cast<const uint4*>(g_B0h + ((size_t)(b*NN + j0 + rr))*128)[c16];
                *reinterpret_cast<uint4*>(smem + OFF_B0S + rr*272 + c16*16) = v;
            }
        }
        __syncthreads();

        float acc[2][8][4];
#pragma unroll
        for (int a1=0;a1<2;a1++)
#pragma unroll
            for (int a2=0;a2<8;a2++)
#pragma unroll
                for (int a3=0;a3<4;a3++) acc[a1][a2][a3] = 0.f;

        {
            const __half2* A0p = reinterpret_cast<const __half2*>(smem + OFF_A0S);
            const __half2* B0p = reinterpret_cast<const __half2*>(smem + OFF_B0S);

#pragma unroll
            for (int ks = 0; ks < 8; ks++){
                __half2 b0a = B0p[g*68      + ks*8 + r];
                __half2 b0b = B0p[g*68      + ks*8 + 4 + r];
                __half2 b1a = B0p[(g+8)*68  + ks*8 + r];
                __half2 b1b = B0p[(g+8)*68  + ks*8 + 4 + r];

                uint32_t ah[2][4];
#pragma unroll
                for (int mt=0; mt<2; mt++){
                    __half2 aa = A0p[(mg*2+mt)*68 + ks*8 + r];
                    __half2 ab = A0p[(mg*2+mt)*68 + ks*8 + 4 + r];
                    ah[mt][0] = lrelu2(__hadd2(aa, b0a), slope);
                    ah[mt][1] = lrelu2(__hadd2(aa, b1a), slope);
                    ah[mt][2] = lrelu2(__hadd2(ab, b0b), slope);
                    ah[mt][3] = lrelu2(__hadd2(ab, b1b), slope);
                }
#pragma unroll
                for (int n2 = 0; n2 < 4; n2++){
                    uint32_t bh[4];
                    LDM4(bh, bHi + n2*4352 + ks*32);
                    MMA16816H(acc[0][2*n2],   ah[0], bh[0], bh[1]);
                    MMA16816H(acc[0][2*n2+1], ah[0], bh[2], bh[3]);
                    MMA16816H(acc[1][2*n2],   ah[1], bh[0], bh[1]);
                    MMA16816H(acc[1][2*n2+1], ah[1], bh[2], bh[3]);
                }
            }
        }

        float e[2][2][4];
#pragma unroll
        for (int a1=0;a1<2;a1++)
#pragma unroll
            for (int a2=0;a2<2;a2++)
#pragma unroll
                for (int a3=0;a3<4;a3++) e[a1][a2][a3] = 0.f;

        {
#pragma unroll
            for (int qk = 0; qk < 4; qk++){
                uint32_t bh[4];
                LDM4(bh, wHi + (ng*4+qk)*32);
#pragma unroll
                for (int mt = 0; mt < 2; mt++){
                    const int ntA = 2*qk, ntB = 2*qk+1;
                    const int cA = ng*64 + ntA*8 + 2*r;
                    const int cB = ng*64 + ntB*8 + 2*r;
                    float beA0 = smemf[OFF_BE1/4 + cA], beA1 = smemf[OFF_BE1/4 + cA + 1];
                    float beB0 = smemf[OFF_BE1/4 + cB], beB1 = smemf[OFF_BE1/4 + cB + 1];
                    uint32_t ah[4];
                    ah[0] = packh2(lrelu(acc[mt][ntA][0]+beA0), lrelu(acc[mt][ntA][1]+beA1));
                    ah[1] = packh2(lrelu(acc[mt][ntA][2]+beA0), lrelu(acc[mt][ntA][3]+beA1));
                    ah[2] = packh2(lrelu(acc[mt][ntB][0]+beB0), lrelu(acc[mt][ntB][1]+beB1));
                    ah[3] = packh2(lrelu(acc[mt][ntB][2]+beB0), lrelu(acc[mt][ntB][3]+beB1));
                    MMA16816H(e[mt][0], ah, bh[0], bh[1]);
                    MMA16816H(e[mt][1], ah, bh[2], bh[3]);
                }
            }
        }

        if (ng == 1){
#pragma unroll
            for (int mt=0; mt<2; mt++)
#pragma unroll
            for (int t_=0; t_<2; t_++)
#pragma unroll
            for (int rh=0; rh<2; rh++){
                int row = mg*32 + mt*16 + g + rh*8;
                int c = t_*8 + 2*r;
                *reinterpret_cast<float2*>(&es[row*20 + c]) =
                    make_float2(e[mt][t_][rh*2+0], e[mt][t_][rh*2+1]);
            }
        }
        __syncthreads();
        if (ng == 0){
            float* Ub = U + (size_t)b*U_PER_B;
#pragma unroll
            for (int mt=0; mt<2; mt++)
#pragma unroll
            for (int t_=0; t_<2; t_++)
#pragma unroll
            for (int rh=0; rh<2; rh++){
                int row = mg*32 + mt*16 + g + rh*8;
                int c = t_*8 + 2*r;
                float2 part = *reinterpret_cast<const float2*>(&es[row*20 + c]);
                float vx = e[mt][t_][rh*2+0] + part.x + smemf[OFF_BE2/4 + c];
                float vy = e[mt][t_][rh*2+1] + part.y + smemf[OFF_BE2/4 + c + 1];
                int i = i0 + (row >> 4);
                int j = j0 + (row & 15);
                if (i < j){
                    int qq = c >> 2, m = c & 3;
                    float2 v2 = make_float2(vx, vy);
                    *reinterpret_cast<float2*>(Ub + (size_t)(4*i+qq)*U_STRIDE + 4*j + m) = v2;
                    *reinterpret_cast<float2*>(Ub + (size_t)(4*j+qq)*U_STRIDE + 4*i + m) = v2;
                }
            }
        }
        __syncthreads();
    }
}

// ---------------------------------------------------------------------------
extern "C" void kernel_launch(void* const* d_in, const int* in_sizes, int n_in,
                              void* d_out, int out_size)
{
    const float* x   = (const float*)d_in[0];
    const float* Wg0 = (const float*)d_in[4];
    const float* bg0 = (const float*)d_in[5];
    const float* Wg1 = (const float*)d_in[6];
    const float* bg1 = (const float*)d_in[7];
    const float* Wg2 = (const float*)d_in[8];
    const float* bg2 = (const float*)d_in[9];
    const float* Wn0 = (const float*)d_in[10];
    const float* bn0 = (const float*)d_in[11];
    const float* Wn1 = (const float*)d_in[12];
    const float* bn1 = (const float*)d_in[13];
    const float* Wn2 = (const float*)d_in[14];
    const float* bn2 = (const float*)d_in[15];
    const float* We0 = (const float*)d_in[16];
    const float* be0 = (const float*)d_in[17];
    const float* We1 = (const float*)d_in[18];
    const float* be1 = (const float*)d_in[19];
    const float* We2 = (const float*)d_in[20];
    const float* be2 = (const float*)d_in[21];

    float* h_out = (float*)d_out;                 // (16384, 64)
    float* U     = h_out + (size_t)TOTAL*D_MP;    // (128, 512, 512)

    static bool init_done = false;
    static cudaStream_t s2;
    static cudaEvent_t ev_fork, ev_join;
    if (!init_done){
        cudaFuncSetAttribute(k3_edge_mma, cudaFuncAttributeMaxDynamicSharedMemorySize, K3_SMEM);
        cudaFuncSetAttribute(k2b_node, cudaFuncAttributeMaxDynamicSharedMemorySize, K2B_SMEM);
        cudaStreamCreateWithFlags(&s2, cudaStreamNonBlocking);
        cudaEventCreateWithFlags(&ev_fork, cudaEventDisableTiming);
        cudaEventCreateWithFlags(&ev_join, cudaEventDisableTiming);
        init_done = true;
    }

    // main stream: k1 -> k2_ab -> k3 ; side stream: k2b (forks after k1)
    k1_fused<<<164, 512>>>(x, Wg0,bg0, Wg1,bg1, Wg2,bg2, We1, We2, h_out);
    cudaEventRecord(ev_fork, 0);
    cudaStreamWaitEvent(s2, ev_fork, 0);
    k2b_node<<<512, 256, K2B_SMEM, s2>>>(h_out, Wn0,bn0, Wn1,bn1, Wn2,bn2, U);
    cudaEventRecord(ev_join, s2);
    k2_ab<<<512, 256>>>(h_out, We0, be0);
    k3_edge_mma<<<K3_GRID, 256, K3_SMEM>>>(be1, be2, U);
    cudaStreamWaitEvent(0, ev_join, 0);
}